// round 2
// baseline (speedup 1.0000x reference)
#include <cuda_runtime.h>
#include <math.h>

// Problem constants
#define NWIN 4096
#define NTOK 64
#define DIM  128
#define NH   4
#define HD   32
#define NMASK 64

// ---------------------------------------------------------------------------
// Scratch (allocation-free: __device__ globals)
// ---------------------------------------------------------------------------
__device__ float g_Q  [NWIN * NTOK * DIM];        // 134 MB
__device__ float g_KV [NWIN * NTOK * 2 * DIM];    // 268 MB  (k: cols 0-127, v: 128-255)
__device__ float g_ATT[NWIN * NTOK * DIM];        // 134 MB
__device__ float g_biasT[NH * NTOK * NTOK];       // [h][j][i]
__device__ float g_maskT[NMASK * NTOK * NTOK];    // [w][j][i]

// ---------------------------------------------------------------------------
// K0a: transpose shift-mask per window slice: maskT[w][j][i] = mask[w][i][j]
// ---------------------------------------------------------------------------
__global__ void mask_transpose_kernel(const float* __restrict__ mask) {
    const int w = blockIdx.x;
    const float* mi = mask + (size_t)w * NTOK * NTOK;
    float* mo = g_maskT + (size_t)w * NTOK * NTOK;
    for (int idx = threadIdx.x; idx < NTOK * NTOK; idx += blockDim.x) {
        int i = idx >> 6, j = idx & 63;
        mo[j * 64 + i] = mi[i * 64 + j];
    }
}

// ---------------------------------------------------------------------------
// K0b: CPB-MLP relative position bias, gathered + transposed:
//   tbl[r][h] = (relu(table @ w1^T + b1) @ w2^T)[r][h], r in [0,225)
//   biasT[h][j][i] = 16*sigmoid(tbl[rel_pos_index[i][j]][h])
// ---------------------------------------------------------------------------
__global__ void cpb_bias_kernel(const float* __restrict__ table,   // (225,2)
                                const float* __restrict__ w1,      // (512,2)
                                const float* __restrict__ b1,      // (512)
                                const float* __restrict__ w2,      // (4,512)
                                const int*   __restrict__ rpi) {   // (64,64)
    __shared__ float tbl[225][4];
    const int tid = threadIdx.x;
    if (tid < 225) {
        float c0 = table[tid * 2 + 0];
        float c1 = table[tid * 2 + 1];
        float o0 = 0.f, o1 = 0.f, o2 = 0.f, o3 = 0.f;
        for (int m = 0; m < 512; ++m) {
            float hv = fmaf(c0, w1[m * 2], fmaf(c1, w1[m * 2 + 1], b1[m]));
            hv = fmaxf(hv, 0.f);
            o0 = fmaf(hv, w2[0 * 512 + m], o0);
            o1 = fmaf(hv, w2[1 * 512 + m], o1);
            o2 = fmaf(hv, w2[2 * 512 + m], o2);
            o3 = fmaf(hv, w2[3 * 512 + m], o3);
        }
        tbl[tid][0] = o0; tbl[tid][1] = o1; tbl[tid][2] = o2; tbl[tid][3] = o3;
    }
    __syncthreads();
    for (int e = tid; e < NTOK * NTOK; e += blockDim.x) {
        int ii = e >> 6, jj = e & 63;
        int id = rpi[e];  // rpi[ii][jj]
#pragma unroll
        for (int hh = 0; hh < NH; ++hh) {
            float v = tbl[id][hh];
            g_biasT[(hh * 64 + jj) * 64 + ii] = 16.f / (1.f + __expf(-v));
        }
    }
}

// ---------------------------------------------------------------------------
// K1/K3: fp32 GEMM, C[m][n] = sum_k A[m][k]*W[n][k] + bias[n]
//   M tiled by 64 (blockIdx.x), N = 128, K = 128 (fully resident in smem).
//   256 threads, per-thread 4x8 micro-tile. 96 KB dynamic smem, 2 CTAs/SM.
//   mode: 0 -> C=g_Q (ldc 128), 1 -> C=g_KV (ldc 256), 2 -> C=g_KV+128 (ldc 256)
//         3 -> A=g_ATT, C=Cext (ldc 128)
// ---------------------------------------------------------------------------
__global__ __launch_bounds__(256, 2)
void sgemm_k128(const float* __restrict__ Ain, const float* __restrict__ W,
                const float* __restrict__ bias, float* __restrict__ Cext,
                int mode, int ldc) {
    extern __shared__ float sm[];
    float* As = sm;           // [64][128]
    float* Bs = sm + 8192;    // [128][128]  Bs[k][n]

    const float* A = (mode == 3) ? (const float*)g_ATT : Ain;
    float* C = (mode == 0) ? g_Q
             : (mode == 1) ? g_KV
             : (mode == 2) ? (g_KV + 128)
             : Cext;

    const int tid = threadIdx.x;
    const int m0 = blockIdx.x * 64;

    // Load A tile (64x128), fully coalesced float4
    const float4* A4 = reinterpret_cast<const float4*>(A) + (size_t)m0 * 32;
    float4* As4 = reinterpret_cast<float4*>(As);
#pragma unroll
    for (int t = 0; t < 8; ++t) As4[tid + t * 256] = A4[tid + t * 256];

    // Load W (128x128 row-major over [n][k]) transposed into Bs[k][n].
    // Lane mapping keeps STS conflict-free (consecutive n per lane).
    // Global reads are strided (weights are L2-resident, cost acceptable).
#pragma unroll
    for (int t = 0; t < 16; ++t) {
        int idx = tid + t * 256;     // 4096 float4 total
        int n  = idx & 127;
        int kq = idx >> 7;           // 0..31
        float4 g = *reinterpret_cast<const float4*>(W + n * 128 + kq * 4);
        Bs[(kq * 4 + 0) * 128 + n] = g.x;
        Bs[(kq * 4 + 1) * 128 + n] = g.y;
        Bs[(kq * 4 + 2) * 128 + n] = g.z;
        Bs[(kq * 4 + 3) * 128 + n] = g.w;
    }
    __syncthreads();

    const int tcol = tid & 15;
    const int trow = tid >> 4;
    const int mb = trow * 4;
    const int nb = tcol * 8;

    float acc[4][8];
#pragma unroll
    for (int r = 0; r < 4; ++r)
#pragma unroll
        for (int c = 0; c < 8; ++c) acc[r][c] = 0.f;

#pragma unroll 4
    for (int k = 0; k < 128; ++k) {
        float4 b0 = *reinterpret_cast<const float4*>(&Bs[k * 128 + nb]);
        float4 b1 = *reinterpret_cast<const float4*>(&Bs[k * 128 + nb + 4]);
        float bv[8] = {b0.x, b0.y, b0.z, b0.w, b1.x, b1.y, b1.z, b1.w};
        float av[4];
        av[0] = As[(mb + 0) * 128 + k];
        av[1] = As[(mb + 1) * 128 + k];
        av[2] = As[(mb + 2) * 128 + k];
        av[3] = As[(mb + 3) * 128 + k];
#pragma unroll
        for (int r = 0; r < 4; ++r)
#pragma unroll
            for (int c = 0; c < 8; ++c)
                acc[r][c] = fmaf(av[r], bv[c], acc[r][c]);
    }

    float bb[8];
#pragma unroll
    for (int c = 0; c < 8; ++c) bb[c] = bias ? bias[nb + c] : 0.f;

#pragma unroll
    for (int r = 0; r < 4; ++r) {
        size_t row = (size_t)(m0 + mb + r);
        float* Cp = C + row * ldc + nb;
        float4 o0 = make_float4(acc[r][0] + bb[0], acc[r][1] + bb[1],
                                acc[r][2] + bb[2], acc[r][3] + bb[3]);
        float4 o1 = make_float4(acc[r][4] + bb[4], acc[r][5] + bb[5],
                                acc[r][6] + bb[6], acc[r][7] + bb[7]);
        *reinterpret_cast<float4*>(Cp)     = o0;
        *reinterpret_cast<float4*>(Cp + 4) = o1;
    }
}

// ---------------------------------------------------------------------------
// K2: fused cosine attention per window.
//   One CTA per window, 256 threads. Thread = (head h, query row i).
//   Stages q,k,v (96 KB) + biasT (64 KB) + maskT slice (16 KB) in smem.
//   Scores register-resident (fully unrolled 64-wide softmax).
// ---------------------------------------------------------------------------
__global__ __launch_bounds__(256, 1)
void attn_kernel(const float* __restrict__ logit_scale) {
    extern __shared__ float sm[];
    float* q_s    = sm;                 // 8192
    float* k_s    = q_s + 8192;         // 8192
    float* v_s    = k_s + 8192;         // 8192
    float* b_s    = v_s + 8192;         // 16384  [h][j][i]
    float* m_s    = b_s + 16384;        // 4096   [j][i]
    float* kinv_s = m_s + 4096;         // 256    [h][j]

    const int win = blockIdx.x;
    const int tid = threadIdx.x;

    // ---- stage everything into smem (coalesced float4) ----
    {
        const float4* Q4 = reinterpret_cast<const float4*>(g_Q + (size_t)win * 8192);
        float4* q4 = reinterpret_cast<float4*>(q_s);
#pragma unroll
        for (int t = 0; t < 8; ++t) q4[tid + t * 256] = Q4[tid + t * 256];

        const float* KVw = g_KV + (size_t)win * 16384;
        float4* k4 = reinterpret_cast<float4*>(k_s);
        float4* v4 = reinterpret_cast<float4*>(v_s);
#pragma unroll
        for (int t = 0; t < 8; ++t) {
            int idx = tid + t * 256;       // 2048 float4 (= 64 rows x 32)
            int tok = idx >> 5;
            int c   = idx & 31;
            k4[idx] = *reinterpret_cast<const float4*>(KVw + tok * 256 + c * 4);
            v4[idx] = *reinterpret_cast<const float4*>(KVw + tok * 256 + 128 + c * 4);
        }
        const float4* B4 = reinterpret_cast<const float4*>(g_biasT);
        float4* b4 = reinterpret_cast<float4*>(b_s);
#pragma unroll
        for (int t = 0; t < 16; ++t) b4[tid + t * 256] = B4[tid + t * 256];

        const float4* M4 = reinterpret_cast<const float4*>(
            g_maskT + (size_t)(win & (NMASK - 1)) * 4096);
        float4* m4 = reinterpret_cast<float4*>(m_s);
#pragma unroll
        for (int t = 0; t < 4; ++t) m4[tid + t * 256] = M4[tid + t * 256];
    }
    __syncthreads();

    const int h = tid >> 6;      // 0..3
    const int i = tid & 63;      // query row (also used as j for k-norms)

    // ---- k norms (one (h,j) pair per thread) ----
    {
        const float* kr = k_s + i * 128 + h * 32;
        float ss = 0.f;
#pragma unroll
        for (int d = 0; d < 32; ++d) ss = fmaf(kr[d], kr[d], ss);
        kinv_s[h * 64 + i] = 1.f / fmaxf(sqrtf(ss), 1e-12f);
    }

    // ---- q row into registers, fold scale into 1/||q|| ----
    float qr[32];
    {
        const float* qp = q_s + i * 128 + h * 32;
#pragma unroll
        for (int d = 0; d < 32; ++d) qr[d] = qp[d];
    }
    float qss = 0.f;
#pragma unroll
    for (int d = 0; d < 32; ++d) qss = fmaf(qr[d], qr[d], qss);
    float sc = __expf(fminf(logit_scale[h], 4.6051702f));   // min(ls, log(100))
    float qscale = sc / fmaxf(sqrtf(qss), 1e-12f);

    __syncthreads();   // kinv_s ready

    // ---- scores ----
    float s[64];
#pragma unroll
    for (int j = 0; j < 64; ++j) {
        const float* kr = k_s + j * 128 + h * 32;   // broadcast within warp
        float d0 = 0.f, d1 = 0.f, d2 = 0.f, d3 = 0.f;
#pragma unroll
        for (int d = 0; d < 32; d += 4) {
            d0 = fmaf(qr[d + 0], kr[d + 0], d0);
            d1 = fmaf(qr[d + 1], kr[d + 1], d1);
            d2 = fmaf(qr[d + 2], kr[d + 2], d2);
            d3 = fmaf(qr[d + 3], kr[d + 3], d3);
        }
        float dot = (d0 + d1) + (d2 + d3);
        s[j] = dot * qscale * kinv_s[h * 64 + j]
             + b_s[(h * 64 + j) * 64 + i]
             + m_s[j * 64 + i];
    }

    // ---- softmax ----
    float mx = s[0];
#pragma unroll
    for (int j = 1; j < 64; ++j) mx = fmaxf(mx, s[j]);
    float sum = 0.f;
#pragma unroll
    for (int j = 0; j < 64; ++j) { s[j] = __expf(s[j] - mx); sum += s[j]; }
    float inv = 1.f / sum;

    // ---- PV ----
    float acc[32];
#pragma unroll
    for (int d = 0; d < 32; ++d) acc[d] = 0.f;
#pragma unroll
    for (int j = 0; j < 64; ++j) {
        float p = s[j] * inv;
        const float* vr = v_s + j * 128 + h * 32;   // broadcast within warp
#pragma unroll
        for (int d = 0; d < 32; ++d) acc[d] = fmaf(p, vr[d], acc[d]);
    }

    // ---- write (contiguous 128 B per thread; sectors merge) ----
    float* Ow = g_ATT + (size_t)win * 8192 + i * 128 + h * 32;
#pragma unroll
    for (int d4 = 0; d4 < 8; ++d4)
        *reinterpret_cast<float4*>(Ow + d4 * 4) =
            make_float4(acc[d4 * 4 + 0], acc[d4 * 4 + 1],
                        acc[d4 * 4 + 2], acc[d4 * 4 + 3]);
}

// ---------------------------------------------------------------------------
// Launch
// ---------------------------------------------------------------------------
extern "C" void kernel_launch(void* const* d_in, const int* in_sizes, int n_in,
                              void* d_out, int out_size) {
    const float* x    = (const float*)d_in[0];
    const float* ctx  = (const float*)d_in[1];
    const float* mask = (const float*)d_in[2];
    const float* q_w  = (const float*)d_in[3];
    const float* q_b  = (const float*)d_in[4];
    const float* kv_w = (const float*)d_in[5];
    const float* v_b  = (const float*)d_in[6];
    const float* ls   = (const float*)d_in[7];
    const float* w1   = (const float*)d_in[8];
    const float* b1   = (const float*)d_in[9];
    const float* w2   = (const float*)d_in[10];
    const float* pw   = (const float*)d_in[11];
    const float* pb   = (const float*)d_in[12];
    const float* tbl  = (const float*)d_in[13];
    const int*   rpi  = (const int*)d_in[14];
    float* out = (float*)d_out;

    const int GEMM_SMEM = (8192 + 16384) * 4;                 // 96 KB
    const int ATTN_SMEM = (8192 * 3 + 16384 + 4096 + 256) * 4; // 181,248 B

    cudaFuncSetAttribute(sgemm_k128, cudaFuncAttributeMaxDynamicSharedMemorySize, GEMM_SMEM);
    cudaFuncSetAttribute(attn_kernel, cudaFuncAttributeMaxDynamicSharedMemorySize, ATTN_SMEM);

    // Prep (tiny)
    mask_transpose_kernel<<<NMASK, 256>>>(mask);
    cpb_bias_kernel<<<1, 256>>>(tbl, w1, b1, w2, rpi);

    const int MTILES = NWIN * NTOK / 64;   // 4096

    // Q = x @ q_w^T + q_b
    sgemm_k128<<<MTILES, 256, GEMM_SMEM>>>(x, q_w, q_b, nullptr, 0, DIM);
    // K = ctx @ kv_w[0:128]^T  (zero bias)
    sgemm_k128<<<MTILES, 256, GEMM_SMEM>>>(ctx, kv_w, nullptr, nullptr, 1, 2 * DIM);
    // V = ctx @ kv_w[128:256]^T + v_b
    sgemm_k128<<<MTILES, 256, GEMM_SMEM>>>(ctx, kv_w + 128 * 128, v_b, nullptr, 2, 2 * DIM);

    // Fused cosine attention
    attn_kernel<<<NWIN, 256, ATTN_SMEM>>>(ls);

    // out = att @ proj_w^T + proj_b
    sgemm_k128<<<MTILES, 256, GEMM_SMEM>>>(nullptr, pw, pb, out, 3, DIM);
}

// round 3
// speedup vs baseline: 2.0695x; 2.0695x over previous
#include <cuda_runtime.h>
#include <math.h>
#include <stdint.h>

// Problem constants
#define NWIN 4096
#define NTOK 64
#define DIM  128
#define NH   4
#define HD   32
#define NMASK 64

// ---------------------------------------------------------------------------
// Scratch (allocation-free: __device__ globals)
// ---------------------------------------------------------------------------
__device__ float g_Q  [NWIN * NTOK * DIM];        // 134 MB
__device__ float g_KV [NWIN * NTOK * 2 * DIM];    // 268 MB  (k: cols 0-127, v: 128-255)
__device__ float g_ATT[NWIN * NTOK * DIM];        // 134 MB
__device__ float g_biasT[NH * NTOK * NTOK];       // [h][j][i]
__device__ float g_maskT[NMASK * NTOK * NTOK];    // [w][j][i]

// ---------------------------------------------------------------------------
// K0a: transpose shift-mask per window: maskT[w][j][i] = mask[w][i][j]
// ---------------------------------------------------------------------------
__global__ void mask_transpose_kernel(const float* __restrict__ mask) {
    const int w = blockIdx.x;
    const float* mi = mask + (size_t)w * NTOK * NTOK;
    float* mo = g_maskT + (size_t)w * NTOK * NTOK;
    for (int idx = threadIdx.x; idx < NTOK * NTOK; idx += blockDim.x) {
        int i = idx >> 6, j = idx & 63;
        mo[j * 64 + i] = mi[i * 64 + j];
    }
}

// ---------------------------------------------------------------------------
// K0b: CPB-MLP relative position bias, gathered + transposed
// ---------------------------------------------------------------------------
__global__ void cpb_bias_kernel(const float* __restrict__ table,   // (225,2)
                                const float* __restrict__ w1,      // (512,2)
                                const float* __restrict__ b1,      // (512)
                                const float* __restrict__ w2,      // (4,512)
                                const int*   __restrict__ rpi) {   // (64,64)
    __shared__ float tbl[225][4];
    const int tid = threadIdx.x;
    if (tid < 225) {
        float c0 = table[tid * 2 + 0];
        float c1 = table[tid * 2 + 1];
        float o0 = 0.f, o1 = 0.f, o2 = 0.f, o3 = 0.f;
        for (int m = 0; m < 512; ++m) {
            float hv = fmaf(c0, w1[m * 2], fmaf(c1, w1[m * 2 + 1], b1[m]));
            hv = fmaxf(hv, 0.f);
            o0 = fmaf(hv, w2[0 * 512 + m], o0);
            o1 = fmaf(hv, w2[1 * 512 + m], o1);
            o2 = fmaf(hv, w2[2 * 512 + m], o2);
            o3 = fmaf(hv, w2[3 * 512 + m], o3);
        }
        tbl[tid][0] = o0; tbl[tid][1] = o1; tbl[tid][2] = o2; tbl[tid][3] = o3;
    }
    __syncthreads();
    for (int e = tid; e < NTOK * NTOK; e += blockDim.x) {
        int ii = e >> 6, jj = e & 63;
        int id = rpi[e];
#pragma unroll
        for (int hh = 0; hh < NH; ++hh) {
            float v = tbl[id][hh];
            g_biasT[(hh * 64 + jj) * 64 + ii] = 16.f / (1.f + __expf(-v));
        }
    }
}

// ---------------------------------------------------------------------------
// TF32 tensor-core GEMM: C[m][n] = sum_k A[m][k]*W[n][k] + bias[n]
//   CTA: 256 threads (8 warps), tile M=64, N=128, K=128 fully staged.
//   Warp tile 16x64 -> 8 x m16n8k8 mma per k-step, 16 k-steps.
//   Smem stride 132 floats -> conflict-free fragment LDS + aligned float4 STS.
//   mode 0: C=g_Q (ldc 128)          one half, bias=biasA
//   mode 1: C=g_KV (ldc 256)         TWO halves (K then V), reusing A tile
//   mode 3: A=g_ATT, C=Cext (ldc 128)
// ---------------------------------------------------------------------------
#define SLD 132

__device__ __forceinline__ uint32_t f2tf32(float f) {
    uint32_t u;
    asm("cvt.rna.tf32.f32 %0, %1;" : "=r"(u) : "f"(f));
    return u;
}

__device__ __forceinline__ void mma_tf32(float* c, const uint32_t* a,
                                         uint32_t b0, uint32_t b1) {
    asm volatile(
        "mma.sync.aligned.m16n8k8.row.col.f32.tf32.tf32.f32 "
        "{%0,%1,%2,%3}, {%4,%5,%6,%7}, {%8,%9}, {%0,%1,%2,%3};"
        : "+f"(c[0]), "+f"(c[1]), "+f"(c[2]), "+f"(c[3])
        : "r"(a[0]), "r"(a[1]), "r"(a[2]), "r"(a[3]), "r"(b0), "r"(b1));
}

__global__ __launch_bounds__(256, 2)
void gemm_tf32(const float* __restrict__ Ain, const float* __restrict__ Wg,
               const float* __restrict__ biasA, const float* __restrict__ biasB,
               float* __restrict__ Cext, int mode) {
    extern __shared__ float sm[];
    float* As = sm;                 // [64][SLD]
    float* Ws = sm + 64 * SLD;      // [128][SLD]

    const float* A = (mode == 3) ? (const float*)g_ATT : Ain;
    float* C; int ldc, halves;
    if (mode == 0)      { C = g_Q;  ldc = 128; halves = 1; }
    else if (mode == 1) { C = g_KV; ldc = 256; halves = 2; }
    else                { C = Cext; ldc = 128; halves = 1; }

    const int tid = threadIdx.x;
    const int m0 = blockIdx.x * 64;

    // Stage A tile (64x128) once, coalesced float4 -> padded smem
    {
        const float4* A4 = reinterpret_cast<const float4*>(A + (size_t)m0 * 128);
#pragma unroll
        for (int t = 0; t < 8; ++t) {
            int idx = tid + t * 256;          // 0..2047
            int r = idx >> 5, c = idx & 31;
            *reinterpret_cast<float4*>(&As[r * SLD + c * 4]) = A4[idx];
        }
    }

    const int lane = tid & 31, wid = tid >> 5;
    const int warpM = (wid >> 1) * 16;    // 0,16,32,48
    const int warpN = (wid & 1) * 64;     // 0,64
    const int g  = lane >> 2;             // 0..7
    const int tg = lane & 3;              // 0..3

    for (int half = 0; half < halves; ++half) {
        if (half > 0) __syncthreads();  // everyone done with previous Ws
        // Stage W half (128x128)
        {
            const float4* W4 = reinterpret_cast<const float4*>(Wg + (size_t)half * 16384);
#pragma unroll
            for (int t = 0; t < 16; ++t) {
                int idx = tid + t * 256;      // 0..4095
                int n = idx >> 5, c = idx & 31;
                *reinterpret_cast<float4*>(&Ws[n * SLD + c * 4]) = W4[idx];
            }
        }
        __syncthreads();

        float acc[8][4];
#pragma unroll
        for (int nt = 0; nt < 8; ++nt)
#pragma unroll
            for (int r = 0; r < 4; ++r) acc[nt][r] = 0.f;

#pragma unroll
        for (int ks = 0; ks < 16; ++ks) {
            const int k0 = ks * 8;
            uint32_t a[4];
            a[0] = f2tf32(As[(warpM + g)     * SLD + k0 + tg]);
            a[1] = f2tf32(As[(warpM + g + 8) * SLD + k0 + tg]);
            a[2] = f2tf32(As[(warpM + g)     * SLD + k0 + 4 + tg]);
            a[3] = f2tf32(As[(warpM + g + 8) * SLD + k0 + 4 + tg]);
#pragma unroll
            for (int nt = 0; nt < 8; ++nt) {
                const int n = warpN + nt * 8 + g;
                uint32_t b0 = f2tf32(Ws[n * SLD + k0 + tg]);
                uint32_t b1 = f2tf32(Ws[n * SLD + k0 + 4 + tg]);
                mma_tf32(acc[nt], a, b0, b1);
            }
        }

        // Epilogue
        const float* bias = (half == 0) ? biasA : biasB;
        float* Ch = C + ((mode == 1) ? half * 128 : 0);
        const int r0 = m0 + warpM + g;
#pragma unroll
        for (int nt = 0; nt < 8; ++nt) {
            const int col = warpN + nt * 8 + 2 * tg;
            float bb0 = bias ? __ldg(bias + col)     : 0.f;
            float bb1 = bias ? __ldg(bias + col + 1) : 0.f;
            float2 o0 = make_float2(acc[nt][0] + bb0, acc[nt][1] + bb1);
            float2 o1 = make_float2(acc[nt][2] + bb0, acc[nt][3] + bb1);
            *reinterpret_cast<float2*>(&Ch[(size_t)r0 * ldc + col])       = o0;
            *reinterpret_cast<float2*>(&Ch[(size_t)(r0 + 8) * ldc + col]) = o1;
        }
    }
}

// ---------------------------------------------------------------------------
// K2: fused cosine attention per window (fp32).
//   One CTA per window, 256 threads, thread = (head h, query row i).
//   Smem: k,v only (65 KB) -> 3 CTAs/SM. q from global (per-thread rows),
//   bias/mask via __ldg (both 64 KB, L2/L1 resident, coalesced over i=lane).
// ---------------------------------------------------------------------------
__global__ __launch_bounds__(256)
void attn_kernel(const float* __restrict__ logit_scale) {
    extern __shared__ float sm[];
    float* k_s    = sm;                 // 8192
    float* v_s    = k_s + 8192;         // 8192
    float* kinv_s = v_s + 8192;         // 256  [h][j]

    const int win = blockIdx.x;
    const int tid = threadIdx.x;

    // ---- stage k, v (coalesced float4) ----
    {
        const float* KVw = g_KV + (size_t)win * 16384;
        float4* k4 = reinterpret_cast<float4*>(k_s);
        float4* v4 = reinterpret_cast<float4*>(v_s);
#pragma unroll
        for (int t = 0; t < 8; ++t) {
            int idx = tid + t * 256;       // 2048 float4 (= 64 rows x 32)
            int tok = idx >> 5;
            int c   = idx & 31;
            k4[idx] = *reinterpret_cast<const float4*>(KVw + tok * 256 + c * 4);
            v4[idx] = *reinterpret_cast<const float4*>(KVw + tok * 256 + 128 + c * 4);
        }
    }
    __syncthreads();

    const int h = tid >> 6;      // 0..3
    const int i = tid & 63;      // query row (doubles as j for k-norms)

    // ---- k norms ----
    {
        const float* kr = k_s + i * 128 + h * 32;
        float ss = 0.f;
#pragma unroll
        for (int d = 0; d < 32; ++d) ss = fmaf(kr[d], kr[d], ss);
        kinv_s[h * 64 + i] = 1.f / fmaxf(sqrtf(ss), 1e-12f);
    }

    // ---- q row from global, fold scale into 1/||q|| ----
    float qr[32];
    {
        const float* qp = g_Q + (size_t)win * 8192 + i * 128 + h * 32;
#pragma unroll
        for (int d4 = 0; d4 < 8; ++d4) {
            float4 q4 = *reinterpret_cast<const float4*>(qp + d4 * 4);
            qr[d4 * 4 + 0] = q4.x; qr[d4 * 4 + 1] = q4.y;
            qr[d4 * 4 + 2] = q4.z; qr[d4 * 4 + 3] = q4.w;
        }
    }
    float qss = 0.f;
#pragma unroll
    for (int d = 0; d < 32; ++d) qss = fmaf(qr[d], qr[d], qss);
    float sc = __expf(fminf(logit_scale[h], 4.6051702f));   // min(ls, log(100))
    float qscale = sc / fmaxf(sqrtf(qss), 1e-12f);

    __syncthreads();   // kinv_s ready

    const float* biasp = g_biasT + (size_t)h * 4096 + i;          // [h][j][i]
    const float* maskp = g_maskT + (size_t)(win & (NMASK - 1)) * 4096 + i;

    // ---- scores ----
    float s[64];
#pragma unroll
    for (int j = 0; j < 64; ++j) {
        const float* kr = k_s + j * 128 + h * 32;   // broadcast within warp
        float d0 = 0.f, d1 = 0.f, d2 = 0.f, d3 = 0.f;
#pragma unroll
        for (int d4 = 0; d4 < 8; ++d4) {
            float4 kk = *reinterpret_cast<const float4*>(kr + d4 * 4);
            d0 = fmaf(qr[d4 * 4 + 0], kk.x, d0);
            d1 = fmaf(qr[d4 * 4 + 1], kk.y, d1);
            d2 = fmaf(qr[d4 * 4 + 2], kk.z, d2);
            d3 = fmaf(qr[d4 * 4 + 3], kk.w, d3);
        }
        float dot = (d0 + d1) + (d2 + d3);
        s[j] = dot * qscale * kinv_s[h * 64 + j]
             + __ldg(biasp + j * 64)
             + __ldg(maskp + j * 64);
    }

    // ---- softmax ----
    float mx = s[0];
#pragma unroll
    for (int j = 1; j < 64; ++j) mx = fmaxf(mx, s[j]);
    float sum = 0.f;
#pragma unroll
    for (int j = 0; j < 64; ++j) { s[j] = __expf(s[j] - mx); sum += s[j]; }
    float inv = 1.f / sum;

    // ---- PV ----
    float acc[32];
#pragma unroll
    for (int d = 0; d < 32; ++d) acc[d] = 0.f;
#pragma unroll
    for (int j = 0; j < 64; ++j) {
        float p = s[j] * inv;
        const float* vr = v_s + j * 128 + h * 32;   // broadcast within warp
#pragma unroll
        for (int d4 = 0; d4 < 8; ++d4) {
            float4 vv = *reinterpret_cast<const float4*>(vr + d4 * 4);
            acc[d4 * 4 + 0] = fmaf(p, vv.x, acc[d4 * 4 + 0]);
            acc[d4 * 4 + 1] = fmaf(p, vv.y, acc[d4 * 4 + 1]);
            acc[d4 * 4 + 2] = fmaf(p, vv.z, acc[d4 * 4 + 2]);
            acc[d4 * 4 + 3] = fmaf(p, vv.w, acc[d4 * 4 + 3]);
        }
    }

    // ---- write ----
    float* Ow = g_ATT + (size_t)win * 8192 + i * 128 + h * 32;
#pragma unroll
    for (int d4 = 0; d4 < 8; ++d4)
        *reinterpret_cast<float4*>(Ow + d4 * 4) =
            make_float4(acc[d4 * 4 + 0], acc[d4 * 4 + 1],
                        acc[d4 * 4 + 2], acc[d4 * 4 + 3]);
}

// ---------------------------------------------------------------------------
// Launch
// ---------------------------------------------------------------------------
extern "C" void kernel_launch(void* const* d_in, const int* in_sizes, int n_in,
                              void* d_out, int out_size) {
    const float* x    = (const float*)d_in[0];
    const float* ctx  = (const float*)d_in[1];
    const float* mask = (const float*)d_in[2];
    const float* q_w  = (const float*)d_in[3];
    const float* q_b  = (const float*)d_in[4];
    const float* kv_w = (const float*)d_in[5];
    const float* v_b  = (const float*)d_in[6];
    const float* ls   = (const float*)d_in[7];
    const float* w1   = (const float*)d_in[8];
    const float* b1   = (const float*)d_in[9];
    const float* w2   = (const float*)d_in[10];
    const float* pw   = (const float*)d_in[11];
    const float* pb   = (const float*)d_in[12];
    const float* tbl  = (const float*)d_in[13];
    const int*   rpi  = (const int*)d_in[14];
    float* out = (float*)d_out;

    const int GEMM_SMEM = (64 + 128) * SLD * 4;           // 101,376 B
    const int ATTN_SMEM = (8192 * 2 + 256) * 4;           // 66,560 B

    cudaFuncSetAttribute(gemm_tf32, cudaFuncAttributeMaxDynamicSharedMemorySize, GEMM_SMEM);
    cudaFuncSetAttribute(attn_kernel, cudaFuncAttributeMaxDynamicSharedMemorySize, ATTN_SMEM);

    // Prep (tiny)
    mask_transpose_kernel<<<NMASK, 256>>>(mask);
    cpb_bias_kernel<<<1, 256>>>(tbl, w1, b1, w2, rpi);

    const int MTILES = NWIN * NTOK / 64;   // 4096

    // Q = x @ q_w^T + q_b
    gemm_tf32<<<MTILES, 256, GEMM_SMEM>>>(x, q_w, q_b, nullptr, nullptr, 0);
    // K|V = ctx @ kv_w^T (+ [0;v_b]) — single pass over ctx, two W halves
    gemm_tf32<<<MTILES, 256, GEMM_SMEM>>>(ctx, kv_w, nullptr, v_b, nullptr, 1);

    // Fused cosine attention
    attn_kernel<<<NWIN, 256, ATTN_SMEM>>>(ls);

    // out = att @ proj_w^T + proj_b
    gemm_tf32<<<MTILES, 256, GEMM_SMEM>>>(x, pw, pb, nullptr, out, 3);
}

// round 9
// speedup vs baseline: 2.1836x; 1.0552x over previous
#include <cuda_runtime.h>
#include <math.h>
#include <stdint.h>

// Problem constants
#define NWIN 4096
#define NTOK 64
#define DIM  128
#define NH   4
#define HD   32
#define NMASK 64

// ---------------------------------------------------------------------------
// Scratch (allocation-free: __device__ globals; NEVER referenced from host)
// ---------------------------------------------------------------------------
__device__ float    g_Q  [NWIN * NTOK * DIM];        // 134 MB
__device__ float    g_KV [NWIN * NTOK * 2 * DIM];    // 268 MB (k: 0-127, v: 128-255)
__device__ float    g_ATT[NWIN * NTOK * DIM];        // 134 MB
__device__ float    g_biasT[NH * NTOK * NTOK];       // [h][j][i]
__device__ float    g_maskT[NMASK * NTOK * NTOK];    // [w][j][i]
__device__ uint32_t g_Wpk[4 * 16384];                // packed tf32 weights:
                                                     // 0=q_w, 1=kv_w(K), 2=kv_w(V), 3=proj_w

__device__ __forceinline__ uint32_t f2tf32(float f) {
    uint32_t u;
    asm("cvt.rna.tf32.f32 %0, %1;" : "=r"(u) : "f"(f));
    return u;
}

// ---------------------------------------------------------------------------
// K0a: transpose shift-mask per window: maskT[w][j][i] = mask[w][i][j]
// ---------------------------------------------------------------------------
__global__ void mask_transpose_kernel(const float* __restrict__ mask) {
    const int w = blockIdx.x;
    const float* mi = mask + (size_t)w * NTOK * NTOK;
    float* mo = g_maskT + (size_t)w * NTOK * NTOK;
    for (int idx = threadIdx.x; idx < NTOK * NTOK; idx += blockDim.x) {
        int i = idx >> 6, j = idx & 63;
        mo[j * 64 + i] = mi[i * 64 + j];
    }
}

// ---------------------------------------------------------------------------
// K0b: CPB-MLP relative position bias, gathered + transposed
// ---------------------------------------------------------------------------
__global__ void cpb_bias_kernel(const float* __restrict__ table,   // (225,2)
                                const float* __restrict__ w1,      // (512,2)
                                const float* __restrict__ b1,      // (512)
                                const float* __restrict__ w2,      // (4,512)
                                const int*   __restrict__ rpi) {   // (64,64)
    __shared__ float tbl[225][4];
    const int tid = threadIdx.x;
    if (tid < 225) {
        float c0 = table[tid * 2 + 0];
        float c1 = table[tid * 2 + 1];
        float o0 = 0.f, o1 = 0.f, o2 = 0.f, o3 = 0.f;
        for (int m = 0; m < 512; ++m) {
            float hv = fmaf(c0, w1[m * 2], fmaf(c1, w1[m * 2 + 1], b1[m]));
            hv = fmaxf(hv, 0.f);
            o0 = fmaf(hv, w2[0 * 512 + m], o0);
            o1 = fmaf(hv, w2[1 * 512 + m], o1);
            o2 = fmaf(hv, w2[2 * 512 + m], o2);
            o3 = fmaf(hv, w2[3 * 512 + m], o3);
        }
        tbl[tid][0] = o0; tbl[tid][1] = o1; tbl[tid][2] = o2; tbl[tid][3] = o3;
    }
    __syncthreads();
    for (int e = tid; e < NTOK * NTOK; e += blockDim.x) {
        int ii = e >> 6, jj = e & 63;
        int id = rpi[e];
#pragma unroll
        for (int hh = 0; hh < NH; ++hh) {
            float v = tbl[id][hh];
            g_biasT[(hh * 64 + jj) * 64 + ii] = 16.f / (1.f + __expf(-v));
        }
    }
}

// ---------------------------------------------------------------------------
// K0c: pack weights -> tf32 mma-fragment order.
//   Wpk[((ntile*8 + ks2)*32 + lane)*4 + reg]:
//     n = ntile*8 + (lane>>2), k = ks2*16 + reg*4 + (lane&3)
//   One LDS.128 per (ntile, ks2) yields {b0,b1,b2,b3} covering two k-steps.
// ---------------------------------------------------------------------------
__global__ void pack_weights_kernel(const float* __restrict__ qw,
                                    const float* __restrict__ kvw,
                                    const float* __restrict__ pw) {
    const int b = blockIdx.x;
    const float* W = (b == 0) ? qw : (b == 1) ? kvw : (b == 2) ? (kvw + 16384) : pw;
    uint32_t* out = g_Wpk + b * 16384;
    for (int idx = threadIdx.x; idx < 16384; idx += blockDim.x) {
        int reg = idx & 3, lane = (idx >> 2) & 31, ks2 = (idx >> 7) & 7, ntile = idx >> 10;
        int n = ntile * 8 + (lane >> 2);
        int k = ks2 * 16 + reg * 4 + (lane & 3);
        out[idx] = f2tf32(W[n * 128 + k]);
    }
}

// ---------------------------------------------------------------------------
// TF32 tensor-core GEMM: C[m][n] = sum_k A[m][k]*W[n][k] + bias[n]
//   CTA: 256 thr (8 warps, 2M x 4N), tile M=64, N=128, K=128 fully staged.
//   Warp tile 32x32. Weights selected via integer wsel (device-side address
//   computation — NO device-global pointer passed from host).
//   Mainloop: unroll 1 + per-mt sequencing keeps live regs ~70, no spill.
// ---------------------------------------------------------------------------
__device__ __forceinline__ void mma_tf32(float& c0, float& c1, float& c2, float& c3,
                                         uint32_t a0, uint32_t a1, uint32_t a2, uint32_t a3,
                                         uint32_t b0, uint32_t b1) {
    asm volatile(
        "mma.sync.aligned.m16n8k8.row.col.f32.tf32.tf32.f32 "
        "{%0,%1,%2,%3}, {%4,%5,%6,%7}, {%8,%9}, {%0,%1,%2,%3};"
        : "+f"(c0), "+f"(c1), "+f"(c2), "+f"(c3)
        : "r"(a0), "r"(a1), "r"(a2), "r"(a3), "r"(b0), "r"(b1));
}

#define A_PITCH 132   // words per (mtile,kstep) fragment slot (128 + 4 pad)

__global__ __launch_bounds__(256)
void gemm_tf32(const float* __restrict__ Ain,
               const float* __restrict__ biasA, const float* __restrict__ biasB,
               float* __restrict__ Cext, int mode, int wsel) {
    extern __shared__ uint32_t smu[];
    uint32_t* As = smu;              // 64 slots * 132 = 8448 words (33 KB)
    uint32_t* Ws = smu + 8448;       // 16384 words (64 KB)

    // Device-side symbol addressing only.
    const uint32_t* Wpk = g_Wpk + (size_t)wsel * 16384;
    const float* A = (mode == 3) ? (const float*)g_ATT : Ain;
    float* C; int ldc, halves;
    if (mode == 0)      { C = g_Q;  ldc = 128; halves = 1; }
    else if (mode == 1) { C = g_KV; ldc = 256; halves = 2; }
    else                { C = Cext; ldc = 128; halves = 1; }

    const int tid = threadIdx.x;
    const int m0 = blockIdx.x * 64;

    // ---- stage A (64x128) -> fragment-packed tf32 smem ----
    {
        const float4* A4 = reinterpret_cast<const float4*>(A + (size_t)m0 * 128);
#pragma unroll
        for (int t = 0; t < 8; ++t) {
            int idx = tid + t * 256;            // 0..2047
            int r = idx >> 5, c4 = idx & 31;    // row, float4-chunk (coalesced)
            float4 v = A4[idx];
            int mtile = r >> 4, g = r & 7, mh = (r >> 3) & 1;
            int slot = mtile * 16 + (c4 >> 1);
            int regb = (c4 & 1) * 2 + mh;
            uint32_t* base = As + slot * A_PITCH + g * 16 + regb;
            base[0]  = f2tf32(v.x);
            base[4]  = f2tf32(v.y);
            base[8]  = f2tf32(v.z);
            base[12] = f2tf32(v.w);
        }
    }

    const int lane = tid & 31, wid = tid >> 5;
    const int wm = wid >> 2;            // 0..1  (M offset 32*wm)
    const int wn = wid & 3;             // 0..3  (N offset 32*wn)
    const int g  = lane >> 2;           // 0..7
    const int tg = lane & 3;            // 0..3
    const uint32_t* Abase = As + lane * 4;
    const uint32_t* Bbase = Ws + lane * 4;

    for (int half = 0; half < halves; ++half) {
        if (half > 0) __syncthreads();  // everyone done with previous Ws
        // ---- stage packed W half (straight coalesced copy) ----
        {
            const float4* W4 = reinterpret_cast<const float4*>(Wpk + half * 16384);
            float4* Ws4 = reinterpret_cast<float4*>(Ws);
#pragma unroll
            for (int t = 0; t < 16; ++t) Ws4[tid + t * 256] = W4[tid + t * 256];
        }
        __syncthreads();

        float acc[2][4][4];
#pragma unroll
        for (int mt = 0; mt < 2; ++mt)
#pragma unroll
            for (int nt = 0; nt < 4; ++nt)
#pragma unroll
                for (int r = 0; r < 4; ++r) acc[mt][nt][r] = 0.f;

        // Mainloop: NOT unrolled (prevents load-hoisting register blowup).
#pragma unroll 1
        for (int ks2 = 0; ks2 < 8; ++ks2) {
            // ---- mt = 0 ----
            {
                const int sA = (wm * 2 + 0) * 16 + ks2 * 2;
                uint4 aL = *reinterpret_cast<const uint4*>(Abase + sA * A_PITCH);
                uint4 aH = *reinterpret_cast<const uint4*>(Abase + (sA + 1) * A_PITCH);
#pragma unroll
                for (int nt = 0; nt < 4; ++nt) {
                    uint4 b = *reinterpret_cast<const uint4*>(
                        Bbase + ((wn * 4 + nt) * 8 + ks2) * 128);
                    mma_tf32(acc[0][nt][0], acc[0][nt][1], acc[0][nt][2], acc[0][nt][3],
                             aL.x, aL.y, aL.z, aL.w, b.x, b.y);
                    mma_tf32(acc[0][nt][0], acc[0][nt][1], acc[0][nt][2], acc[0][nt][3],
                             aH.x, aH.y, aH.z, aH.w, b.z, b.w);
                }
            }
            // ---- mt = 1 ----
            {
                const int sA = (wm * 2 + 1) * 16 + ks2 * 2;
                uint4 aL = *reinterpret_cast<const uint4*>(Abase + sA * A_PITCH);
                uint4 aH = *reinterpret_cast<const uint4*>(Abase + (sA + 1) * A_PITCH);
#pragma unroll
                for (int nt = 0; nt < 4; ++nt) {
                    uint4 b = *reinterpret_cast<const uint4*>(
                        Bbase + ((wn * 4 + nt) * 8 + ks2) * 128);
                    mma_tf32(acc[1][nt][0], acc[1][nt][1], acc[1][nt][2], acc[1][nt][3],
                             aL.x, aL.y, aL.z, aL.w, b.x, b.y);
                    mma_tf32(acc[1][nt][0], acc[1][nt][1], acc[1][nt][2], acc[1][nt][3],
                             aH.x, aH.y, aH.z, aH.w, b.z, b.w);
                }
            }
        }

        // ---- epilogue ----
        const float* bias = (half == 0) ? biasA : biasB;
        float* Ch = C + ((mode == 1) ? half * 128 : 0);
#pragma unroll
        for (int mt = 0; mt < 2; ++mt) {
            const int r0 = m0 + wm * 32 + mt * 16 + g;
#pragma unroll
            for (int nt = 0; nt < 4; ++nt) {
                const int col = wn * 32 + nt * 8 + 2 * tg;
                float bb0 = bias ? __ldg(bias + col)     : 0.f;
                float bb1 = bias ? __ldg(bias + col + 1) : 0.f;
                float2 o0 = make_float2(acc[mt][nt][0] + bb0, acc[mt][nt][1] + bb1);
                float2 o1 = make_float2(acc[mt][nt][2] + bb0, acc[mt][nt][3] + bb1);
                *reinterpret_cast<float2*>(&Ch[(size_t)r0 * ldc + col])       = o0;
                *reinterpret_cast<float2*>(&Ch[(size_t)(r0 + 8) * ldc + col]) = o1;
            }
        }
    }
}

// ---------------------------------------------------------------------------
// K2: fused cosine attention per window (fp32).
//   One CTA per window, 256 threads, thread = (head h, query row i).
//   Smem: k,v only (65 KB) -> 3 CTAs/SM. q from global, bias/mask via __ldg.
//   (Unchanged from the kernel that passed twice.)
// ---------------------------------------------------------------------------
__global__ __launch_bounds__(256)
void attn_kernel(const float* __restrict__ logit_scale) {
    extern __shared__ float sm[];
    float* k_s    = sm;                 // 8192
    float* v_s    = k_s + 8192;         // 8192
    float* kinv_s = v_s + 8192;         // 256  [h][j]

    const int win = blockIdx.x;
    const int tid = threadIdx.x;

    {
        const float* KVw = g_KV + (size_t)win * 16384;
        float4* k4 = reinterpret_cast<float4*>(k_s);
        float4* v4 = reinterpret_cast<float4*>(v_s);
#pragma unroll
        for (int t = 0; t < 8; ++t) {
            int idx = tid + t * 256;
            int tok = idx >> 5;
            int c   = idx & 31;
            k4[idx] = *reinterpret_cast<const float4*>(KVw + tok * 256 + c * 4);
            v4[idx] = *reinterpret_cast<const float4*>(KVw + tok * 256 + 128 + c * 4);
        }
    }
    __syncthreads();

    const int h = tid >> 6;
    const int i = tid & 63;

    {
        const float* kr = k_s + i * 128 + h * 32;
        float ss = 0.f;
#pragma unroll
        for (int d = 0; d < 32; ++d) ss = fmaf(kr[d], kr[d], ss);
        kinv_s[h * 64 + i] = 1.f / fmaxf(sqrtf(ss), 1e-12f);
    }

    float qr[32];
    {
        const float* qp = g_Q + (size_t)win * 8192 + i * 128 + h * 32;
#pragma unroll
        for (int d4 = 0; d4 < 8; ++d4) {
            float4 q4 = *reinterpret_cast<const float4*>(qp + d4 * 4);
            qr[d4 * 4 + 0] = q4.x; qr[d4 * 4 + 1] = q4.y;
            qr[d4 * 4 + 2] = q4.z; qr[d4 * 4 + 3] = q4.w;
        }
    }
    float qss = 0.f;
#pragma unroll
    for (int d = 0; d < 32; ++d) qss = fmaf(qr[d], qr[d], qss);
    float sc = __expf(fminf(logit_scale[h], 4.6051702f));
    float qscale = sc / fmaxf(sqrtf(qss), 1e-12f);

    __syncthreads();

    const float* biasp = g_biasT + (size_t)h * 4096 + i;
    const float* maskp = g_maskT + (size_t)(win & (NMASK - 1)) * 4096 + i;

    float s[64];
#pragma unroll
    for (int j = 0; j < 64; ++j) {
        const float* kr = k_s + j * 128 + h * 32;
        float d0 = 0.f, d1 = 0.f, d2 = 0.f, d3 = 0.f;
#pragma unroll
        for (int d4 = 0; d4 < 8; ++d4) {
            float4 kk = *reinterpret_cast<const float4*>(kr + d4 * 4);
            d0 = fmaf(qr[d4 * 4 + 0], kk.x, d0);
            d1 = fmaf(qr[d4 * 4 + 1], kk.y, d1);
            d2 = fmaf(qr[d4 * 4 + 2], kk.z, d2);
            d3 = fmaf(qr[d4 * 4 + 3], kk.w, d3);
        }
        float dot = (d0 + d1) + (d2 + d3);
        s[j] = dot * qscale * kinv_s[h * 64 + j]
             + __ldg(biasp + j * 64)
             + __ldg(maskp + j * 64);
    }

    float mx = s[0];
#pragma unroll
    for (int j = 1; j < 64; ++j) mx = fmaxf(mx, s[j]);
    float sum = 0.f;
#pragma unroll
    for (int j = 0; j < 64; ++j) { s[j] = __expf(s[j] - mx); sum += s[j]; }
    float inv = 1.f / sum;

    float acc[32];
#pragma unroll
    for (int d = 0; d < 32; ++d) acc[d] = 0.f;
#pragma unroll
    for (int j = 0; j < 64; ++j) {
        float p = s[j] * inv;
        const float* vr = v_s + j * 128 + h * 32;
#pragma unroll
        for (int d4 = 0; d4 < 8; ++d4) {
            float4 vv = *reinterpret_cast<const float4*>(vr + d4 * 4);
            acc[d4 * 4 + 0] = fmaf(p, vv.x, acc[d4 * 4 + 0]);
            acc[d4 * 4 + 1] = fmaf(p, vv.y, acc[d4 * 4 + 1]);
            acc[d4 * 4 + 2] = fmaf(p, vv.z, acc[d4 * 4 + 2]);
            acc[d4 * 4 + 3] = fmaf(p, vv.w, acc[d4 * 4 + 3]);
        }
    }

    float* Ow = g_ATT + (size_t)win * 8192 + i * 128 + h * 32;
#pragma unroll
    for (int d4 = 0; d4 < 8; ++d4)
        *reinterpret_cast<float4*>(Ow + d4 * 4) =
            make_float4(acc[d4 * 4 + 0], acc[d4 * 4 + 1],
                        acc[d4 * 4 + 2], acc[d4 * 4 + 3]);
}

// ---------------------------------------------------------------------------
// Launch — only harness-provided pointers cross the host/device boundary.
// ---------------------------------------------------------------------------
extern "C" void kernel_launch(void* const* d_in, const int* in_sizes, int n_in,
                              void* d_out, int out_size) {
    const float* x    = (const float*)d_in[0];
    const float* ctx  = (const float*)d_in[1];
    const float* mask = (const float*)d_in[2];
    const float* q_w  = (const float*)d_in[3];
    const float* q_b  = (const float*)d_in[4];
    const float* kv_w = (const float*)d_in[5];
    const float* v_b  = (const float*)d_in[6];
    const float* ls   = (const float*)d_in[7];
    const float* w1   = (const float*)d_in[8];
    const float* b1   = (const float*)d_in[9];
    const float* w2   = (const float*)d_in[10];
    const float* pw   = (const float*)d_in[11];
    const float* pb   = (const float*)d_in[12];
    const float* tbl  = (const float*)d_in[13];
    const int*   rpi  = (const int*)d_in[14];
    float* out = (float*)d_out;

    const int GEMM_SMEM = (8448 + 16384) * 4;   // 99,328 B
    const int ATTN_SMEM = (8192 * 2 + 256) * 4; // 66,560 B

    cudaFuncSetAttribute(gemm_tf32, cudaFuncAttributeMaxDynamicSharedMemorySize, GEMM_SMEM);
    cudaFuncSetAttribute(attn_kernel, cudaFuncAttributeMaxDynamicSharedMemorySize, ATTN_SMEM);

    // Prep (tiny)
    mask_transpose_kernel<<<NMASK, 256>>>(mask);
    cpb_bias_kernel<<<1, 256>>>(tbl, w1, b1, w2, rpi);
    pack_weights_kernel<<<4, 256>>>(q_w, kv_w, pw);

    const int MTILES = NWIN * NTOK / 64;   // 4096

    // Q = x @ q_w^T + q_b
    gemm_tf32<<<MTILES, 256, GEMM_SMEM>>>(x, q_b, nullptr, nullptr, 0, 0);
    // K|V = ctx @ kv_w^T (+ [0;v_b]) — single pass over ctx, two packed halves
    gemm_tf32<<<MTILES, 256, GEMM_SMEM>>>(ctx, nullptr, v_b, nullptr, 1, 1);

    // Fused cosine attention
    attn_kernel<<<NWIN, 256, ATTN_SMEM>>>(ls);

    // out = att @ proj_w^T + proj_b
    gemm_tf32<<<MTILES, 256, GEMM_SMEM>>>(x, pb, nullptr, out, 3, 3);
}

// round 11
// speedup vs baseline: 2.4350x; 1.1151x over previous
#include <cuda_runtime.h>
#include <math.h>
#include <stdint.h>

// Problem constants
#define NWIN 4096
#define NTOK 64
#define DIM  128
#define NH   4
#define HD   32
#define NMASK 64

// ---------------------------------------------------------------------------
// Scratch (allocation-free: __device__ globals; NEVER referenced from host)
// ---------------------------------------------------------------------------
__device__ float    g_Q  [NWIN * NTOK * DIM];        // 134 MB
__device__ float    g_KV [NWIN * NTOK * 2 * DIM];    // 268 MB (k: 0-127, v: 128-255)
__device__ float    g_ATT[NWIN * NTOK * DIM];        // 134 MB
__device__ float    g_biasD[NH * NTOK * NTOK];       // [h][i][j]  (direct layout)
__device__ uint32_t g_Wpk[4 * 16384];                // packed tf32 weights:
                                                     // 0=q_w, 1=kv_w(K), 2=kv_w(V), 3=proj_w

__device__ __forceinline__ uint32_t f2tf32(float f) {
    uint32_t u;
    asm("cvt.rna.tf32.f32 %0, %1;" : "=r"(u) : "f"(f));
    return u;
}
__device__ __forceinline__ float tf32f(float f) {
    return __uint_as_float(f2tf32(f));
}

// ---------------------------------------------------------------------------
// K0b: CPB-MLP relative position bias, gathered, DIRECT layout [h][i][j]
// ---------------------------------------------------------------------------
__global__ void cpb_bias_kernel(const float* __restrict__ table,   // (225,2)
                                const float* __restrict__ w1,      // (512,2)
                                const float* __restrict__ b1,      // (512)
                                const float* __restrict__ w2,      // (4,512)
                                const int*   __restrict__ rpi) {   // (64,64)
    __shared__ float tbl[225][4];
    const int tid = threadIdx.x;
    if (tid < 225) {
        float c0 = table[tid * 2 + 0];
        float c1 = table[tid * 2 + 1];
        float o0 = 0.f, o1 = 0.f, o2 = 0.f, o3 = 0.f;
        for (int m = 0; m < 512; ++m) {
            float hv = fmaf(c0, w1[m * 2], fmaf(c1, w1[m * 2 + 1], b1[m]));
            hv = fmaxf(hv, 0.f);
            o0 = fmaf(hv, w2[0 * 512 + m], o0);
            o1 = fmaf(hv, w2[1 * 512 + m], o1);
            o2 = fmaf(hv, w2[2 * 512 + m], o2);
            o3 = fmaf(hv, w2[3 * 512 + m], o3);
        }
        tbl[tid][0] = o0; tbl[tid][1] = o1; tbl[tid][2] = o2; tbl[tid][3] = o3;
    }
    __syncthreads();
    for (int e = tid; e < NTOK * NTOK; e += blockDim.x) {
        int id = rpi[e];   // e = ii*64 + jj
#pragma unroll
        for (int hh = 0; hh < NH; ++hh) {
            float v = tbl[id][hh];
            g_biasD[hh * 4096 + e] = 16.f / (1.f + __expf(-v));
        }
    }
}

// ---------------------------------------------------------------------------
// K0c: pack weights -> tf32 mma-fragment order.
// ---------------------------------------------------------------------------
__global__ void pack_weights_kernel(const float* __restrict__ qw,
                                    const float* __restrict__ kvw,
                                    const float* __restrict__ pw) {
    const int b = blockIdx.x;
    const float* W = (b == 0) ? qw : (b == 1) ? kvw : (b == 2) ? (kvw + 16384) : pw;
    uint32_t* out = g_Wpk + b * 16384;
    for (int idx = threadIdx.x; idx < 16384; idx += blockDim.x) {
        int reg = idx & 3, lane = (idx >> 2) & 31, ks2 = (idx >> 7) & 7, ntile = idx >> 10;
        int n = ntile * 8 + (lane >> 2);
        int k = ks2 * 16 + reg * 4 + (lane & 3);
        out[idx] = f2tf32(W[n * 128 + k]);
    }
}

// ---------------------------------------------------------------------------
// TF32 tensor-core GEMM (unchanged from passing R9 kernel)
// ---------------------------------------------------------------------------
__device__ __forceinline__ void mma_tf32(float& c0, float& c1, float& c2, float& c3,
                                         uint32_t a0, uint32_t a1, uint32_t a2, uint32_t a3,
                                         uint32_t b0, uint32_t b1) {
    asm volatile(
        "mma.sync.aligned.m16n8k8.row.col.f32.tf32.tf32.f32 "
        "{%0,%1,%2,%3}, {%4,%5,%6,%7}, {%8,%9}, {%0,%1,%2,%3};"
        : "+f"(c0), "+f"(c1), "+f"(c2), "+f"(c3)
        : "r"(a0), "r"(a1), "r"(a2), "r"(a3), "r"(b0), "r"(b1));
}
__device__ __forceinline__ void mma_tf32f(float& c0, float& c1, float& c2, float& c3,
                                          float a0, float a1, float a2, float a3,
                                          float b0, float b1) {
    mma_tf32(c0, c1, c2, c3,
             __float_as_uint(a0), __float_as_uint(a1),
             __float_as_uint(a2), __float_as_uint(a3),
             __float_as_uint(b0), __float_as_uint(b1));
}

#define A_PITCH 132

__global__ __launch_bounds__(256)
void gemm_tf32(const float* __restrict__ Ain,
               const float* __restrict__ biasA, const float* __restrict__ biasB,
               float* __restrict__ Cext, int mode, int wsel) {
    extern __shared__ uint32_t smu[];
    uint32_t* As = smu;              // 8448 words
    uint32_t* Ws = smu + 8448;       // 16384 words

    const uint32_t* Wpk = g_Wpk + (size_t)wsel * 16384;
    const float* A = (mode == 3) ? (const float*)g_ATT : Ain;
    float* C; int ldc, halves;
    if (mode == 0)      { C = g_Q;  ldc = 128; halves = 1; }
    else if (mode == 1) { C = g_KV; ldc = 256; halves = 2; }
    else                { C = Cext; ldc = 128; halves = 1; }

    const int tid = threadIdx.x;
    const int m0 = blockIdx.x * 64;

    {
        const float4* A4 = reinterpret_cast<const float4*>(A + (size_t)m0 * 128);
#pragma unroll
        for (int t = 0; t < 8; ++t) {
            int idx = tid + t * 256;
            int r = idx >> 5, c4 = idx & 31;
            float4 v = A4[idx];
            int mtile = r >> 4, g = r & 7, mh = (r >> 3) & 1;
            int slot = mtile * 16 + (c4 >> 1);
            int regb = (c4 & 1) * 2 + mh;
            uint32_t* base = As + slot * A_PITCH + g * 16 + regb;
            base[0]  = f2tf32(v.x);
            base[4]  = f2tf32(v.y);
            base[8]  = f2tf32(v.z);
            base[12] = f2tf32(v.w);
        }
    }

    const int lane = tid & 31, wid = tid >> 5;
    const int wm = wid >> 2;
    const int wn = wid & 3;
    const int g  = lane >> 2;
    const int tg = lane & 3;
    const uint32_t* Abase = As + lane * 4;
    const uint32_t* Bbase = Ws + lane * 4;

    for (int half = 0; half < halves; ++half) {
        if (half > 0) __syncthreads();
        {
            const float4* W4 = reinterpret_cast<const float4*>(Wpk + half * 16384);
            float4* Ws4 = reinterpret_cast<float4*>(Ws);
#pragma unroll
            for (int t = 0; t < 16; ++t) Ws4[tid + t * 256] = W4[tid + t * 256];
        }
        __syncthreads();

        float acc[2][4][4];
#pragma unroll
        for (int mt = 0; mt < 2; ++mt)
#pragma unroll
            for (int nt = 0; nt < 4; ++nt)
#pragma unroll
                for (int r = 0; r < 4; ++r) acc[mt][nt][r] = 0.f;

#pragma unroll 1
        for (int ks2 = 0; ks2 < 8; ++ks2) {
            {
                const int sA = (wm * 2 + 0) * 16 + ks2 * 2;
                uint4 aL = *reinterpret_cast<const uint4*>(Abase + sA * A_PITCH);
                uint4 aH = *reinterpret_cast<const uint4*>(Abase + (sA + 1) * A_PITCH);
#pragma unroll
                for (int nt = 0; nt < 4; ++nt) {
                    uint4 b = *reinterpret_cast<const uint4*>(
                        Bbase + ((wn * 4 + nt) * 8 + ks2) * 128);
                    mma_tf32(acc[0][nt][0], acc[0][nt][1], acc[0][nt][2], acc[0][nt][3],
                             aL.x, aL.y, aL.z, aL.w, b.x, b.y);
                    mma_tf32(acc[0][nt][0], acc[0][nt][1], acc[0][nt][2], acc[0][nt][3],
                             aH.x, aH.y, aH.z, aH.w, b.z, b.w);
                }
            }
            {
                const int sA = (wm * 2 + 1) * 16 + ks2 * 2;
                uint4 aL = *reinterpret_cast<const uint4*>(Abase + sA * A_PITCH);
                uint4 aH = *reinterpret_cast<const uint4*>(Abase + (sA + 1) * A_PITCH);
#pragma unroll
                for (int nt = 0; nt < 4; ++nt) {
                    uint4 b = *reinterpret_cast<const uint4*>(
                        Bbase + ((wn * 4 + nt) * 8 + ks2) * 128);
                    mma_tf32(acc[1][nt][0], acc[1][nt][1], acc[1][nt][2], acc[1][nt][3],
                             aL.x, aL.y, aL.z, aL.w, b.x, b.y);
                    mma_tf32(acc[1][nt][0], acc[1][nt][1], acc[1][nt][2], acc[1][nt][3],
                             aH.x, aH.y, aH.z, aH.w, b.z, b.w);
                }
            }
        }

        const float* bias = (half == 0) ? biasA : biasB;
        float* Ch = C + ((mode == 1) ? half * 128 : 0);
#pragma unroll
        for (int mt = 0; mt < 2; ++mt) {
            const int r0 = m0 + wm * 32 + mt * 16 + g;
#pragma unroll
            for (int nt = 0; nt < 4; ++nt) {
                const int col = wn * 32 + nt * 8 + 2 * tg;
                float bb0 = bias ? __ldg(bias + col)     : 0.f;
                float bb1 = bias ? __ldg(bias + col + 1) : 0.f;
                float2 o0 = make_float2(acc[mt][nt][0] + bb0, acc[mt][nt][1] + bb1);
                float2 o1 = make_float2(acc[mt][nt][2] + bb0, acc[mt][nt][3] + bb1);
                *reinterpret_cast<float2*>(&Ch[(size_t)r0 * ldc + col])       = o0;
                *reinterpret_cast<float2*>(&Ch[(size_t)(r0 + 8) * ldc + col]) = o1;
            }
        }
    }
}

// ---------------------------------------------------------------------------
// K2: TENSORIZED cosine attention. One CTA/window, 256 thr (8 warps).
//   Warp w: head h = w>>1, row-half mh = w&1 (32 query rows).
//   QK^T: tf32x3 (hi*hi + hi*lo + lo*hi) for fp32-grade scores.
//   PV:   single tf32 (P and V quantized, error ~3e-4).
//   Smem (words): qhi[4][64][36]=9216 | qlo=9216 | kar[4][hi 2304|lo 2304]
//                 (P[h] pitch-68 overlays kar[h]) | vn[4][64][40]=10240
//   Total 47104 words = 188,416 B -> 1 CTA/SM.
// ---------------------------------------------------------------------------
__global__ __launch_bounds__(256)
void attn_mma_kernel(const float* __restrict__ ls, const float* __restrict__ mask) {
    extern __shared__ float smf[];
    float* qhi = smf;               // 9216
    float* qlo = smf + 9216;        // 9216
    float* kar = smf + 18432;       // 18432 (4 heads x [khi 2304 | klo 2304])
    float* vn  = smf + 36864;       // 10240

    const int win = blockIdx.x, tid = threadIdx.x;

    // ---------- staging: thread = (sh = tid>>6, sr = tid&63) ----------
    {
        const int sh = tid >> 6, sr = tid & 63;
        float buf[32];
        // Q: normalize, fold scale, split tf32 hi/lo, rotated store (pitch 36)
        {
            const float4* p = reinterpret_cast<const float4*>(
                g_Q + (size_t)win * 8192 + sr * 128 + sh * 32);
#pragma unroll
            for (int t = 0; t < 8; ++t) {
                float4 x = p[t];
                buf[4*t] = x.x; buf[4*t+1] = x.y; buf[4*t+2] = x.z; buf[4*t+3] = x.w;
            }
            float ssum = 0.f;
#pragma unroll
            for (int d = 0; d < 32; ++d) ssum = fmaf(buf[d], buf[d], ssum);
            float sc = __expf(fminf(ls[sh], 4.6051702f));
            float qs = sc / fmaxf(sqrtf(ssum), 1e-12f);
            float* dh = qhi + (sh * 64 + sr) * 36;
            float* dl = qlo + (sh * 64 + sr) * 36;
#pragma unroll
            for (int d = 0; d < 32; ++d) {
                float x = buf[d] * qs;
                float hi = tf32f(x);
                float lo = tf32f(x - hi);
                int dd = (d + sr) & 31;
                dh[dd] = hi; dl[dd] = lo;
            }
        }
        // K: normalize, split hi/lo
        {
            const float4* p = reinterpret_cast<const float4*>(
                g_KV + (size_t)win * 16384 + sr * 256 + sh * 32);
#pragma unroll
            for (int t = 0; t < 8; ++t) {
                float4 x = p[t];
                buf[4*t] = x.x; buf[4*t+1] = x.y; buf[4*t+2] = x.z; buf[4*t+3] = x.w;
            }
            float ssum = 0.f;
#pragma unroll
            for (int d = 0; d < 32; ++d) ssum = fmaf(buf[d], buf[d], ssum);
            float kqs = 1.f / fmaxf(sqrtf(ssum), 1e-12f);
            float* dh = kar + sh * 4608 + sr * 36;
            float* dl = dh + 2304;
#pragma unroll
            for (int d = 0; d < 32; ++d) {
                float x = buf[d] * kqs;
                float hi = tf32f(x);
                float lo = tf32f(x - hi);
                int dd = (d + sr) & 31;
                dh[dd] = hi; dl[dd] = lo;
            }
        }
        // V: tf32, rotated store (pitch 40)
        {
            const float4* p = reinterpret_cast<const float4*>(
                g_KV + (size_t)win * 16384 + sr * 256 + 128 + sh * 32);
#pragma unroll
            for (int t = 0; t < 8; ++t) {
                float4 x = p[t];
                buf[4*t] = x.x; buf[4*t+1] = x.y; buf[4*t+2] = x.z; buf[4*t+3] = x.w;
            }
            float* dv = vn + (sh * 64 + sr) * 40;
#pragma unroll
            for (int d = 0; d < 32; ++d) dv[(d + sr) & 31] = tf32f(buf[d]);
        }
    }
    __syncthreads();

    // ---------- per-warp mma work ----------
    const int w = tid >> 5, lane = tid & 31;
    const int h = w >> 1, mh = w & 1;
    const int g = lane >> 2, tg = lane & 3;

    const float* Qh = qhi + h * 2304;
    const float* Ql = qlo + h * 2304;
    const float* Kh = kar + h * 4608;
    const float* Kl = Kh + 2304;

    float acc[2][8][4];
#pragma unroll
    for (int mt = 0; mt < 2; ++mt)
#pragma unroll
        for (int nt = 0; nt < 8; ++nt)
#pragma unroll
            for (int r = 0; r < 4; ++r) acc[mt][nt][r] = 0.f;

    // ---- QK^T: m64(n per warp 32) x n64 x k32 via tf32x3 ----
#pragma unroll 1
    for (int ks = 0; ks < 4; ++ks) {
        const int c0 = ks * 8 + tg, c1 = c0 + 4;
        float ah[2][4], al[2][4];
#pragma unroll
        for (int mt = 0; mt < 2; ++mt) {
            int ra = mh * 32 + mt * 16 + g, rb = ra + 8;
            int oa0 = ra * 36 + ((c0 + ra) & 31);
            int ob0 = rb * 36 + ((c0 + rb) & 31);
            int oa1 = ra * 36 + ((c1 + ra) & 31);
            int ob1 = rb * 36 + ((c1 + rb) & 31);
            ah[mt][0] = Qh[oa0]; ah[mt][1] = Qh[ob0];
            ah[mt][2] = Qh[oa1]; ah[mt][3] = Qh[ob1];
            al[mt][0] = Ql[oa0]; al[mt][1] = Ql[ob0];
            al[mt][2] = Ql[oa1]; al[mt][3] = Ql[ob1];
        }
#pragma unroll
        for (int nt = 0; nt < 8; ++nt) {
            int j = nt * 8 + g;
            int o0 = j * 36 + ((c0 + j) & 31);
            int o1 = j * 36 + ((c1 + j) & 31);
            float bh0 = Kh[o0], bh1 = Kh[o1];
            float bl0 = Kl[o0], bl1 = Kl[o1];
#pragma unroll
            for (int mt = 0; mt < 2; ++mt) {
                mma_tf32f(acc[mt][nt][0], acc[mt][nt][1], acc[mt][nt][2], acc[mt][nt][3],
                          ah[mt][0], ah[mt][1], ah[mt][2], ah[mt][3], bh0, bh1);
                mma_tf32f(acc[mt][nt][0], acc[mt][nt][1], acc[mt][nt][2], acc[mt][nt][3],
                          ah[mt][0], ah[mt][1], ah[mt][2], ah[mt][3], bl0, bl1);
                mma_tf32f(acc[mt][nt][0], acc[mt][nt][1], acc[mt][nt][2], acc[mt][nt][3],
                          al[mt][0], al[mt][1], al[mt][2], al[mt][3], bh0, bh1);
            }
        }
    }

    // ---- bias + mask (direct layouts, float2 loads) ----
    {
        const float* bias = g_biasD + h * 4096;
        const float* msk  = mask + (size_t)(win & (NMASK - 1)) * 4096;
#pragma unroll
        for (int mt = 0; mt < 2; ++mt) {
            int ra = mh * 32 + mt * 16 + g, rb = ra + 8;
#pragma unroll
            for (int nt = 0; nt < 8; ++nt) {
                int col = nt * 8 + 2 * tg;
                float2 ba = *reinterpret_cast<const float2*>(bias + ra * 64 + col);
                float2 ma = *reinterpret_cast<const float2*>(msk  + ra * 64 + col);
                float2 bb = *reinterpret_cast<const float2*>(bias + rb * 64 + col);
                float2 mb = *reinterpret_cast<const float2*>(msk  + rb * 64 + col);
                acc[mt][nt][0] += ba.x + ma.x;
                acc[mt][nt][1] += ba.y + ma.y;
                acc[mt][nt][2] += bb.x + mb.x;
                acc[mt][nt][3] += bb.y + mb.y;
            }
        }
    }

    // ---- softmax over j (64 cols): per lane 4 rows x 16 cols, quad shuffles ----
#pragma unroll
    for (int mt = 0; mt < 2; ++mt) {
#pragma unroll
        for (int hf = 0; hf < 2; ++hf) {
            float m = -1e30f;
#pragma unroll
            for (int nt = 0; nt < 8; ++nt)
                m = fmaxf(m, fmaxf(acc[mt][nt][hf * 2], acc[mt][nt][hf * 2 + 1]));
            m = fmaxf(m, __shfl_xor_sync(0xffffffffu, m, 1));
            m = fmaxf(m, __shfl_xor_sync(0xffffffffu, m, 2));
            float s = 0.f;
#pragma unroll
            for (int nt = 0; nt < 8; ++nt) {
                float e0 = __expf(acc[mt][nt][hf * 2]     - m);
                float e1 = __expf(acc[mt][nt][hf * 2 + 1] - m);
                acc[mt][nt][hf * 2]     = e0;
                acc[mt][nt][hf * 2 + 1] = e1;
                s += e0 + e1;
            }
            s += __shfl_xor_sync(0xffffffffu, s, 1);
            s += __shfl_xor_sync(0xffffffffu, s, 2);
            float inv = 1.f / s;
#pragma unroll
            for (int nt = 0; nt < 8; ++nt) {
                acc[mt][nt][hf * 2]     *= inv;
                acc[mt][nt][hf * 2 + 1] *= inv;
            }
        }
    }

    __syncthreads();   // all warps done reading K before P overlays kar

    // ---- store P (tf32, pitch 68) into kar[h] region ----
    float* P = kar + h * 4608;
#pragma unroll
    for (int mt = 0; mt < 2; ++mt) {
        int ra = mh * 32 + mt * 16 + g, rb = ra + 8;
#pragma unroll
        for (int nt = 0; nt < 8; ++nt) {
            int col = nt * 8 + 2 * tg;
            float2 p0 = make_float2(tf32f(acc[mt][nt][0]), tf32f(acc[mt][nt][1]));
            float2 p1 = make_float2(tf32f(acc[mt][nt][2]), tf32f(acc[mt][nt][3]));
            *reinterpret_cast<float2*>(P + ra * 68 + col) = p0;
            *reinterpret_cast<float2*>(P + rb * 68 + col) = p1;
        }
    }
    __syncwarp();

    // ---- PV: m32(warp) x n32 x k64 ----
    const float* Vh = vn + h * 2560;
    float o[2][4][4];
#pragma unroll
    for (int mt = 0; mt < 2; ++mt)
#pragma unroll
        for (int nt = 0; nt < 4; ++nt)
#pragma unroll
            for (int r = 0; r < 4; ++r) o[mt][nt][r] = 0.f;

#pragma unroll 1
    for (int ks = 0; ks < 8; ++ks) {
        const int j0 = ks * 8 + tg, j1 = j0 + 4;
        float pa[2][4];
#pragma unroll
        for (int mt = 0; mt < 2; ++mt) {
            int ra = mh * 32 + mt * 16 + g, rb = ra + 8;
            pa[mt][0] = P[ra * 68 + j0];
            pa[mt][1] = P[rb * 68 + j0];
            pa[mt][2] = P[ra * 68 + j1];
            pa[mt][3] = P[rb * 68 + j1];
        }
#pragma unroll
        for (int nt = 0; nt < 4; ++nt) {
            int d = nt * 8 + g;
            float vb0 = Vh[j0 * 40 + ((d + j0) & 31)];
            float vb1 = Vh[j1 * 40 + ((d + j1) & 31)];
#pragma unroll
            for (int mt = 0; mt < 2; ++mt)
                mma_tf32f(o[mt][nt][0], o[mt][nt][1], o[mt][nt][2], o[mt][nt][3],
                          pa[mt][0], pa[mt][1], pa[mt][2], pa[mt][3], vb0, vb1);
        }
    }

    // ---- write O to g_ATT ----
    {
        float* Ow = g_ATT + (size_t)win * 8192 + h * 32;
#pragma unroll
        for (int mt = 0; mt < 2; ++mt) {
            int ra = mh * 32 + mt * 16 + g, rb = ra + 8;
#pragma unroll
            for (int nt = 0; nt < 4; ++nt) {
                int d = nt * 8 + 2 * tg;
                *reinterpret_cast<float2*>(Ow + ra * 128 + d) =
                    make_float2(o[mt][nt][0], o[mt][nt][1]);
                *reinterpret_cast<float2*>(Ow + rb * 128 + d) =
                    make_float2(o[mt][nt][2], o[mt][nt][3]);
            }
        }
    }
}

// ---------------------------------------------------------------------------
// Launch — only harness-provided pointers cross the host/device boundary.
// ---------------------------------------------------------------------------
extern "C" void kernel_launch(void* const* d_in, const int* in_sizes, int n_in,
                              void* d_out, int out_size) {
    const float* x    = (const float*)d_in[0];
    const float* ctx  = (const float*)d_in[1];
    const float* mask = (const float*)d_in[2];
    const float* q_w  = (const float*)d_in[3];
    const float* q_b  = (const float*)d_in[4];
    const float* kv_w = (const float*)d_in[5];
    const float* v_b  = (const float*)d_in[6];
    const float* ls   = (const float*)d_in[7];
    const float* w1   = (const float*)d_in[8];
    const float* b1   = (const float*)d_in[9];
    const float* w2   = (const float*)d_in[10];
    const float* pw   = (const float*)d_in[11];
    const float* pb   = (const float*)d_in[12];
    const float* tbl  = (const float*)d_in[13];
    const int*   rpi  = (const int*)d_in[14];
    float* out = (float*)d_out;

    const int GEMM_SMEM = (8448 + 16384) * 4;   // 99,328 B
    const int ATTN_SMEM = 47104 * 4;            // 188,416 B

    cudaFuncSetAttribute(gemm_tf32, cudaFuncAttributeMaxDynamicSharedMemorySize, GEMM_SMEM);
    cudaFuncSetAttribute(attn_mma_kernel, cudaFuncAttributeMaxDynamicSharedMemorySize, ATTN_SMEM);

    // Prep (tiny)
    cpb_bias_kernel<<<1, 256>>>(tbl, w1, b1, w2, rpi);
    pack_weights_kernel<<<4, 256>>>(q_w, kv_w, pw);

    const int MTILES = NWIN * NTOK / 64;   // 4096

    // Q = x @ q_w^T + q_b
    gemm_tf32<<<MTILES, 256, GEMM_SMEM>>>(x, q_b, nullptr, nullptr, 0, 0);
    // K|V = ctx @ kv_w^T (+ [0;v_b]) — single pass, two packed halves
    gemm_tf32<<<MTILES, 256, GEMM_SMEM>>>(ctx, nullptr, v_b, nullptr, 1, 1);

    // Tensorized fused cosine attention
    attn_mma_kernel<<<NWIN, 256, ATTN_SMEM>>>(ls, mask);

    // out = att @ proj_w^T + proj_b
    gemm_tf32<<<MTILES, 256, GEMM_SMEM>>>(x, pb, nullptr, out, 3, 3);
}

// round 12
// speedup vs baseline: 2.6568x; 1.0911x over previous
#include <cuda_runtime.h>
#include <math.h>
#include <stdint.h>

// Problem constants
#define NWIN 4096
#define NTOK 64
#define DIM  128
#define NH   4
#define HD   32
#define NMASK 64

// ---------------------------------------------------------------------------
// Scratch (allocation-free: __device__ globals; NEVER referenced from host)
// ---------------------------------------------------------------------------
__device__ float    g_Q  [NWIN * NTOK * DIM];        // 134 MB
__device__ float    g_KV [NWIN * NTOK * 2 * DIM];    // 268 MB (k: 0-127, v: 128-255)
__device__ float    g_ATT[NWIN * NTOK * DIM];        // 134 MB
__device__ float    g_biasD[NH * NTOK * NTOK];       // [h][i][j]  (direct layout)
__device__ uint32_t g_Wpk[4 * 16384];                // packed tf32 weights

__device__ __forceinline__ uint32_t f2tf32(float f) {
    uint32_t u;
    asm("cvt.rna.tf32.f32 %0, %1;" : "=r"(u) : "f"(f));
    return u;
}
__device__ __forceinline__ float tf32f(float f) {
    return __uint_as_float(f2tf32(f));
}

// ---------------------------------------------------------------------------
// K0b: CPB-MLP relative position bias, gathered, DIRECT layout [h][i][j]
// ---------------------------------------------------------------------------
__global__ void cpb_bias_kernel(const float* __restrict__ table,
                                const float* __restrict__ w1,
                                const float* __restrict__ b1,
                                const float* __restrict__ w2,
                                const int*   __restrict__ rpi) {
    __shared__ float tbl[225][4];
    const int tid = threadIdx.x;
    if (tid < 225) {
        float c0 = table[tid * 2 + 0];
        float c1 = table[tid * 2 + 1];
        float o0 = 0.f, o1 = 0.f, o2 = 0.f, o3 = 0.f;
        for (int m = 0; m < 512; ++m) {
            float hv = fmaf(c0, w1[m * 2], fmaf(c1, w1[m * 2 + 1], b1[m]));
            hv = fmaxf(hv, 0.f);
            o0 = fmaf(hv, w2[0 * 512 + m], o0);
            o1 = fmaf(hv, w2[1 * 512 + m], o1);
            o2 = fmaf(hv, w2[2 * 512 + m], o2);
            o3 = fmaf(hv, w2[3 * 512 + m], o3);
        }
        tbl[tid][0] = o0; tbl[tid][1] = o1; tbl[tid][2] = o2; tbl[tid][3] = o3;
    }
    __syncthreads();
    for (int e = tid; e < NTOK * NTOK; e += blockDim.x) {
        int id = rpi[e];
#pragma unroll
        for (int hh = 0; hh < NH; ++hh) {
            float v = tbl[id][hh];
            g_biasD[hh * 4096 + e] = 16.f / (1.f + __expf(-v));
        }
    }
}

// ---------------------------------------------------------------------------
// K0c: pack weights -> tf32 mma-fragment order.
// ---------------------------------------------------------------------------
__global__ void pack_weights_kernel(const float* __restrict__ qw,
                                    const float* __restrict__ kvw,
                                    const float* __restrict__ pw) {
    const int b = blockIdx.x;
    const float* W = (b == 0) ? qw : (b == 1) ? kvw : (b == 2) ? (kvw + 16384) : pw;
    uint32_t* out = g_Wpk + b * 16384;
    for (int idx = threadIdx.x; idx < 16384; idx += blockDim.x) {
        int reg = idx & 3, lane = (idx >> 2) & 31, ks2 = (idx >> 7) & 7, ntile = idx >> 10;
        int n = ntile * 8 + (lane >> 2);
        int k = ks2 * 16 + reg * 4 + (lane & 3);
        out[idx] = f2tf32(W[n * 128 + k]);
    }
}

// ---------------------------------------------------------------------------
// TF32 tensor-core GEMM. Mainloop now loads B ONCE per (nt,ks2), shared
// across both mt (cuts mainloop LDS by 1/3 vs R11). unroll 1 retained.
// ---------------------------------------------------------------------------
__device__ __forceinline__ void mma_tf32(float& c0, float& c1, float& c2, float& c3,
                                         uint32_t a0, uint32_t a1, uint32_t a2, uint32_t a3,
                                         uint32_t b0, uint32_t b1) {
    asm volatile(
        "mma.sync.aligned.m16n8k8.row.col.f32.tf32.tf32.f32 "
        "{%0,%1,%2,%3}, {%4,%5,%6,%7}, {%8,%9}, {%0,%1,%2,%3};"
        : "+f"(c0), "+f"(c1), "+f"(c2), "+f"(c3)
        : "r"(a0), "r"(a1), "r"(a2), "r"(a3), "r"(b0), "r"(b1));
}
__device__ __forceinline__ void mma_tf32f(float& c0, float& c1, float& c2, float& c3,
                                          float a0, float a1, float a2, float a3,
                                          float b0, float b1) {
    mma_tf32(c0, c1, c2, c3,
             __float_as_uint(a0), __float_as_uint(a1),
             __float_as_uint(a2), __float_as_uint(a3),
             __float_as_uint(b0), __float_as_uint(b1));
}

#define A_PITCH 132

__global__ __launch_bounds__(256)
void gemm_tf32(const float* __restrict__ Ain,
               const float* __restrict__ biasA, const float* __restrict__ biasB,
               float* __restrict__ Cext, int mode, int wsel) {
    extern __shared__ uint32_t smu[];
    uint32_t* As = smu;              // 8448 words
    uint32_t* Ws = smu + 8448;       // 16384 words

    const uint32_t* Wpk = g_Wpk + (size_t)wsel * 16384;
    const float* A = (mode == 3) ? (const float*)g_ATT : Ain;
    float* C; int ldc, halves;
    if (mode == 0)      { C = g_Q;  ldc = 128; halves = 1; }
    else if (mode == 1) { C = g_KV; ldc = 256; halves = 2; }
    else                { C = Cext; ldc = 128; halves = 1; }

    const int tid = threadIdx.x;
    const int m0 = blockIdx.x * 64;

    {
        const float4* A4 = reinterpret_cast<const float4*>(A + (size_t)m0 * 128);
#pragma unroll
        for (int t = 0; t < 8; ++t) {
            int idx = tid + t * 256;
            int r = idx >> 5, c4 = idx & 31;
            float4 v = A4[idx];
            int mtile = r >> 4, g = r & 7, mh = (r >> 3) & 1;
            int slot = mtile * 16 + (c4 >> 1);
            int regb = (c4 & 1) * 2 + mh;
            uint32_t* base = As + slot * A_PITCH + g * 16 + regb;
            base[0]  = f2tf32(v.x);
            base[4]  = f2tf32(v.y);
            base[8]  = f2tf32(v.z);
            base[12] = f2tf32(v.w);
        }
    }

    const int lane = tid & 31, wid = tid >> 5;
    const int wm = wid >> 2;
    const int wn = wid & 3;
    const int g  = lane >> 2;
    const int tg = lane & 3;
    const uint32_t* Abase = As + lane * 4;
    const uint32_t* Bbase = Ws + lane * 4;

    for (int half = 0; half < halves; ++half) {
        if (half > 0) __syncthreads();
        {
            const float4* W4 = reinterpret_cast<const float4*>(Wpk + half * 16384);
            float4* Ws4 = reinterpret_cast<float4*>(Ws);
#pragma unroll
            for (int t = 0; t < 16; ++t) Ws4[tid + t * 256] = W4[tid + t * 256];
        }
        __syncthreads();

        float acc[2][4][4];
#pragma unroll
        for (int mt = 0; mt < 2; ++mt)
#pragma unroll
            for (int nt = 0; nt < 4; ++nt)
#pragma unroll
                for (int r = 0; r < 4; ++r) acc[mt][nt][r] = 0.f;

#pragma unroll 1
        for (int ks2 = 0; ks2 < 8; ++ks2) {
            const int sA0 = (wm * 2 + 0) * 16 + ks2 * 2;
            const int sA1 = (wm * 2 + 1) * 16 + ks2 * 2;
            uint4 a0L = *reinterpret_cast<const uint4*>(Abase + sA0 * A_PITCH);
            uint4 a0H = *reinterpret_cast<const uint4*>(Abase + (sA0 + 1) * A_PITCH);
            uint4 a1L = *reinterpret_cast<const uint4*>(Abase + sA1 * A_PITCH);
            uint4 a1H = *reinterpret_cast<const uint4*>(Abase + (sA1 + 1) * A_PITCH);
#pragma unroll
            for (int nt = 0; nt < 4; ++nt) {
                uint4 b = *reinterpret_cast<const uint4*>(
                    Bbase + ((wn * 4 + nt) * 8 + ks2) * 128);
                mma_tf32(acc[0][nt][0], acc[0][nt][1], acc[0][nt][2], acc[0][nt][3],
                         a0L.x, a0L.y, a0L.z, a0L.w, b.x, b.y);
                mma_tf32(acc[0][nt][0], acc[0][nt][1], acc[0][nt][2], acc[0][nt][3],
                         a0H.x, a0H.y, a0H.z, a0H.w, b.z, b.w);
                mma_tf32(acc[1][nt][0], acc[1][nt][1], acc[1][nt][2], acc[1][nt][3],
                         a1L.x, a1L.y, a1L.z, a1L.w, b.x, b.y);
                mma_tf32(acc[1][nt][0], acc[1][nt][1], acc[1][nt][2], acc[1][nt][3],
                         a1H.x, a1H.y, a1H.z, a1H.w, b.z, b.w);
            }
        }

        const float* bias = (half == 0) ? biasA : biasB;
        float* Ch = C + ((mode == 1) ? half * 128 : 0);
#pragma unroll
        for (int mt = 0; mt < 2; ++mt) {
            const int r0 = m0 + wm * 32 + mt * 16 + g;
#pragma unroll
            for (int nt = 0; nt < 4; ++nt) {
                const int col = wn * 32 + nt * 8 + 2 * tg;
                float bb0 = bias ? __ldg(bias + col)     : 0.f;
                float bb1 = bias ? __ldg(bias + col + 1) : 0.f;
                float2 o0 = make_float2(acc[mt][nt][0] + bb0, acc[mt][nt][1] + bb1);
                float2 o1 = make_float2(acc[mt][nt][2] + bb0, acc[mt][nt][3] + bb1);
                *reinterpret_cast<float2*>(&Ch[(size_t)r0 * ldc + col])       = o0;
                *reinterpret_cast<float2*>(&Ch[(size_t)(r0 + 8) * ldc + col]) = o1;
            }
        }
    }
}

// ---------------------------------------------------------------------------
// K2: TENSORIZED cosine attention, v2.
//   q,k stored in smem as NORMALIZED fp32 (hi/lo tf32 split happens on the
//   fly in the mainloop — bit-identical math to R11, half the LDS, and
//   smem drops 188 KB -> 112 KB  =>  2 CTAs/SM.
//   Smem (words): qn[4][64][36]=9216 | kn=9216 | vn[4][64][40]=10240
//                 P (pitch 68, 4*4352=17408 w) overlays qn+kn after QK.
//   Total 28672 words = 114,688 B.
// ---------------------------------------------------------------------------
__global__ __launch_bounds__(256, 2)
void attn_mma_kernel(const float* __restrict__ ls, const float* __restrict__ mask) {
    extern __shared__ float smf[];
    float* qn = smf;                // 9216
    float* kn = smf + 9216;         // 9216
    float* vn = smf + 18432;        // 10240

    const int win = blockIdx.x, tid = threadIdx.x;

    // ---------- staging: thread = (sh = tid>>6, sr = tid&63) ----------
    {
        const int sh = tid >> 6, sr = tid & 63;
        float buf[32];
        // Q: normalize + fold clamped scale; store fp32 rotated (pitch 36)
        {
            const float4* p = reinterpret_cast<const float4*>(
                g_Q + (size_t)win * 8192 + sr * 128 + sh * 32);
#pragma unroll
            for (int t = 0; t < 8; ++t) {
                float4 x = p[t];
                buf[4*t] = x.x; buf[4*t+1] = x.y; buf[4*t+2] = x.z; buf[4*t+3] = x.w;
            }
            float ssum = 0.f;
#pragma unroll
            for (int d = 0; d < 32; ++d) ssum = fmaf(buf[d], buf[d], ssum);
            float sc = __expf(fminf(ls[sh], 4.6051702f));
            float qs = sc / fmaxf(sqrtf(ssum), 1e-12f);
            float* dq = qn + (sh * 64 + sr) * 36;
#pragma unroll
            for (int d = 0; d < 32; ++d) dq[(d + sr) & 31] = buf[d] * qs;
        }
        // K: normalize; store fp32 rotated
        {
            const float4* p = reinterpret_cast<const float4*>(
                g_KV + (size_t)win * 16384 + sr * 256 + sh * 32);
#pragma unroll
            for (int t = 0; t < 8; ++t) {
                float4 x = p[t];
                buf[4*t] = x.x; buf[4*t+1] = x.y; buf[4*t+2] = x.z; buf[4*t+3] = x.w;
            }
            float ssum = 0.f;
#pragma unroll
            for (int d = 0; d < 32; ++d) ssum = fmaf(buf[d], buf[d], ssum);
            float kqs = 1.f / fmaxf(sqrtf(ssum), 1e-12f);
            float* dk = kn + (sh * 64 + sr) * 36;
#pragma unroll
            for (int d = 0; d < 32; ++d) dk[(d + sr) & 31] = buf[d] * kqs;
        }
        // V: tf32, rotated (pitch 40)
        {
            const float4* p = reinterpret_cast<const float4*>(
                g_KV + (size_t)win * 16384 + sr * 256 + 128 + sh * 32);
#pragma unroll
            for (int t = 0; t < 8; ++t) {
                float4 x = p[t];
                buf[4*t] = x.x; buf[4*t+1] = x.y; buf[4*t+2] = x.z; buf[4*t+3] = x.w;
            }
            float* dv = vn + (sh * 64 + sr) * 40;
#pragma unroll
            for (int d = 0; d < 32; ++d) dv[(d + sr) & 31] = tf32f(buf[d]);
        }
    }
    __syncthreads();

    // ---------- per-warp mma work ----------
    const int w = tid >> 5, lane = tid & 31;
    const int h = w >> 1, mh = w & 1;
    const int g = lane >> 2, tg = lane & 3;

    const float* Qb = qn + h * 2304;
    const float* Kb = kn + h * 2304;

    float acc[2][8][4];
#pragma unroll
    for (int mt = 0; mt < 2; ++mt)
#pragma unroll
        for (int nt = 0; nt < 8; ++nt)
#pragma unroll
            for (int r = 0; r < 4; ++r) acc[mt][nt][r] = 0.f;

    // ---- QK^T: tf32x3 with on-the-fly hi/lo split ----
#pragma unroll 1
    for (int ks = 0; ks < 4; ++ks) {
        const int c0 = ks * 8 + tg, c1 = c0 + 4;
        float qh[2][4], ql[2][4];
#pragma unroll
        for (int mt = 0; mt < 2; ++mt) {
            int ra = mh * 32 + mt * 16 + g, rb = ra + 8;
            float v0 = Qb[ra * 36 + ((c0 + ra) & 31)];
            float v1 = Qb[rb * 36 + ((c0 + rb) & 31)];
            float v2 = Qb[ra * 36 + ((c1 + ra) & 31)];
            float v3 = Qb[rb * 36 + ((c1 + rb) & 31)];
            qh[mt][0] = tf32f(v0); ql[mt][0] = tf32f(v0 - qh[mt][0]);
            qh[mt][1] = tf32f(v1); ql[mt][1] = tf32f(v1 - qh[mt][1]);
            qh[mt][2] = tf32f(v2); ql[mt][2] = tf32f(v2 - qh[mt][2]);
            qh[mt][3] = tf32f(v3); ql[mt][3] = tf32f(v3 - qh[mt][3]);
        }
#pragma unroll
        for (int nt = 0; nt < 8; ++nt) {
            int j = nt * 8 + g;
            float k0 = Kb[j * 36 + ((c0 + j) & 31)];
            float k1 = Kb[j * 36 + ((c1 + j) & 31)];
            float bh0 = tf32f(k0), bl0 = tf32f(k0 - bh0);
            float bh1 = tf32f(k1), bl1 = tf32f(k1 - bh1);
#pragma unroll
            for (int mt = 0; mt < 2; ++mt) {
                mma_tf32f(acc[mt][nt][0], acc[mt][nt][1], acc[mt][nt][2], acc[mt][nt][3],
                          qh[mt][0], qh[mt][1], qh[mt][2], qh[mt][3], bh0, bh1);
                mma_tf32f(acc[mt][nt][0], acc[mt][nt][1], acc[mt][nt][2], acc[mt][nt][3],
                          qh[mt][0], qh[mt][1], qh[mt][2], qh[mt][3], bl0, bl1);
                mma_tf32f(acc[mt][nt][0], acc[mt][nt][1], acc[mt][nt][2], acc[mt][nt][3],
                          ql[mt][0], ql[mt][1], ql[mt][2], ql[mt][3], bh0, bh1);
            }
        }
    }

    // ---- bias + mask (direct layouts, float2 loads) ----
    {
        const float* bias = g_biasD + h * 4096;
        const float* msk  = mask + (size_t)(win & (NMASK - 1)) * 4096;
#pragma unroll
        for (int mt = 0; mt < 2; ++mt) {
            int ra = mh * 32 + mt * 16 + g, rb = ra + 8;
#pragma unroll
            for (int nt = 0; nt < 8; ++nt) {
                int col = nt * 8 + 2 * tg;
                float2 ba = *reinterpret_cast<const float2*>(bias + ra * 64 + col);
                float2 ma = *reinterpret_cast<const float2*>(msk  + ra * 64 + col);
                float2 bb = *reinterpret_cast<const float2*>(bias + rb * 64 + col);
                float2 mb = *reinterpret_cast<const float2*>(msk  + rb * 64 + col);
                acc[mt][nt][0] += ba.x + ma.x;
                acc[mt][nt][1] += ba.y + ma.y;
                acc[mt][nt][2] += bb.x + mb.x;
                acc[mt][nt][3] += bb.y + mb.y;
            }
        }
    }

    // ---- softmax over j (quad shuffles) ----
#pragma unroll
    for (int mt = 0; mt < 2; ++mt) {
#pragma unroll
        for (int hf = 0; hf < 2; ++hf) {
            float m = -1e30f;
#pragma unroll
            for (int nt = 0; nt < 8; ++nt)
                m = fmaxf(m, fmaxf(acc[mt][nt][hf * 2], acc[mt][nt][hf * 2 + 1]));
            m = fmaxf(m, __shfl_xor_sync(0xffffffffu, m, 1));
            m = fmaxf(m, __shfl_xor_sync(0xffffffffu, m, 2));
            float s = 0.f;
#pragma unroll
            for (int nt = 0; nt < 8; ++nt) {
                float e0 = __expf(acc[mt][nt][hf * 2]     - m);
                float e1 = __expf(acc[mt][nt][hf * 2 + 1] - m);
                acc[mt][nt][hf * 2]     = e0;
                acc[mt][nt][hf * 2 + 1] = e1;
                s += e0 + e1;
            }
            s += __shfl_xor_sync(0xffffffffu, s, 1);
            s += __shfl_xor_sync(0xffffffffu, s, 2);
            float inv = 1.f / s;
#pragma unroll
            for (int nt = 0; nt < 8; ++nt) {
                acc[mt][nt][hf * 2]     *= inv;
                acc[mt][nt][hf * 2 + 1] *= inv;
            }
        }
    }

    __syncthreads();   // all warps done reading qn/kn before P overlays them

    // ---- store P (tf32, pitch 68) overlaying qn+kn ----
    float* P = smf + h * 4352;
#pragma unroll
    for (int mt = 0; mt < 2; ++mt) {
        int ra = mh * 32 + mt * 16 + g, rb = ra + 8;
#pragma unroll
        for (int nt = 0; nt < 8; ++nt) {
            int col = nt * 8 + 2 * tg;
            float2 p0 = make_float2(tf32f(acc[mt][nt][0]), tf32f(acc[mt][nt][1]));
            float2 p1 = make_float2(tf32f(acc[mt][nt][2]), tf32f(acc[mt][nt][3]));
            *reinterpret_cast<float2*>(P + ra * 68 + col) = p0;
            *reinterpret_cast<float2*>(P + rb * 68 + col) = p1;
        }
    }
    __syncwarp();

    // ---- PV: m32(warp) x n32 x k64 ----
    const float* Vh = vn + h * 2560;
    float o[2][4][4];
#pragma unroll
    for (int mt = 0; mt < 2; ++mt)
#pragma unroll
        for (int nt = 0; nt < 4; ++nt)
#pragma unroll
            for (int r = 0; r < 4; ++r) o[mt][nt][r] = 0.f;

#pragma unroll 1
    for (int ks = 0; ks < 8; ++ks) {
        const int j0 = ks * 8 + tg, j1 = j0 + 4;
        float pa[2][4];
#pragma unroll
        for (int mt = 0; mt < 2; ++mt) {
            int ra = mh * 32 + mt * 16 + g, rb = ra + 8;
            pa[mt][0] = P[ra * 68 + j0];
            pa[mt][1] = P[rb * 68 + j0];
            pa[mt][2] = P[ra * 68 + j1];
            pa[mt][3] = P[rb * 68 + j1];
        }
#pragma unroll
        for (int nt = 0; nt < 4; ++nt) {
            int d = nt * 8 + g;
            float vb0 = Vh[j0 * 40 + ((d + j0) & 31)];
            float vb1 = Vh[j1 * 40 + ((d + j1) & 31)];
#pragma unroll
            for (int mt = 0; mt < 2; ++mt)
                mma_tf32f(o[mt][nt][0], o[mt][nt][1], o[mt][nt][2], o[mt][nt][3],
                          pa[mt][0], pa[mt][1], pa[mt][2], pa[mt][3], vb0, vb1);
        }
    }

    // ---- write O to g_ATT ----
    {
        float* Ow = g_ATT + (size_t)win * 8192 + h * 32;
#pragma unroll
        for (int mt = 0; mt < 2; ++mt) {
            int ra = mh * 32 + mt * 16 + g, rb = ra + 8;
#pragma unroll
            for (int nt = 0; nt < 4; ++nt) {
                int d = nt * 8 + 2 * tg;
                *reinterpret_cast<float2*>(Ow + ra * 128 + d) =
                    make_float2(o[mt][nt][0], o[mt][nt][1]);
                *reinterpret_cast<float2*>(Ow + rb * 128 + d) =
                    make_float2(o[mt][nt][2], o[mt][nt][3]);
            }
        }
    }
}

// ---------------------------------------------------------------------------
// Launch — only harness-provided pointers cross the host/device boundary.
// ---------------------------------------------------------------------------
extern "C" void kernel_launch(void* const* d_in, const int* in_sizes, int n_in,
                              void* d_out, int out_size) {
    const float* x    = (const float*)d_in[0];
    const float* ctx  = (const float*)d_in[1];
    const float* mask = (const float*)d_in[2];
    const float* q_w  = (const float*)d_in[3];
    const float* q_b  = (const float*)d_in[4];
    const float* kv_w = (const float*)d_in[5];
    const float* v_b  = (const float*)d_in[6];
    const float* ls   = (const float*)d_in[7];
    const float* w1   = (const float*)d_in[8];
    const float* b1   = (const float*)d_in[9];
    const float* w2   = (const float*)d_in[10];
    const float* pw   = (const float*)d_in[11];
    const float* pb   = (const float*)d_in[12];
    const float* tbl  = (const float*)d_in[13];
    const int*   rpi  = (const int*)d_in[14];
    float* out = (float*)d_out;

    const int GEMM_SMEM = (8448 + 16384) * 4;   // 99,328 B
    const int ATTN_SMEM = 28672 * 4;            // 114,688 B -> 2 CTAs/SM

    cudaFuncSetAttribute(gemm_tf32, cudaFuncAttributeMaxDynamicSharedMemorySize, GEMM_SMEM);
    cudaFuncSetAttribute(attn_mma_kernel, cudaFuncAttributeMaxDynamicSharedMemorySize, ATTN_SMEM);

    // Prep (tiny)
    cpb_bias_kernel<<<1, 256>>>(tbl, w1, b1, w2, rpi);
    pack_weights_kernel<<<4, 256>>>(q_w, kv_w, pw);

    const int MTILES = NWIN * NTOK / 64;   // 4096

    // Q = x @ q_w^T + q_b
    gemm_tf32<<<MTILES, 256, GEMM_SMEM>>>(x, q_b, nullptr, nullptr, 0, 0);
    // K|V = ctx @ kv_w^T (+ [0;v_b]) — single pass, two packed halves
    gemm_tf32<<<MTILES, 256, GEMM_SMEM>>>(ctx, nullptr, v_b, nullptr, 1, 1);

    // Tensorized fused cosine attention (2 CTAs/SM)
    attn_mma_kernel<<<NWIN, 256, ATTN_SMEM>>>(ls, mask);

    // out = att @ proj_w^T + proj_b
    gemm_tf32<<<MTILES, 256, GEMM_SMEM>>>(x, pb, nullptr, out, 3, 3);
}

// round 14
// speedup vs baseline: 2.7377x; 1.0305x over previous
#include <cuda_runtime.h>
#include <math.h>
#include <stdint.h>

// Problem constants
#define NWIN 4096
#define NTOK 64
#define DIM  128
#define NH   4
#define HD   32
#define NMASK 64

// ---------------------------------------------------------------------------
// Scratch (allocation-free: __device__ globals; NEVER referenced from host)
// ---------------------------------------------------------------------------
__device__ float    g_Q  [NWIN * NTOK * DIM];        // 134 MB
__device__ float    g_KV [NWIN * NTOK * 2 * DIM];    // 268 MB (k: 0-127, v: 128-255)
__device__ float    g_biasD[NH * NTOK * NTOK];       // [h][i][j]  (direct layout)
__device__ uint32_t g_Wpk[4 * 16384];                // packed tf32 weights
                                                     // 0=q_w, 1=kv_w(K), 2=kv_w(V), 3=proj_w

__device__ __forceinline__ uint32_t f2tf32(float f) {
    uint32_t u;
    asm("cvt.rna.tf32.f32 %0, %1;" : "=r"(u) : "f"(f));
    return u;
}
__device__ __forceinline__ float tf32f(float f) {
    return __uint_as_float(f2tf32(f));
}

// ---------------------------------------------------------------------------
// K0b: CPB-MLP relative position bias, gathered, DIRECT layout [h][i][j]
// ---------------------------------------------------------------------------
__global__ void cpb_bias_kernel(const float* __restrict__ table,
                                const float* __restrict__ w1,
                                const float* __restrict__ b1,
                                const float* __restrict__ w2,
                                const int*   __restrict__ rpi) {
    __shared__ float tbl[225][4];
    const int tid = threadIdx.x;
    if (tid < 225) {
        float c0 = table[tid * 2 + 0];
        float c1 = table[tid * 2 + 1];
        float o0 = 0.f, o1 = 0.f, o2 = 0.f, o3 = 0.f;
        for (int m = 0; m < 512; ++m) {
            float hv = fmaf(c0, w1[m * 2], fmaf(c1, w1[m * 2 + 1], b1[m]));
            hv = fmaxf(hv, 0.f);
            o0 = fmaf(hv, w2[0 * 512 + m], o0);
            o1 = fmaf(hv, w2[1 * 512 + m], o1);
            o2 = fmaf(hv, w2[2 * 512 + m], o2);
            o3 = fmaf(hv, w2[3 * 512 + m], o3);
        }
        tbl[tid][0] = o0; tbl[tid][1] = o1; tbl[tid][2] = o2; tbl[tid][3] = o3;
    }
    __syncthreads();
    for (int e = tid; e < NTOK * NTOK; e += blockDim.x) {
        int id = rpi[e];
#pragma unroll
        for (int hh = 0; hh < NH; ++hh) {
            float v = tbl[id][hh];
            g_biasD[hh * 4096 + e] = 16.f / (1.f + __expf(-v));
        }
    }
}

// ---------------------------------------------------------------------------
// K0c: pack weights -> tf32 mma-fragment order.
// ---------------------------------------------------------------------------
__global__ void pack_weights_kernel(const float* __restrict__ qw,
                                    const float* __restrict__ kvw,
                                    const float* __restrict__ pw) {
    const int b = blockIdx.x;
    const float* W = (b == 0) ? qw : (b == 1) ? kvw : (b == 2) ? (kvw + 16384) : pw;
    uint32_t* out = g_Wpk + b * 16384;
    for (int idx = threadIdx.x; idx < 16384; idx += blockDim.x) {
        int reg = idx & 3, lane = (idx >> 2) & 31, ks2 = (idx >> 7) & 7, ntile = idx >> 10;
        int n = ntile * 8 + (lane >> 2);
        int k = ks2 * 16 + reg * 4 + (lane & 3);
        out[idx] = f2tf32(W[n * 128 + k]);
    }
}

// ---------------------------------------------------------------------------
// TF32 tensor-core GEMM (R12 version, unchanged).
// ---------------------------------------------------------------------------
__device__ __forceinline__ void mma_tf32(float& c0, float& c1, float& c2, float& c3,
                                         uint32_t a0, uint32_t a1, uint32_t a2, uint32_t a3,
                                         uint32_t b0, uint32_t b1) {
    asm volatile(
        "mma.sync.aligned.m16n8k8.row.col.f32.tf32.tf32.f32 "
        "{%0,%1,%2,%3}, {%4,%5,%6,%7}, {%8,%9}, {%0,%1,%2,%3};"
        : "+f"(c0), "+f"(c1), "+f"(c2), "+f"(c3)
        : "r"(a0), "r"(a1), "r"(a2), "r"(a3), "r"(b0), "r"(b1));
}
__device__ __forceinline__ void mma_tf32f(float& c0, float& c1, float& c2, float& c3,
                                          float a0, float a1, float a2, float a3,
                                          float b0, float b1) {
    mma_tf32(c0, c1, c2, c3,
             __float_as_uint(a0), __float_as_uint(a1),
             __float_as_uint(a2), __float_as_uint(a3),
             __float_as_uint(b0), __float_as_uint(b1));
}

#define A_PITCH 132

__global__ __launch_bounds__(256)
void gemm_tf32(const float* __restrict__ Ain,
               const float* __restrict__ biasA, const float* __restrict__ biasB,
               int mode, int wsel) {
    extern __shared__ uint32_t smu[];
    uint32_t* As = smu;              // 8448 words
    uint32_t* Ws = smu + 8448;       // 16384 words

    const uint32_t* Wpk = g_Wpk + (size_t)wsel * 16384;
    const float* A = Ain;
    float* C; int ldc, halves;
    if (mode == 0)      { C = g_Q;  ldc = 128; halves = 1; }
    else                { C = g_KV; ldc = 256; halves = 2; }

    const int tid = threadIdx.x;
    const int m0 = blockIdx.x * 64;

    {
        const float4* A4 = reinterpret_cast<const float4*>(A + (size_t)m0 * 128);
#pragma unroll
        for (int t = 0; t < 8; ++t) {
            int idx = tid + t * 256;
            int r = idx >> 5, c4 = idx & 31;
            float4 v = A4[idx];
            int mtile = r >> 4, g = r & 7, mh = (r >> 3) & 1;
            int slot = mtile * 16 + (c4 >> 1);
            int regb = (c4 & 1) * 2 + mh;
            uint32_t* base = As + slot * A_PITCH + g * 16 + regb;
            base[0]  = f2tf32(v.x);
            base[4]  = f2tf32(v.y);
            base[8]  = f2tf32(v.z);
            base[12] = f2tf32(v.w);
        }
    }

    const int lane = tid & 31, wid = tid >> 5;
    const int wm = wid >> 2;
    const int wn = wid & 3;
    const int g  = lane >> 2;
    const int tg = lane & 3;
    const uint32_t* Abase = As + lane * 4;
    const uint32_t* Bbase = Ws + lane * 4;

    for (int half = 0; half < halves; ++half) {
        if (half > 0) __syncthreads();
        {
            const float4* W4 = reinterpret_cast<const float4*>(Wpk + half * 16384);
            float4* Ws4 = reinterpret_cast<float4*>(Ws);
#pragma unroll
            for (int t = 0; t < 16; ++t) Ws4[tid + t * 256] = W4[tid + t * 256];
        }
        __syncthreads();

        float acc[2][4][4];
#pragma unroll
        for (int mt = 0; mt < 2; ++mt)
#pragma unroll
            for (int nt = 0; nt < 4; ++nt)
#pragma unroll
                for (int r = 0; r < 4; ++r) acc[mt][nt][r] = 0.f;

#pragma unroll 1
        for (int ks2 = 0; ks2 < 8; ++ks2) {
            const int sA0 = (wm * 2 + 0) * 16 + ks2 * 2;
            const int sA1 = (wm * 2 + 1) * 16 + ks2 * 2;
            uint4 a0L = *reinterpret_cast<const uint4*>(Abase + sA0 * A_PITCH);
            uint4 a0H = *reinterpret_cast<const uint4*>(Abase + (sA0 + 1) * A_PITCH);
            uint4 a1L = *reinterpret_cast<const uint4*>(Abase + sA1 * A_PITCH);
            uint4 a1H = *reinterpret_cast<const uint4*>(Abase + (sA1 + 1) * A_PITCH);
#pragma unroll
            for (int nt = 0; nt < 4; ++nt) {
                uint4 b = *reinterpret_cast<const uint4*>(
                    Bbase + ((wn * 4 + nt) * 8 + ks2) * 128);
                mma_tf32(acc[0][nt][0], acc[0][nt][1], acc[0][nt][2], acc[0][nt][3],
                         a0L.x, a0L.y, a0L.z, a0L.w, b.x, b.y);
                mma_tf32(acc[0][nt][0], acc[0][nt][1], acc[0][nt][2], acc[0][nt][3],
                         a0H.x, a0H.y, a0H.z, a0H.w, b.z, b.w);
                mma_tf32(acc[1][nt][0], acc[1][nt][1], acc[1][nt][2], acc[1][nt][3],
                         a1L.x, a1L.y, a1L.z, a1L.w, b.x, b.y);
                mma_tf32(acc[1][nt][0], acc[1][nt][1], acc[1][nt][2], acc[1][nt][3],
                         a1H.x, a1H.y, a1H.z, a1H.w, b.z, b.w);
            }
        }

        const float* bias = (half == 0) ? biasA : biasB;
        float* Ch = C + ((mode == 1) ? half * 128 : 0);
#pragma unroll
        for (int mt = 0; mt < 2; ++mt) {
            const int r0 = m0 + wm * 32 + mt * 16 + g;
#pragma unroll
            for (int nt = 0; nt < 4; ++nt) {
                const int col = wn * 32 + nt * 8 + 2 * tg;
                float bb0 = bias ? __ldg(bias + col)     : 0.f;
                float bb1 = bias ? __ldg(bias + col + 1) : 0.f;
                float2 o0 = make_float2(acc[mt][nt][0] + bb0, acc[mt][nt][1] + bb1);
                float2 o1 = make_float2(acc[mt][nt][2] + bb0, acc[mt][nt][3] + bb1);
                *reinterpret_cast<float2*>(&Ch[(size_t)r0 * ldc + col])       = o0;
                *reinterpret_cast<float2*>(&Ch[(size_t)(r0 + 8) * ldc + col]) = o1;
            }
        }
    }
}

// ---------------------------------------------------------------------------
// K2: TENSORIZED cosine attention + FUSED OUTPUT PROJECTION.
//   v3: after PV, O is stored from mma registers into the gemm fragment-
//   packed tf32 layout (overlaying dead P region), then each warp runs a
//   32x32 proj tile: A via LDS.128, B via LDG.128 from packed proj weights
//   (L2-resident), + pb, writes d_out. g_ATT and the 4th gemm are GONE.
//   Smem: qn 9216 | kn 9216 | vn 10240 = 28672 w (114,688 B) -> 2 CTAs/SM.
//   P (pitch 68) overlays qn+kn after QK; O-pack (8448 w) overlays P after PV.
// ---------------------------------------------------------------------------
__global__ __launch_bounds__(256, 2)
void attn_mma_kernel(const float* __restrict__ ls, const float* __restrict__ mask,
                     const float* __restrict__ pb, float* __restrict__ out) {
    extern __shared__ float smf[];
    float* qn = smf;                // 9216
    float* kn = smf + 9216;         // 9216
    float* vn = smf + 18432;        // 10240

    const int win = blockIdx.x, tid = threadIdx.x;

    // ---------- staging: thread = (sh = tid>>6, sr = tid&63) ----------
    {
        const int sh = tid >> 6, sr = tid & 63;
        float buf[32];
        // Q: normalize + fold clamped scale; fp32 rotated (pitch 36)
        {
            const float4* p = reinterpret_cast<const float4*>(
                g_Q + (size_t)win * 8192 + sr * 128 + sh * 32);
#pragma unroll
            for (int t = 0; t < 8; ++t) {
                float4 x = p[t];
                buf[4*t] = x.x; buf[4*t+1] = x.y; buf[4*t+2] = x.z; buf[4*t+3] = x.w;
            }
            float ssum = 0.f;
#pragma unroll
            for (int d = 0; d < 32; ++d) ssum = fmaf(buf[d], buf[d], ssum);
            float sc = __expf(fminf(ls[sh], 4.6051702f));
            float qs = sc / fmaxf(sqrtf(ssum), 1e-12f);
            float* dq = qn + (sh * 64 + sr) * 36;
#pragma unroll
            for (int d = 0; d < 32; ++d) dq[(d + sr) & 31] = buf[d] * qs;
        }
        // K: normalize; fp32 rotated
        {
            const float4* p = reinterpret_cast<const float4*>(
                g_KV + (size_t)win * 16384 + sr * 256 + sh * 32);
#pragma unroll
            for (int t = 0; t < 8; ++t) {
                float4 x = p[t];
                buf[4*t] = x.x; buf[4*t+1] = x.y; buf[4*t+2] = x.z; buf[4*t+3] = x.w;
            }
            float ssum = 0.f;
#pragma unroll
            for (int d = 0; d < 32; ++d) ssum = fmaf(buf[d], buf[d], ssum);
            float kqs = 1.f / fmaxf(sqrtf(ssum), 1e-12f);
            float* dk = kn + (sh * 64 + sr) * 36;
#pragma unroll
            for (int d = 0; d < 32; ++d) dk[(d + sr) & 31] = buf[d] * kqs;
        }
        // V: tf32, rotated (pitch 40)
        {
            const float4* p = reinterpret_cast<const float4*>(
                g_KV + (size_t)win * 16384 + sr * 256 + 128 + sh * 32);
#pragma unroll
            for (int t = 0; t < 8; ++t) {
                float4 x = p[t];
                buf[4*t] = x.x; buf[4*t+1] = x.y; buf[4*t+2] = x.z; buf[4*t+3] = x.w;
            }
            float* dv = vn + (sh * 64 + sr) * 40;
#pragma unroll
            for (int d = 0; d < 32; ++d) dv[(d + sr) & 31] = tf32f(buf[d]);
        }
    }
    __syncthreads();

    // ---------- per-warp mma work ----------
    const int w = tid >> 5, lane = tid & 31;
    const int h = w >> 1, mh = w & 1;
    const int g = lane >> 2, tg = lane & 3;

    const float* Qb = qn + h * 2304;
    const float* Kb = kn + h * 2304;

    float acc[2][8][4];
#pragma unroll
    for (int mt = 0; mt < 2; ++mt)
#pragma unroll
        for (int nt = 0; nt < 8; ++nt)
#pragma unroll
            for (int r = 0; r < 4; ++r) acc[mt][nt][r] = 0.f;

    // ---- QK^T: tf32x3 with on-the-fly hi/lo split ----
#pragma unroll 1
    for (int ks = 0; ks < 4; ++ks) {
        const int c0 = ks * 8 + tg, c1 = c0 + 4;
        float qh[2][4], ql[2][4];
#pragma unroll
        for (int mt = 0; mt < 2; ++mt) {
            int ra = mh * 32 + mt * 16 + g, rb = ra + 8;
            float v0 = Qb[ra * 36 + ((c0 + ra) & 31)];
            float v1 = Qb[rb * 36 + ((c0 + rb) & 31)];
            float v2 = Qb[ra * 36 + ((c1 + ra) & 31)];
            float v3 = Qb[rb * 36 + ((c1 + rb) & 31)];
            qh[mt][0] = tf32f(v0); ql[mt][0] = tf32f(v0 - qh[mt][0]);
            qh[mt][1] = tf32f(v1); ql[mt][1] = tf32f(v1 - qh[mt][1]);
            qh[mt][2] = tf32f(v2); ql[mt][2] = tf32f(v2 - qh[mt][2]);
            qh[mt][3] = tf32f(v3); ql[mt][3] = tf32f(v3 - qh[mt][3]);
        }
#pragma unroll
        for (int nt = 0; nt < 8; ++nt) {
            int j = nt * 8 + g;
            float k0 = Kb[j * 36 + ((c0 + j) & 31)];
            float k1 = Kb[j * 36 + ((c1 + j) & 31)];
            float bh0 = tf32f(k0), bl0 = tf32f(k0 - bh0);
            float bh1 = tf32f(k1), bl1 = tf32f(k1 - bh1);
#pragma unroll
            for (int mt = 0; mt < 2; ++mt) {
                mma_tf32f(acc[mt][nt][0], acc[mt][nt][1], acc[mt][nt][2], acc[mt][nt][3],
                          qh[mt][0], qh[mt][1], qh[mt][2], qh[mt][3], bh0, bh1);
                mma_tf32f(acc[mt][nt][0], acc[mt][nt][1], acc[mt][nt][2], acc[mt][nt][3],
                          qh[mt][0], qh[mt][1], qh[mt][2], qh[mt][3], bl0, bl1);
                mma_tf32f(acc[mt][nt][0], acc[mt][nt][1], acc[mt][nt][2], acc[mt][nt][3],
                          ql[mt][0], ql[mt][1], ql[mt][2], ql[mt][3], bh0, bh1);
            }
        }
    }

    // ---- bias + mask ----
    {
        const float* bias = g_biasD + h * 4096;
        const float* msk  = mask + (size_t)(win & (NMASK - 1)) * 4096;
#pragma unroll
        for (int mt = 0; mt < 2; ++mt) {
            int ra = mh * 32 + mt * 16 + g, rb = ra + 8;
#pragma unroll
            for (int nt = 0; nt < 8; ++nt) {
                int col = nt * 8 + 2 * tg;
                float2 ba = *reinterpret_cast<const float2*>(bias + ra * 64 + col);
                float2 ma = *reinterpret_cast<const float2*>(msk  + ra * 64 + col);
                float2 bb = *reinterpret_cast<const float2*>(bias + rb * 64 + col);
                float2 mb = *reinterpret_cast<const float2*>(msk  + rb * 64 + col);
                acc[mt][nt][0] += ba.x + ma.x;
                acc[mt][nt][1] += ba.y + ma.y;
                acc[mt][nt][2] += bb.x + mb.x;
                acc[mt][nt][3] += bb.y + mb.y;
            }
        }
    }

    // ---- softmax over j (quad shuffles) ----
#pragma unroll
    for (int mt = 0; mt < 2; ++mt) {
#pragma unroll
        for (int hf = 0; hf < 2; ++hf) {
            float m = -1e30f;
#pragma unroll
            for (int nt = 0; nt < 8; ++nt)
                m = fmaxf(m, fmaxf(acc[mt][nt][hf * 2], acc[mt][nt][hf * 2 + 1]));
            m = fmaxf(m, __shfl_xor_sync(0xffffffffu, m, 1));
            m = fmaxf(m, __shfl_xor_sync(0xffffffffu, m, 2));
            float s = 0.f;
#pragma unroll
            for (int nt = 0; nt < 8; ++nt) {
                float e0 = __expf(acc[mt][nt][hf * 2]     - m);
                float e1 = __expf(acc[mt][nt][hf * 2 + 1] - m);
                acc[mt][nt][hf * 2]     = e0;
                acc[mt][nt][hf * 2 + 1] = e1;
                s += e0 + e1;
            }
            s += __shfl_xor_sync(0xffffffffu, s, 1);
            s += __shfl_xor_sync(0xffffffffu, s, 2);
            float inv = 1.f / s;
#pragma unroll
            for (int nt = 0; nt < 8; ++nt) {
                acc[mt][nt][hf * 2]     *= inv;
                acc[mt][nt][hf * 2 + 1] *= inv;
            }
        }
    }

    __syncthreads();   // all warps done reading qn/kn before P overlays them

    // ---- store P (tf32, pitch 68) overlaying qn+kn ----
    float* P = smf + h * 4352;
#pragma unroll
    for (int mt = 0; mt < 2; ++mt) {
        int ra = mh * 32 + mt * 16 + g, rb = ra + 8;
#pragma unroll
        for (int nt = 0; nt < 8; ++nt) {
            int col = nt * 8 + 2 * tg;
            float2 p0 = make_float2(tf32f(acc[mt][nt][0]), tf32f(acc[mt][nt][1]));
            float2 p1 = make_float2(tf32f(acc[mt][nt][2]), tf32f(acc[mt][nt][3]));
            *reinterpret_cast<float2*>(P + ra * 68 + col) = p0;
            *reinterpret_cast<float2*>(P + rb * 68 + col) = p1;
        }
    }
    __syncwarp();

    // ---- PV: m32(warp) x n32 x k64 ----
    const float* Vh = vn + h * 2560;
    float o[2][4][4];
#pragma unroll
    for (int mt = 0; mt < 2; ++mt)
#pragma unroll
        for (int nt = 0; nt < 4; ++nt)
#pragma unroll
            for (int r = 0; r < 4; ++r) o[mt][nt][r] = 0.f;

#pragma unroll 1
    for (int ks = 0; ks < 8; ++ks) {
        const int j0 = ks * 8 + tg, j1 = j0 + 4;
        float pa[2][4];
#pragma unroll
        for (int mt = 0; mt < 2; ++mt) {
            int ra = mh * 32 + mt * 16 + g, rb = ra + 8;
            pa[mt][0] = P[ra * 68 + j0];
            pa[mt][1] = P[rb * 68 + j0];
            pa[mt][2] = P[ra * 68 + j1];
            pa[mt][3] = P[rb * 68 + j1];
        }
#pragma unroll
        for (int nt = 0; nt < 4; ++nt) {
            int d = nt * 8 + g;
            float vb0 = Vh[j0 * 40 + ((d + j0) & 31)];
            float vb1 = Vh[j1 * 40 + ((d + j1) & 31)];
#pragma unroll
            for (int mt = 0; mt < 2; ++mt)
                mma_tf32f(o[mt][nt][0], o[mt][nt][1], o[mt][nt][2], o[mt][nt][3],
                          pa[mt][0], pa[mt][1], pa[mt][2], pa[mt][3], vb0, vb1);
        }
    }

    __syncthreads();   // all P/V reads done before O-pack overlays the region

    // ---- store O (tf32) in gemm fragment-packed layout at smf[0..8448) ----
    // addr(r,c) = ((r>>4)*16 + (c>>3))*132 + (r&7)*16 + ((c>>2)&1)*2
    //           + ((r>>3)&1) + (c&3)*4
    // From mma C-fragments: r = mh*32+mt*16+g(+8), c = h*32+nt*8+2tg(+1).
    {
        uint32_t* Ou = reinterpret_cast<uint32_t*>(smf);
#pragma unroll
        for (int mt = 0; mt < 2; ++mt) {
#pragma unroll
            for (int nt = 0; nt < 4; ++nt) {
                int S = (mh * 2 + mt) * 16 + h * 4 + nt;
                uint32_t* base = Ou + S * A_PITCH + g * 16 + (tg >> 1) * 2 + (tg & 1) * 8;
                base[0] = f2tf32(o[mt][nt][0]);   // row g,   col 2tg
                base[4] = f2tf32(o[mt][nt][1]);   // row g,   col 2tg+1
                base[1] = f2tf32(o[mt][nt][2]);   // row g+8, col 2tg
                base[5] = f2tf32(o[mt][nt][3]);   // row g+8, col 2tg+1
            }
        }
    }
    __syncthreads();

    // ---- fused projection: out(64x128) = O @ pw^T + pb ----
    // Warp grid: wm2 = w>>2 (2 row tiles of 32), wn2 = w&3 (4 col tiles of 32).
    {
        const int wm2 = w >> 2, wn2 = w & 3;
        const uint32_t* Ob = reinterpret_cast<const uint32_t*>(smf) + lane * 4;
        const uint32_t* Wp = g_Wpk + 3 * 16384 + lane * 4;

        float pr[2][4][4];
#pragma unroll
        for (int mt = 0; mt < 2; ++mt)
#pragma unroll
            for (int nt = 0; nt < 4; ++nt)
#pragma unroll
                for (int r = 0; r < 4; ++r) pr[mt][nt][r] = 0.f;

#pragma unroll 1
        for (int ks2 = 0; ks2 < 8; ++ks2) {
            const int sA0 = (wm2 * 2 + 0) * 16 + ks2 * 2;
            const int sA1 = (wm2 * 2 + 1) * 16 + ks2 * 2;
            uint4 a0L = *reinterpret_cast<const uint4*>(Ob + sA0 * A_PITCH);
            uint4 a0H = *reinterpret_cast<const uint4*>(Ob + (sA0 + 1) * A_PITCH);
            uint4 a1L = *reinterpret_cast<const uint4*>(Ob + sA1 * A_PITCH);
            uint4 a1H = *reinterpret_cast<const uint4*>(Ob + (sA1 + 1) * A_PITCH);
#pragma unroll
            for (int nt = 0; nt < 4; ++nt) {
                uint4 b = *reinterpret_cast<const uint4*>(
                    Wp + ((wn2 * 4 + nt) * 8 + ks2) * 128);
                mma_tf32(pr[0][nt][0], pr[0][nt][1], pr[0][nt][2], pr[0][nt][3],
                         a0L.x, a0L.y, a0L.z, a0L.w, b.x, b.y);
                mma_tf32(pr[0][nt][0], pr[0][nt][1], pr[0][nt][2], pr[0][nt][3],
                         a0H.x, a0H.y, a0H.z, a0H.w, b.z, b.w);
                mma_tf32(pr[1][nt][0], pr[1][nt][1], pr[1][nt][2], pr[1][nt][3],
                         a1L.x, a1L.y, a1L.z, a1L.w, b.x, b.y);
                mma_tf32(pr[1][nt][0], pr[1][nt][1], pr[1][nt][2], pr[1][nt][3],
                         a1H.x, a1H.y, a1H.z, a1H.w, b.z, b.w);
            }
        }

        float* Out = out + (size_t)win * 8192;
#pragma unroll
        for (int mt = 0; mt < 2; ++mt) {
            const int r0 = wm2 * 32 + mt * 16 + g;
#pragma unroll
            for (int nt = 0; nt < 4; ++nt) {
                const int col = wn2 * 32 + nt * 8 + 2 * tg;
                float bb0 = __ldg(pb + col);
                float bb1 = __ldg(pb + col + 1);
                *reinterpret_cast<float2*>(&Out[(size_t)r0 * 128 + col]) =
                    make_float2(pr[mt][nt][0] + bb0, pr[mt][nt][1] + bb1);
                *reinterpret_cast<float2*>(&Out[(size_t)(r0 + 8) * 128 + col]) =
                    make_float2(pr[mt][nt][2] + bb0, pr[mt][nt][3] + bb1);
            }
        }
    }
}

// ---------------------------------------------------------------------------
// Launch — only harness-provided pointers cross the host/device boundary.
// ---------------------------------------------------------------------------
extern "C" void kernel_launch(void* const* d_in, const int* in_sizes, int n_in,
                              void* d_out, int out_size) {
    const float* x    = (const float*)d_in[0];
    const float* ctx  = (const float*)d_in[1];
    const float* mask = (const float*)d_in[2];
    const float* q_w  = (const float*)d_in[3];
    const float* q_b  = (const float*)d_in[4];
    const float* kv_w = (const float*)d_in[5];
    const float* v_b  = (const float*)d_in[6];
    const float* ls   = (const float*)d_in[7];
    const float* w1   = (const float*)d_in[8];
    const float* b1   = (const float*)d_in[9];
    const float* w2   = (const float*)d_in[10];
    const float* pw   = (const float*)d_in[11];
    const float* pb   = (const float*)d_in[12];
    const float* tbl  = (const float*)d_in[13];
    const int*   rpi  = (const int*)d_in[14];
    float* out = (float*)d_out;

    const int GEMM_SMEM = (8448 + 16384) * 4;   // 99,328 B
    const int ATTN_SMEM = 28672 * 4;            // 114,688 B -> 2 CTAs/SM

    cudaFuncSetAttribute(gemm_tf32, cudaFuncAttributeMaxDynamicSharedMemorySize, GEMM_SMEM);
    cudaFuncSetAttribute(attn_mma_kernel, cudaFuncAttributeMaxDynamicSharedMemorySize, ATTN_SMEM);

    // Prep (tiny)
    cpb_bias_kernel<<<1, 256>>>(tbl, w1, b1, w2, rpi);
    pack_weights_kernel<<<4, 256>>>(q_w, kv_w, pw);

    const int MTILES = NWIN * NTOK / 64;   // 4096

    // Q = x @ q_w^T + q_b
    gemm_tf32<<<MTILES, 256, GEMM_SMEM>>>(x, q_b, nullptr, 0, 0);
    // K|V = ctx @ kv_w^T (+ [0;v_b]) — single pass, two packed halves
    gemm_tf32<<<MTILES, 256, GEMM_SMEM>>>(ctx, nullptr, v_b, 1, 1);

    // Tensorized fused cosine attention + output projection
    attn_mma_kernel<<<NWIN, 256, ATTN_SMEM>>>(ls, mask, pb, out);
}

// round 15
// speedup vs baseline: 2.8247x; 1.0318x over previous
#include <cuda_runtime.h>
#include <math.h>
#include <stdint.h>

// Problem constants
#define NWIN 4096
#define NTOK 64
#define DIM  128
#define NH   4
#define HD   32
#define NMASK 64

// ---------------------------------------------------------------------------
// Scratch (allocation-free: __device__ globals; NEVER referenced from host)
// ---------------------------------------------------------------------------
__device__ float    g_Q  [NWIN * NTOK * DIM];        // 134 MB
__device__ float    g_KV [NWIN * NTOK * 2 * DIM];    // 268 MB (k: 0-127, v: 128-255)
__device__ float    g_biasD[NH * NTOK * NTOK];       // [h][i][j]  (direct layout)
__device__ uint32_t g_Wpk[4 * 16384];                // packed tf32 weights
                                                     // 0=q_w, 1=kv_w(K), 2=kv_w(V), 3=proj_w

__device__ __forceinline__ uint32_t f2tf32(float f) {
    uint32_t u;
    asm("cvt.rna.tf32.f32 %0, %1;" : "=r"(u) : "f"(f));
    return u;
}
__device__ __forceinline__ float tf32f(float f) {
    return __uint_as_float(f2tf32(f));
}

// ---------------------------------------------------------------------------
// K0b: CPB-MLP relative position bias, gathered, DIRECT layout [h][i][j]
// ---------------------------------------------------------------------------
__global__ void cpb_bias_kernel(const float* __restrict__ table,
                                const float* __restrict__ w1,
                                const float* __restrict__ b1,
                                const float* __restrict__ w2,
                                const int*   __restrict__ rpi) {
    __shared__ float tbl[225][4];
    const int tid = threadIdx.x;
    if (tid < 225) {
        float c0 = table[tid * 2 + 0];
        float c1 = table[tid * 2 + 1];
        float o0 = 0.f, o1 = 0.f, o2 = 0.f, o3 = 0.f;
        for (int m = 0; m < 512; ++m) {
            float hv = fmaf(c0, w1[m * 2], fmaf(c1, w1[m * 2 + 1], b1[m]));
            hv = fmaxf(hv, 0.f);
            o0 = fmaf(hv, w2[0 * 512 + m], o0);
            o1 = fmaf(hv, w2[1 * 512 + m], o1);
            o2 = fmaf(hv, w2[2 * 512 + m], o2);
            o3 = fmaf(hv, w2[3 * 512 + m], o3);
        }
        tbl[tid][0] = o0; tbl[tid][1] = o1; tbl[tid][2] = o2; tbl[tid][3] = o3;
    }
    __syncthreads();
    for (int e = tid; e < NTOK * NTOK; e += blockDim.x) {
        int id = rpi[e];
#pragma unroll
        for (int hh = 0; hh < NH; ++hh) {
            float v = tbl[id][hh];
            g_biasD[hh * 4096 + e] = 16.f / (1.f + __expf(-v));
        }
    }
}

// ---------------------------------------------------------------------------
// K0c: pack weights -> tf32 mma-fragment order.
// ---------------------------------------------------------------------------
__global__ void pack_weights_kernel(const float* __restrict__ qw,
                                    const float* __restrict__ kvw,
                                    const float* __restrict__ pw) {
    const int b = blockIdx.x;
    const float* W = (b == 0) ? qw : (b == 1) ? kvw : (b == 2) ? (kvw + 16384) : pw;
    uint32_t* out = g_Wpk + b * 16384;
    for (int idx = threadIdx.x; idx < 16384; idx += blockDim.x) {
        int reg = idx & 3, lane = (idx >> 2) & 31, ks2 = (idx >> 7) & 7, ntile = idx >> 10;
        int n = ntile * 8 + (lane >> 2);
        int k = ks2 * 16 + reg * 4 + (lane & 3);
        out[idx] = f2tf32(W[n * 128 + k]);
    }
}

// ---------------------------------------------------------------------------
// TF32 tensor-core GEMM, v2: NO W smem staging. B fragments are read directly
// from packed weights via coalesced LDG.128 (L2-resident). Smem = A pack only
// (33 KB static) -> 4 CTAs/SM. No inter-half barrier needed.
// ---------------------------------------------------------------------------
__device__ __forceinline__ void mma_tf32(float& c0, float& c1, float& c2, float& c3,
                                         uint32_t a0, uint32_t a1, uint32_t a2, uint32_t a3,
                                         uint32_t b0, uint32_t b1) {
    asm volatile(
        "mma.sync.aligned.m16n8k8.row.col.f32.tf32.tf32.f32 "
        "{%0,%1,%2,%3}, {%4,%5,%6,%7}, {%8,%9}, {%0,%1,%2,%3};"
        : "+f"(c0), "+f"(c1), "+f"(c2), "+f"(c3)
        : "r"(a0), "r"(a1), "r"(a2), "r"(a3), "r"(b0), "r"(b1));
}
__device__ __forceinline__ void mma_tf32f(float& c0, float& c1, float& c2, float& c3,
                                          float a0, float a1, float a2, float a3,
                                          float b0, float b1) {
    mma_tf32(c0, c1, c2, c3,
             __float_as_uint(a0), __float_as_uint(a1),
             __float_as_uint(a2), __float_as_uint(a3),
             __float_as_uint(b0), __float_as_uint(b1));
}

#define A_PITCH 132

__global__ __launch_bounds__(256, 4)
void gemm_tf32(const float* __restrict__ Ain,
               const float* __restrict__ biasA, const float* __restrict__ biasB,
               int mode, int wsel) {
    __shared__ uint32_t As[8448];    // 33 KB (A fragment pack only)

    const float* A = Ain;
    float* C; int ldc, halves;
    if (mode == 0)      { C = g_Q;  ldc = 128; halves = 1; }
    else                { C = g_KV; ldc = 256; halves = 2; }

    const int tid = threadIdx.x;
    const int m0 = blockIdx.x * 64;

    // ---- stage A (64x128) -> fragment-packed tf32 smem ----
    {
        const float4* A4 = reinterpret_cast<const float4*>(A + (size_t)m0 * 128);
#pragma unroll
        for (int t = 0; t < 8; ++t) {
            int idx = tid + t * 256;
            int r = idx >> 5, c4 = idx & 31;
            float4 v = A4[idx];
            int mtile = r >> 4, g = r & 7, mh = (r >> 3) & 1;
            int slot = mtile * 16 + (c4 >> 1);
            int regb = (c4 & 1) * 2 + mh;
            uint32_t* base = As + slot * A_PITCH + g * 16 + regb;
            base[0]  = f2tf32(v.x);
            base[4]  = f2tf32(v.y);
            base[8]  = f2tf32(v.z);
            base[12] = f2tf32(v.w);
        }
    }
    __syncthreads();

    const int lane = tid & 31, wid = tid >> 5;
    const int wm = wid >> 2;
    const int wn = wid & 3;
    const int g  = lane >> 2;
    const int tg = lane & 3;
    const uint32_t* Abase = As + lane * 4;
    const uint32_t* Wg = g_Wpk + (size_t)wsel * 16384 + lane * 4;

#pragma unroll 1
    for (int half = 0; half < halves; ++half) {
        const uint32_t* Wh = Wg + half * 16384;

        float acc[2][4][4];
#pragma unroll
        for (int mt = 0; mt < 2; ++mt)
#pragma unroll
            for (int nt = 0; nt < 4; ++nt)
#pragma unroll
                for (int r = 0; r < 4; ++r) acc[mt][nt][r] = 0.f;

#pragma unroll 1
        for (int ks2 = 0; ks2 < 8; ++ks2) {
            const int sA0 = (wm * 2 + 0) * 16 + ks2 * 2;
            const int sA1 = (wm * 2 + 1) * 16 + ks2 * 2;
            uint4 a0L = *reinterpret_cast<const uint4*>(Abase + sA0 * A_PITCH);
            uint4 a0H = *reinterpret_cast<const uint4*>(Abase + (sA0 + 1) * A_PITCH);
            uint4 a1L = *reinterpret_cast<const uint4*>(Abase + sA1 * A_PITCH);
            uint4 a1H = *reinterpret_cast<const uint4*>(Abase + (sA1 + 1) * A_PITCH);
#pragma unroll
            for (int nt = 0; nt < 4; ++nt) {
                uint4 b = *reinterpret_cast<const uint4*>(
                    Wh + ((wn * 4 + nt) * 8 + ks2) * 128);
                mma_tf32(acc[0][nt][0], acc[0][nt][1], acc[0][nt][2], acc[0][nt][3],
                         a0L.x, a0L.y, a0L.z, a0L.w, b.x, b.y);
                mma_tf32(acc[0][nt][0], acc[0][nt][1], acc[0][nt][2], acc[0][nt][3],
                         a0H.x, a0H.y, a0H.z, a0H.w, b.z, b.w);
                mma_tf32(acc[1][nt][0], acc[1][nt][1], acc[1][nt][2], acc[1][nt][3],
                         a1L.x, a1L.y, a1L.z, a1L.w, b.x, b.y);
                mma_tf32(acc[1][nt][0], acc[1][nt][1], acc[1][nt][2], acc[1][nt][3],
                         a1H.x, a1H.y, a1H.z, a1H.w, b.z, b.w);
            }
        }

        const float* bias = (half == 0) ? biasA : biasB;
        float* Ch = C + ((mode == 1) ? half * 128 : 0);
#pragma unroll
        for (int mt = 0; mt < 2; ++mt) {
            const int r0 = m0 + wm * 32 + mt * 16 + g;
#pragma unroll
            for (int nt = 0; nt < 4; ++nt) {
                const int col = wn * 32 + nt * 8 + 2 * tg;
                float bb0 = bias ? __ldg(bias + col)     : 0.f;
                float bb1 = bias ? __ldg(bias + col + 1) : 0.f;
                float2 o0 = make_float2(acc[mt][nt][0] + bb0, acc[mt][nt][1] + bb1);
                float2 o1 = make_float2(acc[mt][nt][2] + bb0, acc[mt][nt][3] + bb1);
                *reinterpret_cast<float2*>(&Ch[(size_t)r0 * ldc + col])       = o0;
                *reinterpret_cast<float2*>(&Ch[(size_t)(r0 + 8) * ldc + col]) = o1;
            }
        }
    }
}

// ---------------------------------------------------------------------------
// K2: TENSORIZED cosine attention + FUSED OUTPUT PROJECTION (unchanged R14).
//   Smem: qn 9216 | kn 9216 | vn 10240 = 28672 w (114,688 B) -> 2 CTAs/SM.
//   P (pitch 68) overlays qn+kn after QK; O-pack (8448 w) overlays P after PV.
// ---------------------------------------------------------------------------
__global__ __launch_bounds__(256, 2)
void attn_mma_kernel(const float* __restrict__ ls, const float* __restrict__ mask,
                     const float* __restrict__ pb, float* __restrict__ out) {
    extern __shared__ float smf[];
    float* qn = smf;                // 9216
    float* kn = smf + 9216;         // 9216
    float* vn = smf + 18432;        // 10240

    const int win = blockIdx.x, tid = threadIdx.x;

    // ---------- staging: thread = (sh = tid>>6, sr = tid&63) ----------
    {
        const int sh = tid >> 6, sr = tid & 63;
        float buf[32];
        // Q: normalize + fold clamped scale; fp32 rotated (pitch 36)
        {
            const float4* p = reinterpret_cast<const float4*>(
                g_Q + (size_t)win * 8192 + sr * 128 + sh * 32);
#pragma unroll
            for (int t = 0; t < 8; ++t) {
                float4 x = p[t];
                buf[4*t] = x.x; buf[4*t+1] = x.y; buf[4*t+2] = x.z; buf[4*t+3] = x.w;
            }
            float ssum = 0.f;
#pragma unroll
            for (int d = 0; d < 32; ++d) ssum = fmaf(buf[d], buf[d], ssum);
            float sc = __expf(fminf(ls[sh], 4.6051702f));
            float qs = sc / fmaxf(sqrtf(ssum), 1e-12f);
            float* dq = qn + (sh * 64 + sr) * 36;
#pragma unroll
            for (int d = 0; d < 32; ++d) dq[(d + sr) & 31] = buf[d] * qs;
        }
        // K: normalize; fp32 rotated
        {
            const float4* p = reinterpret_cast<const float4*>(
                g_KV + (size_t)win * 16384 + sr * 256 + sh * 32);
#pragma unroll
            for (int t = 0; t < 8; ++t) {
                float4 x = p[t];
                buf[4*t] = x.x; buf[4*t+1] = x.y; buf[4*t+2] = x.z; buf[4*t+3] = x.w;
            }
            float ssum = 0.f;
#pragma unroll
            for (int d = 0; d < 32; ++d) ssum = fmaf(buf[d], buf[d], ssum);
            float kqs = 1.f / fmaxf(sqrtf(ssum), 1e-12f);
            float* dk = kn + (sh * 64 + sr) * 36;
#pragma unroll
            for (int d = 0; d < 32; ++d) dk[(d + sr) & 31] = buf[d] * kqs;
        }
        // V: tf32, rotated (pitch 40)
        {
            const float4* p = reinterpret_cast<const float4*>(
                g_KV + (size_t)win * 16384 + sr * 256 + 128 + sh * 32);
#pragma unroll
            for (int t = 0; t < 8; ++t) {
                float4 x = p[t];
                buf[4*t] = x.x; buf[4*t+1] = x.y; buf[4*t+2] = x.z; buf[4*t+3] = x.w;
            }
            float* dv = vn + (sh * 64 + sr) * 40;
#pragma unroll
            for (int d = 0; d < 32; ++d) dv[(d + sr) & 31] = tf32f(buf[d]);
        }
    }
    __syncthreads();

    // ---------- per-warp mma work ----------
    const int w = tid >> 5, lane = tid & 31;
    const int h = w >> 1, mh = w & 1;
    const int g = lane >> 2, tg = lane & 3;

    const float* Qb = qn + h * 2304;
    const float* Kb = kn + h * 2304;

    float acc[2][8][4];
#pragma unroll
    for (int mt = 0; mt < 2; ++mt)
#pragma unroll
        for (int nt = 0; nt < 8; ++nt)
#pragma unroll
            for (int r = 0; r < 4; ++r) acc[mt][nt][r] = 0.f;

    // ---- QK^T: tf32x3 with on-the-fly hi/lo split ----
#pragma unroll 1
    for (int ks = 0; ks < 4; ++ks) {
        const int c0 = ks * 8 + tg, c1 = c0 + 4;
        float qh[2][4], ql[2][4];
#pragma unroll
        for (int mt = 0; mt < 2; ++mt) {
            int ra = mh * 32 + mt * 16 + g, rb = ra + 8;
            float v0 = Qb[ra * 36 + ((c0 + ra) & 31)];
            float v1 = Qb[rb * 36 + ((c0 + rb) & 31)];
            float v2 = Qb[ra * 36 + ((c1 + ra) & 31)];
            float v3 = Qb[rb * 36 + ((c1 + rb) & 31)];
            qh[mt][0] = tf32f(v0); ql[mt][0] = tf32f(v0 - qh[mt][0]);
            qh[mt][1] = tf32f(v1); ql[mt][1] = tf32f(v1 - qh[mt][1]);
            qh[mt][2] = tf32f(v2); ql[mt][2] = tf32f(v2 - qh[mt][2]);
            qh[mt][3] = tf32f(v3); ql[mt][3] = tf32f(v3 - qh[mt][3]);
        }
#pragma unroll
        for (int nt = 0; nt < 8; ++nt) {
            int j = nt * 8 + g;
            float k0 = Kb[j * 36 + ((c0 + j) & 31)];
            float k1 = Kb[j * 36 + ((c1 + j) & 31)];
            float bh0 = tf32f(k0), bl0 = tf32f(k0 - bh0);
            float bh1 = tf32f(k1), bl1 = tf32f(k1 - bh1);
#pragma unroll
            for (int mt = 0; mt < 2; ++mt) {
                mma_tf32f(acc[mt][nt][0], acc[mt][nt][1], acc[mt][nt][2], acc[mt][nt][3],
                          qh[mt][0], qh[mt][1], qh[mt][2], qh[mt][3], bh0, bh1);
                mma_tf32f(acc[mt][nt][0], acc[mt][nt][1], acc[mt][nt][2], acc[mt][nt][3],
                          qh[mt][0], qh[mt][1], qh[mt][2], qh[mt][3], bl0, bl1);
                mma_tf32f(acc[mt][nt][0], acc[mt][nt][1], acc[mt][nt][2], acc[mt][nt][3],
                          ql[mt][0], ql[mt][1], ql[mt][2], ql[mt][3], bh0, bh1);
            }
        }
    }

    // ---- bias + mask ----
    {
        const float* bias = g_biasD + h * 4096;
        const float* msk  = mask + (size_t)(win & (NMASK - 1)) * 4096;
#pragma unroll
        for (int mt = 0; mt < 2; ++mt) {
            int ra = mh * 32 + mt * 16 + g, rb = ra + 8;
#pragma unroll
            for (int nt = 0; nt < 8; ++nt) {
                int col = nt * 8 + 2 * tg;
                float2 ba = *reinterpret_cast<const float2*>(bias + ra * 64 + col);
                float2 ma = *reinterpret_cast<const float2*>(msk  + ra * 64 + col);
                float2 bb = *reinterpret_cast<const float2*>(bias + rb * 64 + col);
                float2 mb = *reinterpret_cast<const float2*>(msk  + rb * 64 + col);
                acc[mt][nt][0] += ba.x + ma.x;
                acc[mt][nt][1] += ba.y + ma.y;
                acc[mt][nt][2] += bb.x + mb.x;
                acc[mt][nt][3] += bb.y + mb.y;
            }
        }
    }

    // ---- softmax over j (quad shuffles) ----
#pragma unroll
    for (int mt = 0; mt < 2; ++mt) {
#pragma unroll
        for (int hf = 0; hf < 2; ++hf) {
            float m = -1e30f;
#pragma unroll
            for (int nt = 0; nt < 8; ++nt)
                m = fmaxf(m, fmaxf(acc[mt][nt][hf * 2], acc[mt][nt][hf * 2 + 1]));
            m = fmaxf(m, __shfl_xor_sync(0xffffffffu, m, 1));
            m = fmaxf(m, __shfl_xor_sync(0xffffffffu, m, 2));
            float s = 0.f;
#pragma unroll
            for (int nt = 0; nt < 8; ++nt) {
                float e0 = __expf(acc[mt][nt][hf * 2]     - m);
                float e1 = __expf(acc[mt][nt][hf * 2 + 1] - m);
                acc[mt][nt][hf * 2]     = e0;
                acc[mt][nt][hf * 2 + 1] = e1;
                s += e0 + e1;
            }
            s += __shfl_xor_sync(0xffffffffu, s, 1);
            s += __shfl_xor_sync(0xffffffffu, s, 2);
            float inv = 1.f / s;
#pragma unroll
            for (int nt = 0; nt < 8; ++nt) {
                acc[mt][nt][hf * 2]     *= inv;
                acc[mt][nt][hf * 2 + 1] *= inv;
            }
        }
    }

    __syncthreads();   // all warps done reading qn/kn before P overlays them

    // ---- store P (tf32, pitch 68) overlaying qn+kn ----
    float* P = smf + h * 4352;
#pragma unroll
    for (int mt = 0; mt < 2; ++mt) {
        int ra = mh * 32 + mt * 16 + g, rb = ra + 8;
#pragma unroll
        for (int nt = 0; nt < 8; ++nt) {
            int col = nt * 8 + 2 * tg;
            float2 p0 = make_float2(tf32f(acc[mt][nt][0]), tf32f(acc[mt][nt][1]));
            float2 p1 = make_float2(tf32f(acc[mt][nt][2]), tf32f(acc[mt][nt][3]));
            *reinterpret_cast<float2*>(P + ra * 68 + col) = p0;
            *reinterpret_cast<float2*>(P + rb * 68 + col) = p1;
        }
    }
    __syncwarp();

    // ---- PV: m32(warp) x n32 x k64 ----
    const float* Vh = vn + h * 2560;
    float o[2][4][4];
#pragma unroll
    for (int mt = 0; mt < 2; ++mt)
#pragma unroll
        for (int nt = 0; nt < 4; ++nt)
#pragma unroll
            for (int r = 0; r < 4; ++r) o[mt][nt][r] = 0.f;

#pragma unroll 1
    for (int ks = 0; ks < 8; ++ks) {
        const int j0 = ks * 8 + tg, j1 = j0 + 4;
        float pa[2][4];
#pragma unroll
        for (int mt = 0; mt < 2; ++mt) {
            int ra = mh * 32 + mt * 16 + g, rb = ra + 8;
            pa[mt][0] = P[ra * 68 + j0];
            pa[mt][1] = P[rb * 68 + j0];
            pa[mt][2] = P[ra * 68 + j1];
            pa[mt][3] = P[rb * 68 + j1];
        }
#pragma unroll
        for (int nt = 0; nt < 4; ++nt) {
            int d = nt * 8 + g;
            float vb0 = Vh[j0 * 40 + ((d + j0) & 31)];
            float vb1 = Vh[j1 * 40 + ((d + j1) & 31)];
#pragma unroll
            for (int mt = 0; mt < 2; ++mt)
                mma_tf32f(o[mt][nt][0], o[mt][nt][1], o[mt][nt][2], o[mt][nt][3],
                          pa[mt][0], pa[mt][1], pa[mt][2], pa[mt][3], vb0, vb1);
        }
    }

    __syncthreads();   // all P/V reads done before O-pack overlays the region

    // ---- store O (tf32) in gemm fragment-packed layout at smf[0..8448) ----
    {
        uint32_t* Ou = reinterpret_cast<uint32_t*>(smf);
#pragma unroll
        for (int mt = 0; mt < 2; ++mt) {
#pragma unroll
            for (int nt = 0; nt < 4; ++nt) {
                int S = (mh * 2 + mt) * 16 + h * 4 + nt;
                uint32_t* base = Ou + S * A_PITCH + g * 16 + (tg >> 1) * 2 + (tg & 1) * 8;
                base[0] = f2tf32(o[mt][nt][0]);   // row g,   col 2tg
                base[4] = f2tf32(o[mt][nt][1]);   // row g,   col 2tg+1
                base[1] = f2tf32(o[mt][nt][2]);   // row g+8, col 2tg
                base[5] = f2tf32(o[mt][nt][3]);   // row g+8, col 2tg+1
            }
        }
    }
    __syncthreads();

    // ---- fused projection: out(64x128) = O @ pw^T + pb ----
    {
        const int wm2 = w >> 2, wn2 = w & 3;
        const uint32_t* Ob = reinterpret_cast<const uint32_t*>(smf) + lane * 4;
        const uint32_t* Wp = g_Wpk + 3 * 16384 + lane * 4;

        float pr[2][4][4];
#pragma unroll
        for (int mt = 0; mt < 2; ++mt)
#pragma unroll
            for (int nt = 0; nt < 4; ++nt)
#pragma unroll
                for (int r = 0; r < 4; ++r) pr[mt][nt][r] = 0.f;

#pragma unroll 1
        for (int ks2 = 0; ks2 < 8; ++ks2) {
            const int sA0 = (wm2 * 2 + 0) * 16 + ks2 * 2;
            const int sA1 = (wm2 * 2 + 1) * 16 + ks2 * 2;
            uint4 a0L = *reinterpret_cast<const uint4*>(Ob + sA0 * A_PITCH);
            uint4 a0H = *reinterpret_cast<const uint4*>(Ob + (sA0 + 1) * A_PITCH);
            uint4 a1L = *reinterpret_cast<const uint4*>(Ob + sA1 * A_PITCH);
            uint4 a1H = *reinterpret_cast<const uint4*>(Ob + (sA1 + 1) * A_PITCH);
#pragma unroll
            for (int nt = 0; nt < 4; ++nt) {
                uint4 b = *reinterpret_cast<const uint4*>(
                    Wp + ((wn2 * 4 + nt) * 8 + ks2) * 128);
                mma_tf32(pr[0][nt][0], pr[0][nt][1], pr[0][nt][2], pr[0][nt][3],
                         a0L.x, a0L.y, a0L.z, a0L.w, b.x, b.y);
                mma_tf32(pr[0][nt][0], pr[0][nt][1], pr[0][nt][2], pr[0][nt][3],
                         a0H.x, a0H.y, a0H.z, a0H.w, b.z, b.w);
                mma_tf32(pr[1][nt][0], pr[1][nt][1], pr[1][nt][2], pr[1][nt][3],
                         a1L.x, a1L.y, a1L.z, a1L.w, b.x, b.y);
                mma_tf32(pr[1][nt][0], pr[1][nt][1], pr[1][nt][2], pr[1][nt][3],
                         a1H.x, a1H.y, a1H.z, a1H.w, b.z, b.w);
            }
        }

        float* Out = out + (size_t)win * 8192;
#pragma unroll
        for (int mt = 0; mt < 2; ++mt) {
            const int r0 = wm2 * 32 + mt * 16 + g;
#pragma unroll
            for (int nt = 0; nt < 4; ++nt) {
                const int col = wn2 * 32 + nt * 8 + 2 * tg;
                float bb0 = __ldg(pb + col);
                float bb1 = __ldg(pb + col + 1);
                *reinterpret_cast<float2*>(&Out[(size_t)r0 * 128 + col]) =
                    make_float2(pr[mt][nt][0] + bb0, pr[mt][nt][1] + bb1);
                *reinterpret_cast<float2*>(&Out[(size_t)(r0 + 8) * 128 + col]) =
                    make_float2(pr[mt][nt][2] + bb0, pr[mt][nt][3] + bb1);
            }
        }
    }
}

// ---------------------------------------------------------------------------
// Launch — only harness-provided pointers cross the host/device boundary.
// ---------------------------------------------------------------------------
extern "C" void kernel_launch(void* const* d_in, const int* in_sizes, int n_in,
                              void* d_out, int out_size) {
    const float* x    = (const float*)d_in[0];
    const float* ctx  = (const float*)d_in[1];
    const float* mask = (const float*)d_in[2];
    const float* q_w  = (const float*)d_in[3];
    const float* q_b  = (const float*)d_in[4];
    const float* kv_w = (const float*)d_in[5];
    const float* v_b  = (const float*)d_in[6];
    const float* ls   = (const float*)d_in[7];
    const float* w1   = (const float*)d_in[8];
    const float* b1   = (const float*)d_in[9];
    const float* w2   = (const float*)d_in[10];
    const float* pw   = (const float*)d_in[11];
    const float* pb   = (const float*)d_in[12];
    const float* tbl  = (const float*)d_in[13];
    const int*   rpi  = (const int*)d_in[14];
    float* out = (float*)d_out;

    const int ATTN_SMEM = 28672 * 4;            // 114,688 B -> 2 CTAs/SM

    cudaFuncSetAttribute(attn_mma_kernel, cudaFuncAttributeMaxDynamicSharedMemorySize, ATTN_SMEM);

    // Prep (tiny)
    cpb_bias_kernel<<<1, 256>>>(tbl, w1, b1, w2, rpi);
    pack_weights_kernel<<<4, 256>>>(q_w, kv_w, pw);

    const int MTILES = NWIN * NTOK / 64;   // 4096

    // Q = x @ q_w^T + q_b
    gemm_tf32<<<MTILES, 256>>>(x, q_b, nullptr, 0, 0);
    // K|V = ctx @ kv_w^T (+ [0;v_b]) — single pass, two packed halves
    gemm_tf32<<<MTILES, 256>>>(ctx, nullptr, v_b, 1, 1);

    // Tensorized fused cosine attention + output projection
    attn_mma_kernel<<<NWIN, 256, ATTN_SMEM>>>(ls, mask, pb, out);
}

// round 16
// speedup vs baseline: 3.7663x; 1.3333x over previous
#include <cuda_runtime.h>
#include <math.h>
#include <stdint.h>

// Problem constants
#define NWIN 4096
#define NTOK 64
#define DIM  128
#define NH   4
#define HD   32
#define NMASK 64

// ---------------------------------------------------------------------------
// Scratch (allocation-free: __device__ globals; NEVER referenced from host)
// ---------------------------------------------------------------------------
__device__ float    g_biasD[NH * NTOK * NTOK];       // [h][i][j]  (direct layout)
__device__ uint32_t g_Wpk[4 * 16384];                // packed tf32 weights
                                                     // 0=q_w, 1=kv_w(K), 2=kv_w(V), 3=proj_w

__device__ __forceinline__ uint32_t f2tf32(float f) {
    uint32_t u;
    asm("cvt.rna.tf32.f32 %0, %1;" : "=r"(u) : "f"(f));
    return u;
}
__device__ __forceinline__ float tf32f(float f) {
    return __uint_as_float(f2tf32(f));
}

// ---------------------------------------------------------------------------
// K0b: CPB-MLP relative position bias, gathered, DIRECT layout [h][i][j]
// ---------------------------------------------------------------------------
__global__ void cpb_bias_kernel(const float* __restrict__ table,
                                const float* __restrict__ w1,
                                const float* __restrict__ b1,
                                const float* __restrict__ w2,
                                const int*   __restrict__ rpi) {
    __shared__ float tbl[225][4];
    const int tid = threadIdx.x;
    if (tid < 225) {
        float c0 = table[tid * 2 + 0];
        float c1 = table[tid * 2 + 1];
        float o0 = 0.f, o1 = 0.f, o2 = 0.f, o3 = 0.f;
        for (int m = 0; m < 512; ++m) {
            float hv = fmaf(c0, w1[m * 2], fmaf(c1, w1[m * 2 + 1], b1[m]));
            hv = fmaxf(hv, 0.f);
            o0 = fmaf(hv, w2[0 * 512 + m], o0);
            o1 = fmaf(hv, w2[1 * 512 + m], o1);
            o2 = fmaf(hv, w2[2 * 512 + m], o2);
            o3 = fmaf(hv, w2[3 * 512 + m], o3);
        }
        tbl[tid][0] = o0; tbl[tid][1] = o1; tbl[tid][2] = o2; tbl[tid][3] = o3;
    }
    __syncthreads();
    for (int e = tid; e < NTOK * NTOK; e += blockDim.x) {
        int id = rpi[e];
#pragma unroll
        for (int hh = 0; hh < NH; ++hh) {
            float v = tbl[id][hh];
            g_biasD[hh * 4096 + e] = 16.f / (1.f + __expf(-v));
        }
    }
}

// ---------------------------------------------------------------------------
// K0c: pack weights -> tf32 mma-fragment order.
// ---------------------------------------------------------------------------
__global__ void pack_weights_kernel(const float* __restrict__ qw,
                                    const float* __restrict__ kvw,
                                    const float* __restrict__ pw) {
    const int b = blockIdx.x;
    const float* W = (b == 0) ? qw : (b == 1) ? kvw : (b == 2) ? (kvw + 16384) : pw;
    uint32_t* out = g_Wpk + b * 16384;
    for (int idx = threadIdx.x; idx < 16384; idx += blockDim.x) {
        int reg = idx & 3, lane = (idx >> 2) & 31, ks2 = (idx >> 7) & 7, ntile = idx >> 10;
        int n = ntile * 8 + (lane >> 2);
        int k = ks2 * 16 + reg * 4 + (lane & 3);
        out[idx] = f2tf32(W[n * 128 + k]);
    }
}

// ---------------------------------------------------------------------------
// mma helpers
// ---------------------------------------------------------------------------
__device__ __forceinline__ void mma_tf32(float& c0, float& c1, float& c2, float& c3,
                                         uint32_t a0, uint32_t a1, uint32_t a2, uint32_t a3,
                                         uint32_t b0, uint32_t b1) {
    asm volatile(
        "mma.sync.aligned.m16n8k8.row.col.f32.tf32.tf32.f32 "
        "{%0,%1,%2,%3}, {%4,%5,%6,%7}, {%8,%9}, {%0,%1,%2,%3};"
        : "+f"(c0), "+f"(c1), "+f"(c2), "+f"(c3)
        : "r"(a0), "r"(a1), "r"(a2), "r"(a3), "r"(b0), "r"(b1));
}
__device__ __forceinline__ void mma_tf32f(float& c0, float& c1, float& c2, float& c3,
                                          float a0, float a1, float a2, float a3,
                                          float b0, float b1) {
    mma_tf32(c0, c1, c2, c3,
             __float_as_uint(a0), __float_as_uint(a1),
             __float_as_uint(a2), __float_as_uint(a3),
             __float_as_uint(b0), __float_as_uint(b1));
}

#define A_PITCH 132

// Stage a 64x128 fp32 tile -> fragment-packed tf32 smem (8448 words).
__device__ __forceinline__ void stage_pack(uint32_t* pack,
                                           const float* __restrict__ src, int tid) {
    const float4* A4 = reinterpret_cast<const float4*>(src);
#pragma unroll
    for (int t = 0; t < 8; ++t) {
        int idx = tid + t * 256;
        int r = idx >> 5, c4 = idx & 31;
        float4 v = A4[idx];
        int mtile = r >> 4, gg = r & 7, mh2 = (r >> 3) & 1;
        int slot = mtile * 16 + (c4 >> 1);
        int regb = (c4 & 1) * 2 + mh2;
        uint32_t* base = pack + slot * A_PITCH + gg * 16 + regb;
        base[0]  = f2tf32(v.x);
        base[4]  = f2tf32(v.y);
        base[8]  = f2tf32(v.z);
        base[12] = f2tf32(v.w);
    }
}

// One 32x32 warp gemm tile from a fragment pack, B via LDG from packed weights.
__device__ __forceinline__ void tile_gemm(const uint32_t* __restrict__ pack,
                                          const uint32_t* __restrict__ Wb,
                                          int wm, int wn, int lane,
                                          float (&acc)[2][4][4]) {
#pragma unroll
    for (int mt = 0; mt < 2; ++mt)
#pragma unroll
        for (int nt = 0; nt < 4; ++nt)
#pragma unroll
            for (int r = 0; r < 4; ++r) acc[mt][nt][r] = 0.f;
    const uint32_t* Abase = pack + lane * 4;
    const uint32_t* Bbase = Wb + lane * 4;
#pragma unroll 1
    for (int ks2 = 0; ks2 < 8; ++ks2) {
        const int sA0 = (wm * 2 + 0) * 16 + ks2 * 2;
        const int sA1 = (wm * 2 + 1) * 16 + ks2 * 2;
        uint4 a0L = *reinterpret_cast<const uint4*>(Abase + sA0 * A_PITCH);
        uint4 a0H = *reinterpret_cast<const uint4*>(Abase + (sA0 + 1) * A_PITCH);
        uint4 a1L = *reinterpret_cast<const uint4*>(Abase + sA1 * A_PITCH);
        uint4 a1H = *reinterpret_cast<const uint4*>(Abase + (sA1 + 1) * A_PITCH);
#pragma unroll
        for (int nt = 0; nt < 4; ++nt) {
            uint4 b = *reinterpret_cast<const uint4*>(
                Bbase + ((wn * 4 + nt) * 8 + ks2) * 128);
            mma_tf32(acc[0][nt][0], acc[0][nt][1], acc[0][nt][2], acc[0][nt][3],
                     a0L.x, a0L.y, a0L.z, a0L.w, b.x, b.y);
            mma_tf32(acc[0][nt][0], acc[0][nt][1], acc[0][nt][2], acc[0][nt][3],
                     a0H.x, a0H.y, a0H.z, a0H.w, b.z, b.w);
            mma_tf32(acc[1][nt][0], acc[1][nt][1], acc[1][nt][2], acc[1][nt][3],
                     a1L.x, a1L.y, a1L.z, a1L.w, b.x, b.y);
            mma_tf32(acc[1][nt][0], acc[1][nt][1], acc[1][nt][2], acc[1][nt][3],
                     a1H.x, a1H.y, a1H.z, a1H.w, b.z, b.w);
        }
    }
}

// Quad-reduce (lanes xor 1, 2) a pair of row sums.
__device__ __forceinline__ float quad_sum(float s) {
    s += __shfl_xor_sync(0xffffffffu, s, 1);
    s += __shfl_xor_sync(0xffffffffu, s, 2);
    return s;
}

// ---------------------------------------------------------------------------
// MEGA KERNEL: projections (Q,K,V) + cosine attention + output projection.
//   One CTA/window, 256 threads, 2 CTAs/SM (114,688 B smem).
//   Region plan (words):  [0,8448)=x-pack -> qn[0,9216)
//                         [9216,18432)=kn
//                         [18432,26880)=ctx-pack -> vn[18432,28672)
//   After QK: P (pitch 68) overlays qn+kn; after PV: O-pack overlays P.
// ---------------------------------------------------------------------------
__global__ __launch_bounds__(256, 2)
void attn_mega_kernel(const float* __restrict__ x, const float* __restrict__ ctx,
                      const float* __restrict__ ls, const float* __restrict__ mask,
                      const float* __restrict__ q_b, const float* __restrict__ v_b,
                      const float* __restrict__ pb, float* __restrict__ out) {
    extern __shared__ float smf[];
    uint32_t* Xp = reinterpret_cast<uint32_t*>(smf);            // x pack
    uint32_t* Cp = reinterpret_cast<uint32_t*>(smf) + 18432;    // ctx pack
    float* qn = smf;            // 9216
    float* kn = smf + 9216;     // 9216
    float* vn = smf + 18432;    // 10240

    const int win = blockIdx.x, tid = threadIdx.x;
    const int w = tid >> 5, lane = tid & 31;
    const int g = lane >> 2, tg = lane & 3;
    const int wm = w >> 2, wn = w & 3;   // projection-phase warp grid

    // ---- stage input packs ----
    stage_pack(Xp, x  + (size_t)win * 8192, tid);
    stage_pack(Cp, ctx + (size_t)win * 8192, tid);
    __syncthreads();

    // ---- Q projection: 32x32 tile, head = wn ----
    {
        float qa[2][4][4];
        tile_gemm(Xp, g_Wpk, wm, wn, lane, qa);
        // + q_b, per-row l2 norm over this head's 32 dims, fold clamped scale
        float sc = __expf(fminf(__ldg(ls + wn), 4.6051702f));
#pragma unroll
        for (int mt = 0; mt < 2; ++mt) {
            float ssA = 0.f, ssB = 0.f;
#pragma unroll
            for (int nt = 0; nt < 4; ++nt) {
                int col = wn * 32 + nt * 8 + 2 * tg;
                float b0 = __ldg(q_b + col), b1 = __ldg(q_b + col + 1);
                qa[mt][nt][0] += b0; qa[mt][nt][1] += b1;
                qa[mt][nt][2] += b0; qa[mt][nt][3] += b1;
                ssA = fmaf(qa[mt][nt][0], qa[mt][nt][0],
                      fmaf(qa[mt][nt][1], qa[mt][nt][1], ssA));
                ssB = fmaf(qa[mt][nt][2], qa[mt][nt][2],
                      fmaf(qa[mt][nt][3], qa[mt][nt][3], ssB));
            }
            float sA = sc / fmaxf(sqrtf(quad_sum(ssA)), 1e-12f);
            float sB = sc / fmaxf(sqrtf(quad_sum(ssB)), 1e-12f);
#pragma unroll
            for (int nt = 0; nt < 4; ++nt) {
                qa[mt][nt][0] *= sA; qa[mt][nt][1] *= sA;
                qa[mt][nt][2] *= sB; qa[mt][nt][3] *= sB;
            }
        }
        __syncthreads();   // all x-pack reads done before qn overlays it
        // write qn[head=wn][row][dim] (pitch 36, rotated)
        float* dq = qn + wn * 2304;
#pragma unroll
        for (int mt = 0; mt < 2; ++mt) {
            int ra = wm * 32 + mt * 16 + g, rb = ra + 8;
#pragma unroll
            for (int nt = 0; nt < 4; ++nt) {
                int d = nt * 8 + 2 * tg;
                dq[ra * 36 + ((d + ra) & 31)]     = qa[mt][nt][0];
                dq[ra * 36 + ((d + 1 + ra) & 31)] = qa[mt][nt][1];
                dq[rb * 36 + ((d + rb) & 31)]     = qa[mt][nt][2];
                dq[rb * 36 + ((d + 1 + rb) & 31)] = qa[mt][nt][3];
            }
        }
    }

    // ---- K projection (no bias, l2 norm) -> kn; V projection (+v_b) -> vn ----
    {
        float ka[2][4][4];
        tile_gemm(Cp, g_Wpk + 16384, wm, wn, lane, ka);
#pragma unroll
        for (int mt = 0; mt < 2; ++mt) {
            float ssA = 0.f, ssB = 0.f;
#pragma unroll
            for (int nt = 0; nt < 4; ++nt) {
                ssA = fmaf(ka[mt][nt][0], ka[mt][nt][0],
                      fmaf(ka[mt][nt][1], ka[mt][nt][1], ssA));
                ssB = fmaf(ka[mt][nt][2], ka[mt][nt][2],
                      fmaf(ka[mt][nt][3], ka[mt][nt][3], ssB));
            }
            float sA = 1.f / fmaxf(sqrtf(quad_sum(ssA)), 1e-12f);
            float sB = 1.f / fmaxf(sqrtf(quad_sum(ssB)), 1e-12f);
#pragma unroll
            for (int nt = 0; nt < 4; ++nt) {
                ka[mt][nt][0] *= sA; ka[mt][nt][1] *= sA;
                ka[mt][nt][2] *= sB; ka[mt][nt][3] *= sB;
            }
        }
        // kn region untouched so far -> write now (no sync needed; Cp not touched)
        float* dk = kn + wn * 2304;
#pragma unroll
        for (int mt = 0; mt < 2; ++mt) {
            int ra = wm * 32 + mt * 16 + g, rb = ra + 8;
#pragma unroll
            for (int nt = 0; nt < 4; ++nt) {
                int d = nt * 8 + 2 * tg;
                dk[ra * 36 + ((d + ra) & 31)]     = ka[mt][nt][0];
                dk[ra * 36 + ((d + 1 + ra) & 31)] = ka[mt][nt][1];
                dk[rb * 36 + ((d + rb) & 31)]     = ka[mt][nt][2];
                dk[rb * 36 + ((d + 1 + rb) & 31)] = ka[mt][nt][3];
            }
        }

        float va[2][4][4];
        tile_gemm(Cp, g_Wpk + 2 * 16384, wm, wn, lane, va);
        __syncthreads();   // all ctx-pack reads done before vn overlays it
        float* dv = vn + wn * 2560;
#pragma unroll
        for (int mt = 0; mt < 2; ++mt) {
            int ra = wm * 32 + mt * 16 + g, rb = ra + 8;
#pragma unroll
            for (int nt = 0; nt < 4; ++nt) {
                int col = wn * 32 + nt * 8 + 2 * tg;
                float b0 = __ldg(v_b + col), b1 = __ldg(v_b + col + 1);
                int d = nt * 8 + 2 * tg;
                dv[ra * 40 + ((d + ra) & 31)]     = tf32f(va[mt][nt][0] + b0);
                dv[ra * 40 + ((d + 1 + ra) & 31)] = tf32f(va[mt][nt][1] + b1);
                dv[rb * 40 + ((d + rb) & 31)]     = tf32f(va[mt][nt][2] + b0);
                dv[rb * 40 + ((d + 1 + rb) & 31)] = tf32f(va[mt][nt][3] + b1);
            }
        }
    }
    __syncthreads();

    // ================= attention phases (identical to R15) =================
    const int h = w >> 1, mh = w & 1;
    const float* Qb = qn + h * 2304;
    const float* Kb = kn + h * 2304;

    float acc[2][8][4];
#pragma unroll
    for (int mt = 0; mt < 2; ++mt)
#pragma unroll
        for (int nt = 0; nt < 8; ++nt)
#pragma unroll
            for (int r = 0; r < 4; ++r) acc[mt][nt][r] = 0.f;

    // ---- QK^T: tf32x3 with on-the-fly hi/lo split ----
#pragma unroll 1
    for (int ks = 0; ks < 4; ++ks) {
        const int c0 = ks * 8 + tg, c1 = c0 + 4;
        float qh[2][4], ql[2][4];
#pragma unroll
        for (int mt = 0; mt < 2; ++mt) {
            int ra = mh * 32 + mt * 16 + g, rb = ra + 8;
            float v0 = Qb[ra * 36 + ((c0 + ra) & 31)];
            float v1 = Qb[rb * 36 + ((c0 + rb) & 31)];
            float v2 = Qb[ra * 36 + ((c1 + ra) & 31)];
            float v3 = Qb[rb * 36 + ((c1 + rb) & 31)];
            qh[mt][0] = tf32f(v0); ql[mt][0] = tf32f(v0 - qh[mt][0]);
            qh[mt][1] = tf32f(v1); ql[mt][1] = tf32f(v1 - qh[mt][1]);
            qh[mt][2] = tf32f(v2); ql[mt][2] = tf32f(v2 - qh[mt][2]);
            qh[mt][3] = tf32f(v3); ql[mt][3] = tf32f(v3 - qh[mt][3]);
        }
#pragma unroll
        for (int nt = 0; nt < 8; ++nt) {
            int j = nt * 8 + g;
            float k0 = Kb[j * 36 + ((c0 + j) & 31)];
            float k1 = Kb[j * 36 + ((c1 + j) & 31)];
            float bh0 = tf32f(k0), bl0 = tf32f(k0 - bh0);
            float bh1 = tf32f(k1), bl1 = tf32f(k1 - bh1);
#pragma unroll
            for (int mt = 0; mt < 2; ++mt) {
                mma_tf32f(acc[mt][nt][0], acc[mt][nt][1], acc[mt][nt][2], acc[mt][nt][3],
                          qh[mt][0], qh[mt][1], qh[mt][2], qh[mt][3], bh0, bh1);
                mma_tf32f(acc[mt][nt][0], acc[mt][nt][1], acc[mt][nt][2], acc[mt][nt][3],
                          qh[mt][0], qh[mt][1], qh[mt][2], qh[mt][3], bl0, bl1);
                mma_tf32f(acc[mt][nt][0], acc[mt][nt][1], acc[mt][nt][2], acc[mt][nt][3],
                          ql[mt][0], ql[mt][1], ql[mt][2], ql[mt][3], bh0, bh1);
            }
        }
    }

    // ---- bias + mask ----
    {
        const float* bias = g_biasD + h * 4096;
        const float* msk  = mask + (size_t)(win & (NMASK - 1)) * 4096;
#pragma unroll
        for (int mt = 0; mt < 2; ++mt) {
            int ra = mh * 32 + mt * 16 + g, rb = ra + 8;
#pragma unroll
            for (int nt = 0; nt < 8; ++nt) {
                int col = nt * 8 + 2 * tg;
                float2 ba = *reinterpret_cast<const float2*>(bias + ra * 64 + col);
                float2 ma = *reinterpret_cast<const float2*>(msk  + ra * 64 + col);
                float2 bb = *reinterpret_cast<const float2*>(bias + rb * 64 + col);
                float2 mb = *reinterpret_cast<const float2*>(msk  + rb * 64 + col);
                acc[mt][nt][0] += ba.x + ma.x;
                acc[mt][nt][1] += ba.y + ma.y;
                acc[mt][nt][2] += bb.x + mb.x;
                acc[mt][nt][3] += bb.y + mb.y;
            }
        }
    }

    // ---- softmax over j (quad shuffles) ----
#pragma unroll
    for (int mt = 0; mt < 2; ++mt) {
#pragma unroll
        for (int hf = 0; hf < 2; ++hf) {
            float m = -1e30f;
#pragma unroll
            for (int nt = 0; nt < 8; ++nt)
                m = fmaxf(m, fmaxf(acc[mt][nt][hf * 2], acc[mt][nt][hf * 2 + 1]));
            m = fmaxf(m, __shfl_xor_sync(0xffffffffu, m, 1));
            m = fmaxf(m, __shfl_xor_sync(0xffffffffu, m, 2));
            float s = 0.f;
#pragma unroll
            for (int nt = 0; nt < 8; ++nt) {
                float e0 = __expf(acc[mt][nt][hf * 2]     - m);
                float e1 = __expf(acc[mt][nt][hf * 2 + 1] - m);
                acc[mt][nt][hf * 2]     = e0;
                acc[mt][nt][hf * 2 + 1] = e1;
                s += e0 + e1;
            }
            s += __shfl_xor_sync(0xffffffffu, s, 1);
            s += __shfl_xor_sync(0xffffffffu, s, 2);
            float inv = 1.f / s;
#pragma unroll
            for (int nt = 0; nt < 8; ++nt) {
                acc[mt][nt][hf * 2]     *= inv;
                acc[mt][nt][hf * 2 + 1] *= inv;
            }
        }
    }

    __syncthreads();   // all warps done reading qn/kn before P overlays them

    // ---- store P (tf32, pitch 68) overlaying qn+kn ----
    float* P = smf + h * 4352;
#pragma unroll
    for (int mt = 0; mt < 2; ++mt) {
        int ra = mh * 32 + mt * 16 + g, rb = ra + 8;
#pragma unroll
        for (int nt = 0; nt < 8; ++nt) {
            int col = nt * 8 + 2 * tg;
            float2 p0 = make_float2(tf32f(acc[mt][nt][0]), tf32f(acc[mt][nt][1]));
            float2 p1 = make_float2(tf32f(acc[mt][nt][2]), tf32f(acc[mt][nt][3]));
            *reinterpret_cast<float2*>(P + ra * 68 + col) = p0;
            *reinterpret_cast<float2*>(P + rb * 68 + col) = p1;
        }
    }
    __syncwarp();

    // ---- PV: m32(warp) x n32 x k64 ----
    const float* Vh = vn + h * 2560;
    float o[2][4][4];
#pragma unroll
    for (int mt = 0; mt < 2; ++mt)
#pragma unroll
        for (int nt = 0; nt < 4; ++nt)
#pragma unroll
            for (int r = 0; r < 4; ++r) o[mt][nt][r] = 0.f;

#pragma unroll 1
    for (int ks = 0; ks < 8; ++ks) {
        const int j0 = ks * 8 + tg, j1 = j0 + 4;
        float pa[2][4];
#pragma unroll
        for (int mt = 0; mt < 2; ++mt) {
            int ra = mh * 32 + mt * 16 + g, rb = ra + 8;
            pa[mt][0] = P[ra * 68 + j0];
            pa[mt][1] = P[rb * 68 + j0];
            pa[mt][2] = P[ra * 68 + j1];
            pa[mt][3] = P[rb * 68 + j1];
        }
#pragma unroll
        for (int nt = 0; nt < 4; ++nt) {
            int d = nt * 8 + g;
            float vb0 = Vh[j0 * 40 + ((d + j0) & 31)];
            float vb1 = Vh[j1 * 40 + ((d + j1) & 31)];
#pragma unroll
            for (int mt = 0; mt < 2; ++mt)
                mma_tf32f(o[mt][nt][0], o[mt][nt][1], o[mt][nt][2], o[mt][nt][3],
                          pa[mt][0], pa[mt][1], pa[mt][2], pa[mt][3], vb0, vb1);
        }
    }

    __syncthreads();   // all P/V reads done before O-pack overlays the region

    // ---- store O (tf32) in gemm fragment-packed layout at smf[0..8448) ----
    {
        uint32_t* Ou = reinterpret_cast<uint32_t*>(smf);
#pragma unroll
        for (int mt = 0; mt < 2; ++mt) {
#pragma unroll
            for (int nt = 0; nt < 4; ++nt) {
                int S = (mh * 2 + mt) * 16 + h * 4 + nt;
                uint32_t* base = Ou + S * A_PITCH + g * 16 + (tg >> 1) * 2 + (tg & 1) * 8;
                base[0] = f2tf32(o[mt][nt][0]);   // row g,   col 2tg
                base[4] = f2tf32(o[mt][nt][1]);   // row g,   col 2tg+1
                base[1] = f2tf32(o[mt][nt][2]);   // row g+8, col 2tg
                base[5] = f2tf32(o[mt][nt][3]);   // row g+8, col 2tg+1
            }
        }
    }
    __syncthreads();

    // ---- fused projection: out(64x128) = O @ pw^T + pb ----
    {
        float pr[2][4][4];
        tile_gemm(reinterpret_cast<const uint32_t*>(smf), g_Wpk + 3 * 16384,
                  wm, wn, lane, pr);
        float* Out = out + (size_t)win * 8192;
#pragma unroll
        for (int mt = 0; mt < 2; ++mt) {
            const int r0 = wm * 32 + mt * 16 + g;
#pragma unroll
            for (int nt = 0; nt < 4; ++nt) {
                const int col = wn * 32 + nt * 8 + 2 * tg;
                float bb0 = __ldg(pb + col);
                float bb1 = __ldg(pb + col + 1);
                *reinterpret_cast<float2*>(&Out[(size_t)r0 * 128 + col]) =
                    make_float2(pr[mt][nt][0] + bb0, pr[mt][nt][1] + bb1);
                *reinterpret_cast<float2*>(&Out[(size_t)(r0 + 8) * 128 + col]) =
                    make_float2(pr[mt][nt][2] + bb0, pr[mt][nt][3] + bb1);
            }
        }
    }
}

// ---------------------------------------------------------------------------
// Launch — only harness-provided pointers cross the host/device boundary.
// ---------------------------------------------------------------------------
extern "C" void kernel_launch(void* const* d_in, const int* in_sizes, int n_in,
                              void* d_out, int out_size) {
    const float* x    = (const float*)d_in[0];
    const float* ctx  = (const float*)d_in[1];
    const float* mask = (const float*)d_in[2];
    const float* q_w  = (const float*)d_in[3];
    const float* q_b  = (const float*)d_in[4];
    const float* kv_w = (const float*)d_in[5];
    const float* v_b  = (const float*)d_in[6];
    const float* ls   = (const float*)d_in[7];
    const float* w1   = (const float*)d_in[8];
    const float* b1   = (const float*)d_in[9];
    const float* w2   = (const float*)d_in[10];
    const float* pw   = (const float*)d_in[11];
    const float* pb   = (const float*)d_in[12];
    const float* tbl  = (const float*)d_in[13];
    const int*   rpi  = (const int*)d_in[14];
    float* out = (float*)d_out;

    const int ATTN_SMEM = 28672 * 4;   // 114,688 B -> 2 CTAs/SM

    cudaFuncSetAttribute(attn_mega_kernel, cudaFuncAttributeMaxDynamicSharedMemorySize, ATTN_SMEM);

    // Prep (tiny)
    cpb_bias_kernel<<<1, 256>>>(tbl, w1, b1, w2, rpi);
    pack_weights_kernel<<<4, 256>>>(q_w, kv_w, pw);

    // Fully fused: projections + attention + output projection
    attn_mega_kernel<<<NWIN, 256, ATTN_SMEM>>>(x, ctx, ls, mask, q_b, v_b, pb, out);
}

// round 17
// speedup vs baseline: 4.0982x; 1.0881x over previous
#include <cuda_runtime.h>
#include <math.h>
#include <stdint.h>

// Problem constants
#define NWIN 4096
#define NTOK 64
#define DIM  128
#define NH   4
#define HD   32
#define NMASK 64

// ---------------------------------------------------------------------------
// Scratch (allocation-free: __device__ globals; NEVER referenced from host)
// ---------------------------------------------------------------------------
__device__ float    g_tbl[225 * 4];                  // CPB MLP outputs [row][h]
__device__ float    g_biasD[NH * NTOK * NTOK];       // [h][i][j]  (direct layout)
__device__ uint32_t g_Wpk[4 * 16384];                // packed tf32 weights
                                                     // 0=q_w, 1=kv_w(K), 2=kv_w(V), 3=proj_w

__device__ __forceinline__ uint32_t f2tf32(float f) {
    uint32_t u;
    asm("cvt.rna.tf32.f32 %0, %1;" : "=r"(u) : "f"(f));
    return u;
}
__device__ __forceinline__ float tf32f(float f) {
    return __uint_as_float(f2tf32(f));
}

// ---------------------------------------------------------------------------
// K0a: CPB MLP, one WARP per table row (225 rows). Lanes split 512 hidden
// units; butterfly-reduce 4 head outputs. 29 blocks x 8 warps.
// ---------------------------------------------------------------------------
__global__ void cpb_mlp_kernel(const float* __restrict__ table,   // (225,2)
                               const float* __restrict__ w1,      // (512,2)
                               const float* __restrict__ b1,      // (512)
                               const float* __restrict__ w2) {    // (4,512)
    const int warp = threadIdx.x >> 5, lane = threadIdx.x & 31;
    const int row = blockIdx.x * 8 + warp;
    if (row >= 225) return;
    const float c0 = __ldg(table + row * 2);
    const float c1 = __ldg(table + row * 2 + 1);
    float o0 = 0.f, o1 = 0.f, o2 = 0.f, o3 = 0.f;
#pragma unroll 4
    for (int m = lane; m < 512; m += 32) {
        float hv = fmaf(c0, __ldg(w1 + m * 2), fmaf(c1, __ldg(w1 + m * 2 + 1), __ldg(b1 + m)));
        hv = fmaxf(hv, 0.f);
        o0 = fmaf(hv, __ldg(w2 + m),        o0);
        o1 = fmaf(hv, __ldg(w2 + 512 + m),  o1);
        o2 = fmaf(hv, __ldg(w2 + 1024 + m), o2);
        o3 = fmaf(hv, __ldg(w2 + 1536 + m), o3);
    }
#pragma unroll
    for (int off = 16; off; off >>= 1) {
        o0 += __shfl_xor_sync(0xffffffffu, o0, off);
        o1 += __shfl_xor_sync(0xffffffffu, o1, off);
        o2 += __shfl_xor_sync(0xffffffffu, o2, off);
        o3 += __shfl_xor_sync(0xffffffffu, o3, off);
    }
    if (lane == 0) {
        g_tbl[row * 4 + 0] = o0;
        g_tbl[row * 4 + 1] = o1;
        g_tbl[row * 4 + 2] = o2;
        g_tbl[row * 4 + 3] = o3;
    }
}

// ---------------------------------------------------------------------------
// K0b: gather + sigmoid -> g_biasD[h][i][j]. 16 blocks x 256 threads.
// ---------------------------------------------------------------------------
__global__ void cpb_gather_kernel(const int* __restrict__ rpi) {   // (64,64)
    const int e = blockIdx.x * 256 + threadIdx.x;   // 0..4095
    const int id = __ldg(rpi + e);
    float4 t = *reinterpret_cast<const float4*>(g_tbl + id * 4);
    g_biasD[0 * 4096 + e] = 16.f / (1.f + __expf(-t.x));
    g_biasD[1 * 4096 + e] = 16.f / (1.f + __expf(-t.y));
    g_biasD[2 * 4096 + e] = 16.f / (1.f + __expf(-t.z));
    g_biasD[3 * 4096 + e] = 16.f / (1.f + __expf(-t.w));
}

// ---------------------------------------------------------------------------
// K0c: pack weights -> tf32 mma-fragment order.
// ---------------------------------------------------------------------------
__global__ void pack_weights_kernel(const float* __restrict__ qw,
                                    const float* __restrict__ kvw,
                                    const float* __restrict__ pw) {
    const int b = blockIdx.x;
    const float* W = (b == 0) ? qw : (b == 1) ? kvw : (b == 2) ? (kvw + 16384) : pw;
    uint32_t* out = g_Wpk + b * 16384;
    for (int idx = threadIdx.x; idx < 16384; idx += blockDim.x) {
        int reg = idx & 3, lane = (idx >> 2) & 31, ks2 = (idx >> 7) & 7, ntile = idx >> 10;
        int n = ntile * 8 + (lane >> 2);
        int k = ks2 * 16 + reg * 4 + (lane & 3);
        out[idx] = f2tf32(W[n * 128 + k]);
    }
}

// ---------------------------------------------------------------------------
// mma helpers
// ---------------------------------------------------------------------------
__device__ __forceinline__ void mma_tf32(float& c0, float& c1, float& c2, float& c3,
                                         uint32_t a0, uint32_t a1, uint32_t a2, uint32_t a3,
                                         uint32_t b0, uint32_t b1) {
    asm volatile(
        "mma.sync.aligned.m16n8k8.row.col.f32.tf32.tf32.f32 "
        "{%0,%1,%2,%3}, {%4,%5,%6,%7}, {%8,%9}, {%0,%1,%2,%3};"
        : "+f"(c0), "+f"(c1), "+f"(c2), "+f"(c3)
        : "r"(a0), "r"(a1), "r"(a2), "r"(a3), "r"(b0), "r"(b1));
}
__device__ __forceinline__ void mma_tf32f(float& c0, float& c1, float& c2, float& c3,
                                          float a0, float a1, float a2, float a3,
                                          float b0, float b1) {
    mma_tf32(c0, c1, c2, c3,
             __float_as_uint(a0), __float_as_uint(a1),
             __float_as_uint(a2), __float_as_uint(a3),
             __float_as_uint(b0), __float_as_uint(b1));
}

#define A_PITCH 132

// Stage a 64x128 fp32 tile -> fragment-packed tf32 smem (8448 words).
__device__ __forceinline__ void stage_pack(uint32_t* pack,
                                           const float* __restrict__ src, int tid) {
    const float4* A4 = reinterpret_cast<const float4*>(src);
#pragma unroll
    for (int t = 0; t < 8; ++t) {
        int idx = tid + t * 256;
        int r = idx >> 5, c4 = idx & 31;
        float4 v = A4[idx];
        int mtile = r >> 4, gg = r & 7, mh2 = (r >> 3) & 1;
        int slot = mtile * 16 + (c4 >> 1);
        int regb = (c4 & 1) * 2 + mh2;
        uint32_t* base = pack + slot * A_PITCH + gg * 16 + regb;
        base[0]  = f2tf32(v.x);
        base[4]  = f2tf32(v.y);
        base[8]  = f2tf32(v.z);
        base[12] = f2tf32(v.w);
    }
}

// One 32x32 warp gemm tile from a fragment pack, B via LDG from packed weights.
__device__ __forceinline__ void tile_gemm(const uint32_t* __restrict__ pack,
                                          const uint32_t* __restrict__ Wb,
                                          int wm, int wn, int lane,
                                          float (&acc)[2][4][4]) {
#pragma unroll
    for (int mt = 0; mt < 2; ++mt)
#pragma unroll
        for (int nt = 0; nt < 4; ++nt)
#pragma unroll
            for (int r = 0; r < 4; ++r) acc[mt][nt][r] = 0.f;
    const uint32_t* Abase = pack + lane * 4;
    const uint32_t* Bbase = Wb + lane * 4;
#pragma unroll 1
    for (int ks2 = 0; ks2 < 8; ++ks2) {
        const int sA0 = (wm * 2 + 0) * 16 + ks2 * 2;
        const int sA1 = (wm * 2 + 1) * 16 + ks2 * 2;
        uint4 a0L = *reinterpret_cast<const uint4*>(Abase + sA0 * A_PITCH);
        uint4 a0H = *reinterpret_cast<const uint4*>(Abase + (sA0 + 1) * A_PITCH);
        uint4 a1L = *reinterpret_cast<const uint4*>(Abase + sA1 * A_PITCH);
        uint4 a1H = *reinterpret_cast<const uint4*>(Abase + (sA1 + 1) * A_PITCH);
#pragma unroll
        for (int nt = 0; nt < 4; ++nt) {
            uint4 b = *reinterpret_cast<const uint4*>(
                Bbase + ((wn * 4 + nt) * 8 + ks2) * 128);
            mma_tf32(acc[0][nt][0], acc[0][nt][1], acc[0][nt][2], acc[0][nt][3],
                     a0L.x, a0L.y, a0L.z, a0L.w, b.x, b.y);
            mma_tf32(acc[0][nt][0], acc[0][nt][1], acc[0][nt][2], acc[0][nt][3],
                     a0H.x, a0H.y, a0H.z, a0H.w, b.z, b.w);
            mma_tf32(acc[1][nt][0], acc[1][nt][1], acc[1][nt][2], acc[1][nt][3],
                     a1L.x, a1L.y, a1L.z, a1L.w, b.x, b.y);
            mma_tf32(acc[1][nt][0], acc[1][nt][1], acc[1][nt][2], acc[1][nt][3],
                     a1H.x, a1H.y, a1H.z, a1H.w, b.z, b.w);
        }
    }
}

// Quad-reduce (lanes xor 1, 2) a row sum.
__device__ __forceinline__ float quad_sum(float s) {
    s += __shfl_xor_sync(0xffffffffu, s, 1);
    s += __shfl_xor_sync(0xffffffffu, s, 2);
    return s;
}

// ---------------------------------------------------------------------------
// MEGA KERNEL: projections (Q,K,V) + cosine attention + output projection.
//   (unchanged from the 534.5 us R16 kernel)
// ---------------------------------------------------------------------------
__global__ __launch_bounds__(256, 2)
void attn_mega_kernel(const float* __restrict__ x, const float* __restrict__ ctx,
                      const float* __restrict__ ls, const float* __restrict__ mask,
                      const float* __restrict__ q_b, const float* __restrict__ v_b,
                      const float* __restrict__ pb, float* __restrict__ out) {
    extern __shared__ float smf[];
    uint32_t* Xp = reinterpret_cast<uint32_t*>(smf);            // x pack
    uint32_t* Cp = reinterpret_cast<uint32_t*>(smf) + 18432;    // ctx pack
    float* qn = smf;            // 9216
    float* kn = smf + 9216;     // 9216
    float* vn = smf + 18432;    // 10240

    const int win = blockIdx.x, tid = threadIdx.x;
    const int w = tid >> 5, lane = tid & 31;
    const int g = lane >> 2, tg = lane & 3;
    const int wm = w >> 2, wn = w & 3;   // projection-phase warp grid

    // ---- stage input packs ----
    stage_pack(Xp, x  + (size_t)win * 8192, tid);
    stage_pack(Cp, ctx + (size_t)win * 8192, tid);
    __syncthreads();

    // ---- Q projection: 32x32 tile, head = wn ----
    {
        float qa[2][4][4];
        tile_gemm(Xp, g_Wpk, wm, wn, lane, qa);
        float sc = __expf(fminf(__ldg(ls + wn), 4.6051702f));
#pragma unroll
        for (int mt = 0; mt < 2; ++mt) {
            float ssA = 0.f, ssB = 0.f;
#pragma unroll
            for (int nt = 0; nt < 4; ++nt) {
                int col = wn * 32 + nt * 8 + 2 * tg;
                float b0 = __ldg(q_b + col), b1 = __ldg(q_b + col + 1);
                qa[mt][nt][0] += b0; qa[mt][nt][1] += b1;
                qa[mt][nt][2] += b0; qa[mt][nt][3] += b1;
                ssA = fmaf(qa[mt][nt][0], qa[mt][nt][0],
                      fmaf(qa[mt][nt][1], qa[mt][nt][1], ssA));
                ssB = fmaf(qa[mt][nt][2], qa[mt][nt][2],
                      fmaf(qa[mt][nt][3], qa[mt][nt][3], ssB));
            }
            float sA = sc / fmaxf(sqrtf(quad_sum(ssA)), 1e-12f);
            float sB = sc / fmaxf(sqrtf(quad_sum(ssB)), 1e-12f);
#pragma unroll
            for (int nt = 0; nt < 4; ++nt) {
                qa[mt][nt][0] *= sA; qa[mt][nt][1] *= sA;
                qa[mt][nt][2] *= sB; qa[mt][nt][3] *= sB;
            }
        }
        __syncthreads();   // all x-pack reads done before qn overlays it
        float* dq = qn + wn * 2304;
#pragma unroll
        for (int mt = 0; mt < 2; ++mt) {
            int ra = wm * 32 + mt * 16 + g, rb = ra + 8;
#pragma unroll
            for (int nt = 0; nt < 4; ++nt) {
                int d = nt * 8 + 2 * tg;
                dq[ra * 36 + ((d + ra) & 31)]     = qa[mt][nt][0];
                dq[ra * 36 + ((d + 1 + ra) & 31)] = qa[mt][nt][1];
                dq[rb * 36 + ((d + rb) & 31)]     = qa[mt][nt][2];
                dq[rb * 36 + ((d + 1 + rb) & 31)] = qa[mt][nt][3];
            }
        }
    }

    // ---- K projection (no bias, l2 norm) -> kn; V projection (+v_b) -> vn ----
    {
        float ka[2][4][4];
        tile_gemm(Cp, g_Wpk + 16384, wm, wn, lane, ka);
#pragma unroll
        for (int mt = 0; mt < 2; ++mt) {
            float ssA = 0.f, ssB = 0.f;
#pragma unroll
            for (int nt = 0; nt < 4; ++nt) {
                ssA = fmaf(ka[mt][nt][0], ka[mt][nt][0],
                      fmaf(ka[mt][nt][1], ka[mt][nt][1], ssA));
                ssB = fmaf(ka[mt][nt][2], ka[mt][nt][2],
                      fmaf(ka[mt][nt][3], ka[mt][nt][3], ssB));
            }
            float sA = 1.f / fmaxf(sqrtf(quad_sum(ssA)), 1e-12f);
            float sB = 1.f / fmaxf(sqrtf(quad_sum(ssB)), 1e-12f);
#pragma unroll
            for (int nt = 0; nt < 4; ++nt) {
                ka[mt][nt][0] *= sA; ka[mt][nt][1] *= sA;
                ka[mt][nt][2] *= sB; ka[mt][nt][3] *= sB;
            }
        }
        float* dk = kn + wn * 2304;
#pragma unroll
        for (int mt = 0; mt < 2; ++mt) {
            int ra = wm * 32 + mt * 16 + g, rb = ra + 8;
#pragma unroll
            for (int nt = 0; nt < 4; ++nt) {
                int d = nt * 8 + 2 * tg;
                dk[ra * 36 + ((d + ra) & 31)]     = ka[mt][nt][0];
                dk[ra * 36 + ((d + 1 + ra) & 31)] = ka[mt][nt][1];
                dk[rb * 36 + ((d + rb) & 31)]     = ka[mt][nt][2];
                dk[rb * 36 + ((d + 1 + rb) & 31)] = ka[mt][nt][3];
            }
        }

        float va[2][4][4];
        tile_gemm(Cp, g_Wpk + 2 * 16384, wm, wn, lane, va);
        __syncthreads();   // all ctx-pack reads done before vn overlays it
        float* dv = vn + wn * 2560;
#pragma unroll
        for (int mt = 0; mt < 2; ++mt) {
            int ra = wm * 32 + mt * 16 + g, rb = ra + 8;
#pragma unroll
            for (int nt = 0; nt < 4; ++nt) {
                int col = wn * 32 + nt * 8 + 2 * tg;
                float b0 = __ldg(v_b + col), b1 = __ldg(v_b + col + 1);
                int d = nt * 8 + 2 * tg;
                dv[ra * 40 + ((d + ra) & 31)]     = tf32f(va[mt][nt][0] + b0);
                dv[ra * 40 + ((d + 1 + ra) & 31)] = tf32f(va[mt][nt][1] + b1);
                dv[rb * 40 + ((d + rb) & 31)]     = tf32f(va[mt][nt][2] + b0);
                dv[rb * 40 + ((d + 1 + rb) & 31)] = tf32f(va[mt][nt][3] + b1);
            }
        }
    }
    __syncthreads();

    // ================= attention phases =================
    const int h = w >> 1, mh = w & 1;
    const float* Qb = qn + h * 2304;
    const float* Kb = kn + h * 2304;

    float acc[2][8][4];
#pragma unroll
    for (int mt = 0; mt < 2; ++mt)
#pragma unroll
        for (int nt = 0; nt < 8; ++nt)
#pragma unroll
            for (int r = 0; r < 4; ++r) acc[mt][nt][r] = 0.f;

    // ---- QK^T: tf32x3 with on-the-fly hi/lo split ----
#pragma unroll 1
    for (int ks = 0; ks < 4; ++ks) {
        const int c0 = ks * 8 + tg, c1 = c0 + 4;
        float qh[2][4], ql[2][4];
#pragma unroll
        for (int mt = 0; mt < 2; ++mt) {
            int ra = mh * 32 + mt * 16 + g, rb = ra + 8;
            float v0 = Qb[ra * 36 + ((c0 + ra) & 31)];
            float v1 = Qb[rb * 36 + ((c0 + rb) & 31)];
            float v2 = Qb[ra * 36 + ((c1 + ra) & 31)];
            float v3 = Qb[rb * 36 + ((c1 + rb) & 31)];
            qh[mt][0] = tf32f(v0); ql[mt][0] = tf32f(v0 - qh[mt][0]);
            qh[mt][1] = tf32f(v1); ql[mt][1] = tf32f(v1 - qh[mt][1]);
            qh[mt][2] = tf32f(v2); ql[mt][2] = tf32f(v2 - qh[mt][2]);
            qh[mt][3] = tf32f(v3); ql[mt][3] = tf32f(v3 - qh[mt][3]);
        }
#pragma unroll
        for (int nt = 0; nt < 8; ++nt) {
            int j = nt * 8 + g;
            float k0 = Kb[j * 36 + ((c0 + j) & 31)];
            float k1 = Kb[j * 36 + ((c1 + j) & 31)];
            float bh0 = tf32f(k0), bl0 = tf32f(k0 - bh0);
            float bh1 = tf32f(k1), bl1 = tf32f(k1 - bh1);
#pragma unroll
            for (int mt = 0; mt < 2; ++mt) {
                mma_tf32f(acc[mt][nt][0], acc[mt][nt][1], acc[mt][nt][2], acc[mt][nt][3],
                          qh[mt][0], qh[mt][1], qh[mt][2], qh[mt][3], bh0, bh1);
                mma_tf32f(acc[mt][nt][0], acc[mt][nt][1], acc[mt][nt][2], acc[mt][nt][3],
                          qh[mt][0], qh[mt][1], qh[mt][2], qh[mt][3], bl0, bl1);
                mma_tf32f(acc[mt][nt][0], acc[mt][nt][1], acc[mt][nt][2], acc[mt][nt][3],
                          ql[mt][0], ql[mt][1], ql[mt][2], ql[mt][3], bh0, bh1);
            }
        }
    }

    // ---- bias + mask ----
    {
        const float* bias = g_biasD + h * 4096;
        const float* msk  = mask + (size_t)(win & (NMASK - 1)) * 4096;
#pragma unroll
        for (int mt = 0; mt < 2; ++mt) {
            int ra = mh * 32 + mt * 16 + g, rb = ra + 8;
#pragma unroll
            for (int nt = 0; nt < 8; ++nt) {
                int col = nt * 8 + 2 * tg;
                float2 ba = *reinterpret_cast<const float2*>(bias + ra * 64 + col);
                float2 ma = *reinterpret_cast<const float2*>(msk  + ra * 64 + col);
                float2 bb = *reinterpret_cast<const float2*>(bias + rb * 64 + col);
                float2 mb = *reinterpret_cast<const float2*>(msk  + rb * 64 + col);
                acc[mt][nt][0] += ba.x + ma.x;
                acc[mt][nt][1] += ba.y + ma.y;
                acc[mt][nt][2] += bb.x + mb.x;
                acc[mt][nt][3] += bb.y + mb.y;
            }
        }
    }

    // ---- softmax over j (quad shuffles) ----
#pragma unroll
    for (int mt = 0; mt < 2; ++mt) {
#pragma unroll
        for (int hf = 0; hf < 2; ++hf) {
            float m = -1e30f;
#pragma unroll
            for (int nt = 0; nt < 8; ++nt)
                m = fmaxf(m, fmaxf(acc[mt][nt][hf * 2], acc[mt][nt][hf * 2 + 1]));
            m = fmaxf(m, __shfl_xor_sync(0xffffffffu, m, 1));
            m = fmaxf(m, __shfl_xor_sync(0xffffffffu, m, 2));
            float s = 0.f;
#pragma unroll
            for (int nt = 0; nt < 8; ++nt) {
                float e0 = __expf(acc[mt][nt][hf * 2]     - m);
                float e1 = __expf(acc[mt][nt][hf * 2 + 1] - m);
                acc[mt][nt][hf * 2]     = e0;
                acc[mt][nt][hf * 2 + 1] = e1;
                s += e0 + e1;
            }
            s += __shfl_xor_sync(0xffffffffu, s, 1);
            s += __shfl_xor_sync(0xffffffffu, s, 2);
            float inv = 1.f / s;
#pragma unroll
            for (int nt = 0; nt < 8; ++nt) {
                acc[mt][nt][hf * 2]     *= inv;
                acc[mt][nt][hf * 2 + 1] *= inv;
            }
        }
    }

    __syncthreads();   // all warps done reading qn/kn before P overlays them

    // ---- store P (tf32, pitch 68) overlaying qn+kn ----
    float* P = smf + h * 4352;
#pragma unroll
    for (int mt = 0; mt < 2; ++mt) {
        int ra = mh * 32 + mt * 16 + g, rb = ra + 8;
#pragma unroll
        for (int nt = 0; nt < 8; ++nt) {
            int col = nt * 8 + 2 * tg;
            float2 p0 = make_float2(tf32f(acc[mt][nt][0]), tf32f(acc[mt][nt][1]));
            float2 p1 = make_float2(tf32f(acc[mt][nt][2]), tf32f(acc[mt][nt][3]));
            *reinterpret_cast<float2*>(P + ra * 68 + col) = p0;
            *reinterpret_cast<float2*>(P + rb * 68 + col) = p1;
        }
    }
    __syncwarp();

    // ---- PV: m32(warp) x n32 x k64 ----
    const float* Vh = vn + h * 2560;
    float o[2][4][4];
#pragma unroll
    for (int mt = 0; mt < 2; ++mt)
#pragma unroll
        for (int nt = 0; nt < 4; ++nt)
#pragma unroll
            for (int r = 0; r < 4; ++r) o[mt][nt][r] = 0.f;

#pragma unroll 1
    for (int ks = 0; ks < 8; ++ks) {
        const int j0 = ks * 8 + tg, j1 = j0 + 4;
        float pa[2][4];
#pragma unroll
        for (int mt = 0; mt < 2; ++mt) {
            int ra = mh * 32 + mt * 16 + g, rb = ra + 8;
            pa[mt][0] = P[ra * 68 + j0];
            pa[mt][1] = P[rb * 68 + j0];
            pa[mt][2] = P[ra * 68 + j1];
            pa[mt][3] = P[rb * 68 + j1];
        }
#pragma unroll
        for (int nt = 0; nt < 4; ++nt) {
            int d = nt * 8 + g;
            float vb0 = Vh[j0 * 40 + ((d + j0) & 31)];
            float vb1 = Vh[j1 * 40 + ((d + j1) & 31)];
#pragma unroll
            for (int mt = 0; mt < 2; ++mt)
                mma_tf32f(o[mt][nt][0], o[mt][nt][1], o[mt][nt][2], o[mt][nt][3],
                          pa[mt][0], pa[mt][1], pa[mt][2], pa[mt][3], vb0, vb1);
        }
    }

    __syncthreads();   // all P/V reads done before O-pack overlays the region

    // ---- store O (tf32) in gemm fragment-packed layout at smf[0..8448) ----
    {
        uint32_t* Ou = reinterpret_cast<uint32_t*>(smf);
#pragma unroll
        for (int mt = 0; mt < 2; ++mt) {
#pragma unroll
            for (int nt = 0; nt < 4; ++nt) {
                int S = (mh * 2 + mt) * 16 + h * 4 + nt;
                uint32_t* base = Ou + S * A_PITCH + g * 16 + (tg >> 1) * 2 + (tg & 1) * 8;
                base[0] = f2tf32(o[mt][nt][0]);
                base[4] = f2tf32(o[mt][nt][1]);
                base[1] = f2tf32(o[mt][nt][2]);
                base[5] = f2tf32(o[mt][nt][3]);
            }
        }
    }
    __syncthreads();

    // ---- fused projection: out(64x128) = O @ pw^T + pb ----
    {
        float pr[2][4][4];
        tile_gemm(reinterpret_cast<const uint32_t*>(smf), g_Wpk + 3 * 16384,
                  wm, wn, lane, pr);
        float* Out = out + (size_t)win * 8192;
#pragma unroll
        for (int mt = 0; mt < 2; ++mt) {
            const int r0 = wm * 32 + mt * 16 + g;
#pragma unroll
            for (int nt = 0; nt < 4; ++nt) {
                const int col = wn * 32 + nt * 8 + 2 * tg;
                float bb0 = __ldg(pb + col);
                float bb1 = __ldg(pb + col + 1);
                *reinterpret_cast<float2*>(&Out[(size_t)r0 * 128 + col]) =
                    make_float2(pr[mt][nt][0] + bb0, pr[mt][nt][1] + bb1);
                *reinterpret_cast<float2*>(&Out[(size_t)(r0 + 8) * 128 + col]) =
                    make_float2(pr[mt][nt][2] + bb0, pr[mt][nt][3] + bb1);
            }
        }
    }
}

// ---------------------------------------------------------------------------
// Launch — only harness-provided pointers cross the host/device boundary.
// ---------------------------------------------------------------------------
extern "C" void kernel_launch(void* const* d_in, const int* in_sizes, int n_in,
                              void* d_out, int out_size) {
    const float* x    = (const float*)d_in[0];
    const float* ctx  = (const float*)d_in[1];
    const float* mask = (const float*)d_in[2];
    const float* q_w  = (const float*)d_in[3];
    const float* q_b  = (const float*)d_in[4];
    const float* kv_w = (const float*)d_in[5];
    const float* v_b  = (const float*)d_in[6];
    const float* ls   = (const float*)d_in[7];
    const float* w1   = (const float*)d_in[8];
    const float* b1   = (const float*)d_in[9];
    const float* w2   = (const float*)d_in[10];
    const float* pw   = (const float*)d_in[11];
    const float* pb   = (const float*)d_in[12];
    const float* tbl  = (const float*)d_in[13];
    const int*   rpi  = (const int*)d_in[14];
    float* out = (float*)d_out;

    const int ATTN_SMEM = 28672 * 4;   // 114,688 B -> 2 CTAs/SM

    cudaFuncSetAttribute(attn_mega_kernel, cudaFuncAttributeMaxDynamicSharedMemorySize, ATTN_SMEM);

    // Prep (parallelized: warp-per-row MLP, then gather)
    cpb_mlp_kernel<<<29, 256>>>(tbl, w1, b1, w2);
    pack_weights_kernel<<<4, 256>>>(q_w, kv_w, pw);
    cpb_gather_kernel<<<16, 256>>>(rpi);

    // Fully fused: projections + attention + output projection
    attn_mega_kernel<<<NWIN, 256, ATTN_SMEM>>>(x, ctx, ls, mask, q_b, v_b, pb, out);
}